// round 1
// baseline (speedup 1.0000x reference)
#include <cuda_runtime.h>
#include <math.h>

// Problem constants
#define BSZ  2
#define TSEQ 2048
#define DIM  768
#define NH   12
#define HD   64          // head dim (K == V == 64)
#define WIN  1024
#define ROWS (BSZ*TSEQ)  // 4096
#define HKD  (NH*HD)     // 768 == DIM
#define REPS 1e-6f
#define NEG_BIG (-1e30f)

// ---------------------------------------------------------------------------
// Scratch (static device globals; no allocation at runtime)
// ---------------------------------------------------------------------------
__device__ float g_xn[ROWS*DIM];            // rmsnorm(x)
__device__ float g_q [BSZ*NH*TSEQ*HD];      // (B,H,T,K)
__device__ float g_k [BSZ*NH*TSEQ*HD];
__device__ float g_v [BSZ*NH*TSEQ*HD];
__device__ float g_qg[BSZ*NH*TSEQ*HD];      // relu(xn@Wgq), (B,H,T,K)
__device__ float g_local[ROWS*HKD];         // attention out, (B,T,H*K)
__device__ float g_retr [ROWS*HKD];         // retrieval,     (B,T,H*V)
__device__ float g_gate [ROWS];             // mean sigmoid gate per row

// ---------------------------------------------------------------------------
// RMSNorm: one block per row
// ---------------------------------------------------------------------------
__global__ __launch_bounds__(256) void rmsnorm_k(const float* __restrict__ x,
                                                 const float* __restrict__ nw) {
    int row = blockIdx.x;
    const float* xr = x + (size_t)row * DIM;
    float ss = 0.f;
    for (int d = threadIdx.x; d < DIM; d += 256) { float v = xr[d]; ss += v * v; }
    #pragma unroll
    for (int o = 16; o; o >>= 1) ss += __shfl_xor_sync(0xffffffffu, ss, o);
    __shared__ float red[8];
    __shared__ float s_rinv;
    int wid = threadIdx.x >> 5, lane = threadIdx.x & 31;
    if (lane == 0) red[wid] = ss;
    __syncthreads();
    if (threadIdx.x == 0) {
        float t = 0.f;
        #pragma unroll
        for (int i = 0; i < 8; i++) t += red[i];
        s_rinv = rsqrtf(t / (float)DIM + REPS);
    }
    __syncthreads();
    float r = s_rinv;
    for (int d = threadIdx.x; d < DIM; d += 256)
        g_xn[(size_t)row * DIM + d] = xr[d] * r * nw[d];
}

// ---------------------------------------------------------------------------
// Generic 64x64 tiled fp32 GEMM (BK=16), 256 threads, 4x4 micro-tile.
// Requires M%64==0, N%64==0, K%16==0, N%4==0 (all hold here).
// Epilogue flags:
//   out_bhtk : scatter row-major (M,N) result into (B,H,T,64) layout
//   relu     : max(v,0)
//   addsrc   : v += addsrc[m*N+n]   (residual)
//   rowscale : v *= rowscale[m]
//   accum    : C[idx] += v  (else assign)
// ---------------------------------------------------------------------------
__global__ __launch_bounds__(256) void gemm_k(
    const float* __restrict__ A, const float* __restrict__ Bm,
    float* __restrict__ C, int M, int N, int Kd,
    int out_bhtk, int relu,
    const float* __restrict__ addsrc, const float* __restrict__ rowscale,
    int accum)
{
    __shared__ float As[16][68];   // [k][m], padded (store-conflict free, f4-aligned)
    __shared__ float Bs[16][64];   // [k][n]

    int tid = threadIdx.x;
    int tx = tid & 15, ty = tid >> 4;
    int m0 = blockIdx.y * 64, n0 = blockIdx.x * 64;
    int arow = tid >> 2, ac4 = (tid & 3) * 4;   // A load: 64 rows x 16 cols
    int brow = tid >> 4, bc4 = (tid & 15) * 4;  // B load: 16 rows x 64 cols

    float c[4][4] = {};

    for (int k0 = 0; k0 < Kd; k0 += 16) {
        float4 av = *(const float4*)(A  + (size_t)(m0 + arow) * Kd + k0 + ac4);
        float4 bv = *(const float4*)(Bm + (size_t)(k0 + brow) * N  + n0 + bc4);
        __syncthreads();
        As[ac4 + 0][arow] = av.x;
        As[ac4 + 1][arow] = av.y;
        As[ac4 + 2][arow] = av.z;
        As[ac4 + 3][arow] = av.w;
        *(float4*)&Bs[brow][bc4] = bv;
        __syncthreads();
        #pragma unroll
        for (int kk = 0; kk < 16; kk++) {
            float4 a4 = *(const float4*)&As[kk][ty * 4];
            float4 b4 = *(const float4*)&Bs[kk][tx * 4];
            c[0][0] += a4.x * b4.x; c[0][1] += a4.x * b4.y;
            c[0][2] += a4.x * b4.z; c[0][3] += a4.x * b4.w;
            c[1][0] += a4.y * b4.x; c[1][1] += a4.y * b4.y;
            c[1][2] += a4.y * b4.z; c[1][3] += a4.y * b4.w;
            c[2][0] += a4.z * b4.x; c[2][1] += a4.z * b4.y;
            c[2][2] += a4.z * b4.z; c[2][3] += a4.z * b4.w;
            c[3][0] += a4.w * b4.x; c[3][1] += a4.w * b4.y;
            c[3][2] += a4.w * b4.z; c[3][3] += a4.w * b4.w;
        }
    }

    #pragma unroll
    for (int i = 0; i < 4; i++) {
        int row = m0 + ty * 4 + i;
        float rs = rowscale ? rowscale[row] : 1.f;
        #pragma unroll
        for (int j = 0; j < 4; j++) {
            int col = n0 + tx * 4 + j;
            float v = c[i][j];
            if (relu) v = fmaxf(v, 0.f);
            v *= rs;
            if (addsrc) v += addsrc[(size_t)row * N + col];
            size_t idx;
            if (out_bhtk) {
                int b = row / TSEQ, t = row % TSEQ;
                int h = col >> 6, kk = col & 63;
                idx = (((size_t)(b * NH + h) * TSEQ + t) << 6) + kk;
            } else {
                idx = (size_t)row * N + col;
            }
            if (accum) C[idx] += v; else C[idx] = v;
        }
    }
}

// ---------------------------------------------------------------------------
// Sliding-window causal attention, flash-style online softmax.
// One block per (b,h,64-query tile); 64 threads, one query per thread.
// ---------------------------------------------------------------------------
__global__ __launch_bounds__(64) void attn_k() {
    int bid = blockIdx.x;
    int qt = bid & 31;           // T/64 = 32 query tiles
    int bh = bid >> 5;           // b*NH + h
    int q0 = qt * 64;
    int tid = threadIdx.x;
    int q_idx = q0 + tid;
    const float scale = 0.125f;  // 64^-0.5
    size_t base = (size_t)bh * TSEQ * HD;

    float qv[64];
    #pragma unroll
    for (int cc = 0; cc < 16; cc++) {
        float4 t4 = *(const float4*)(g_q + base + (size_t)q_idx * HD + cc * 4);
        qv[cc*4+0] = t4.x; qv[cc*4+1] = t4.y; qv[cc*4+2] = t4.z; qv[cc*4+3] = t4.w;
    }
    float o[64];
    #pragma unroll
    for (int d = 0; d < 64; d++) o[d] = 0.f;
    float mrow = NEG_BIG, l = 0.f;

    __shared__ float ks[64][68];
    __shared__ float vs[64][68];

    int kstart = q0 - WIN; if (kstart < 0) kstart = 0;   // tile aligned (WIN%64==0)
    for (int s0 = kstart; s0 < q0 + 64; s0 += 64) {
        // cooperative coalesced load of K/V tiles
        for (int i = tid; i < 64 * 16; i += 64) {
            int r = i >> 4, c4 = (i & 15) * 4;
            float4 k4 = *(const float4*)(g_k + base + (size_t)(s0 + r) * HD + c4);
            float4 v4 = *(const float4*)(g_v + base + (size_t)(s0 + r) * HD + c4);
            ks[r][c4+0] = k4.x; ks[r][c4+1] = k4.y; ks[r][c4+2] = k4.z; ks[r][c4+3] = k4.w;
            vs[r][c4+0] = v4.x; vs[r][c4+1] = v4.y; vs[r][c4+2] = v4.z; vs[r][c4+3] = v4.w;
        }
        __syncthreads();

        float s[64];
        float tmax = NEG_BIG;
        #pragma unroll 2
        for (int j = 0; j < 64; j++) {
            int key = s0 + j;
            float acc = 0.f;
            #pragma unroll
            for (int cc = 0; cc < 16; cc++) {
                float4 k4 = *(const float4*)&ks[j][cc * 4];
                acc += qv[cc*4+0]*k4.x + qv[cc*4+1]*k4.y
                     + qv[cc*4+2]*k4.z + qv[cc*4+3]*k4.w;
            }
            acc *= scale;
            bool ok = (key <= q_idx) && (key >= q_idx - WIN);
            s[j] = ok ? acc : NEG_BIG;
            tmax = fmaxf(tmax, s[j]);
        }

        float newm = fmaxf(mrow, tmax);
        if (newm > -1e29f) {
            float corr = (mrow <= -1e29f) ? 0.f : __expf(mrow - newm);
            l *= corr;
            #pragma unroll
            for (int d = 0; d < 64; d++) o[d] *= corr;
            #pragma unroll 2
            for (int j = 0; j < 64; j++) {
                if (s[j] > -1e29f) {
                    float p = __expf(s[j] - newm);
                    l += p;
                    #pragma unroll
                    for (int cc = 0; cc < 16; cc++) {
                        float4 v4 = *(const float4*)&vs[j][cc * 4];
                        o[cc*4+0] += p * v4.x; o[cc*4+1] += p * v4.y;
                        o[cc*4+2] += p * v4.z; o[cc*4+3] += p * v4.w;
                    }
                }
            }
            mrow = newm;
        }
        __syncthreads();
    }

    float inv = 1.f / l;
    int b = bh / NH, h = bh % NH;
    float* outp = g_local + ((size_t)(b * TSEQ + q_idx)) * HKD + h * HD;
    #pragma unroll
    for (int cc = 0; cc < 16; cc++) {
        float4 t4;
        t4.x = o[cc*4+0]*inv; t4.y = o[cc*4+1]*inv;
        t4.z = o[cc*4+2]*inv; t4.w = o[cc*4+3]*inv;
        *(float4*)(outp + cc * 4) = t4;
    }
}

// ---------------------------------------------------------------------------
// GDN retrieval: per (b,h): (T,K) @ (K,V). Block = (b,h, 128-row tile of T).
// ---------------------------------------------------------------------------
__global__ __launch_bounds__(128) void retr_k(const float* __restrict__ state) {
    int bid = blockIdx.x;
    int tt = bid & 15;           // T/128 = 16
    int bh = bid >> 4;
    __shared__ float st[64][68];     // state tile (K,V), padded for f4 reads
    __shared__ float qs[128][65];    // qg tile, padded for conflict-free column reads

    const float* sp = state + (size_t)bh * HD * HD;
    for (int i = threadIdx.x; i < HD * HD; i += 128)
        st[i >> 6][i & 63] = sp[i];
    size_t qbase = (size_t)bh * TSEQ * HD + (size_t)tt * 128 * HD;
    for (int i = threadIdx.x; i < 128 * HD; i += 128)
        qs[i >> 6][i & 63] = g_qg[qbase + i];
    __syncthreads();

    int t = tt * 128 + threadIdx.x;
    float acc[64];
    #pragma unroll
    for (int v = 0; v < 64; v++) acc[v] = 0.f;
    for (int k = 0; k < 64; k++) {
        float qk = qs[threadIdx.x][k];
        #pragma unroll
        for (int cc = 0; cc < 16; cc++) {
            float4 s4 = *(const float4*)&st[k][cc * 4];
            acc[cc*4+0] += qk * s4.x; acc[cc*4+1] += qk * s4.y;
            acc[cc*4+2] += qk * s4.z; acc[cc*4+3] += qk * s4.w;
        }
    }
    int b = bh / NH, h = bh % NH;
    float* outp = g_retr + ((size_t)(b * TSEQ + t)) * HKD + h * HD;
    #pragma unroll
    for (int cc = 0; cc < 16; cc++) {
        float4 t4;
        t4.x = acc[cc*4+0]; t4.y = acc[cc*4+1];
        t4.z = acc[cc*4+2]; t4.w = acc[cc*4+3];
        *(float4*)(outp + cc * 4) = t4;
    }
}

// ---------------------------------------------------------------------------
// Gate: g_gate[row] = mean_h sigmoid(xn[row]@Wg[:,h] + bg[h]). Block per row.
// ---------------------------------------------------------------------------
__global__ __launch_bounds__(256) void gate_k(const float* __restrict__ Wg,
                                              const float* __restrict__ bg) {
    int row = blockIdx.x;
    float acc[NH];
    #pragma unroll
    for (int h = 0; h < NH; h++) acc[h] = 0.f;
    for (int d = threadIdx.x; d < DIM; d += 256) {
        float xv = g_xn[(size_t)row * DIM + d];
        #pragma unroll
        for (int h = 0; h < NH; h++) acc[h] += xv * Wg[d * NH + h];
    }
    #pragma unroll
    for (int h = 0; h < NH; h++) {
        #pragma unroll
        for (int o = 16; o; o >>= 1) acc[h] += __shfl_xor_sync(0xffffffffu, acc[h], o);
    }
    __shared__ float red[8][NH];
    int wid = threadIdx.x >> 5, lane = threadIdx.x & 31;
    if (lane == 0) {
        #pragma unroll
        for (int h = 0; h < NH; h++) red[wid][h] = acc[h];
    }
    __syncthreads();
    if (threadIdx.x == 0) {
        float s = 0.f;
        #pragma unroll
        for (int h = 0; h < NH; h++) {
            float a = 0.f;
            #pragma unroll
            for (int w = 0; w < 8; w++) a += red[w][h];
            s += 1.f / (1.f + expf(-(a + bg[h])));
        }
        g_gate[row] = s * (1.f / (float)NH);
    }
}

// ---------------------------------------------------------------------------
// Launch
// ---------------------------------------------------------------------------
extern "C" void kernel_launch(void* const* d_in, const int* in_sizes, int n_in,
                              void* d_out, int out_size) {
    const float* x      = (const float*)d_in[0];
    const float* state  = (const float*)d_in[1];
    const float* Wq     = (const float*)d_in[2];
    const float* Wk     = (const float*)d_in[3];
    const float* Wv     = (const float*)d_in[4];
    const float* Wo     = (const float*)d_in[5];
    const float* Wgq    = (const float*)d_in[6];
    const float* Wro    = (const float*)d_in[7];
    const float* Wg     = (const float*)d_in[8];
    const float* bg     = (const float*)d_in[9];
    const float* norm_w = (const float*)d_in[10];
    float* out = (float*)d_out;

    float *p_xn, *p_q, *p_k, *p_v, *p_qg, *p_local, *p_retr, *p_gate;
    cudaGetSymbolAddress((void**)&p_xn,    g_xn);
    cudaGetSymbolAddress((void**)&p_q,     g_q);
    cudaGetSymbolAddress((void**)&p_k,     g_k);
    cudaGetSymbolAddress((void**)&p_v,     g_v);
    cudaGetSymbolAddress((void**)&p_qg,    g_qg);
    cudaGetSymbolAddress((void**)&p_local, g_local);
    cudaGetSymbolAddress((void**)&p_retr,  g_retr);
    cudaGetSymbolAddress((void**)&p_gate,  g_gate);

    dim3 gblk(256);
    dim3 ggrid(HKD / 64, ROWS / 64);   // (12, 64)

    rmsnorm_k<<<ROWS, 256>>>(x, norm_w);

    // projections into (B,H,T,64) layout
    gemm_k<<<ggrid, gblk>>>(p_xn, Wq,  p_q,  ROWS, HKD, DIM, 1, 0, nullptr, nullptr, 0);
    gemm_k<<<ggrid, gblk>>>(p_xn, Wk,  p_k,  ROWS, HKD, DIM, 1, 0, nullptr, nullptr, 0);
    gemm_k<<<ggrid, gblk>>>(p_xn, Wv,  p_v,  ROWS, HKD, DIM, 1, 0, nullptr, nullptr, 0);
    gemm_k<<<ggrid, gblk>>>(p_xn, Wgq, p_qg, ROWS, HKD, DIM, 1, 1, nullptr, nullptr, 0);

    gate_k<<<ROWS, 256>>>(Wg, bg);

    attn_k<<<BSZ * NH * (TSEQ / 64), 64>>>();                 // 768 blocks
    retr_k<<<BSZ * NH * (TSEQ / 128), 128>>>(state);          // 384 blocks

    // out = x + local @ Wo
    gemm_k<<<ggrid, gblk>>>(p_local, Wo, out, ROWS, DIM, HKD, 0, 0, x, nullptr, 0);
    // out += gate_mean .* (retr @ Wro)
    gemm_k<<<ggrid, gblk>>>(p_retr, Wro, out, ROWS, DIM, HKD, 0, 0, nullptr, p_gate, 1);
}

// round 2
// speedup vs baseline: 1.7989x; 1.7989x over previous
#include <cuda_runtime.h>
#include <math.h>
#include <stdint.h>

// Problem constants
#define BSZ  2
#define TSEQ 2048
#define DIM  768
#define NH   12
#define HD   64          // head dim (K == V == 64)
#define WIN  1024
#define ROWS (BSZ*TSEQ)  // 4096
#define HKD  (NH*HD)     // 768 == DIM
#define REPS 1e-6f
#define NEG_BIG (-1e30f)

// GEMM tiling (all big GEMMs are 4096 x 768 x 768)
#define GK   768
#define GN   768
#define BM   128
#define BN   64
#define BKT  32

// ---------------------------------------------------------------------------
// Scratch (static device globals; no allocation at runtime)
// ---------------------------------------------------------------------------
__device__ float g_xn[ROWS*DIM];            // rmsnorm(x)
__device__ float g_q [BSZ*NH*TSEQ*HD];      // (B,H,T,K)
__device__ float g_k [BSZ*NH*TSEQ*HD];
__device__ float g_v [BSZ*NH*TSEQ*HD];
__device__ float g_qg[BSZ*NH*TSEQ*HD];      // relu(xn@Wgq), (B,H,T,K)
__device__ float g_local[ROWS*HKD];         // attention out, (B,T,H*K)
__device__ float g_retr [ROWS*HKD];         // retrieval,     (B,T,H*V)
__device__ float g_gate [ROWS];             // mean sigmoid gate per row

// ---------------------------------------------------------------------------
// RMSNorm: one block per row
// ---------------------------------------------------------------------------
__global__ __launch_bounds__(256) void rmsnorm_k(const float* __restrict__ x,
                                                 const float* __restrict__ nw) {
    int row = blockIdx.x;
    const float* xr = x + (size_t)row * DIM;
    float ss = 0.f;
    for (int d = threadIdx.x; d < DIM; d += 256) { float v = xr[d]; ss += v * v; }
    #pragma unroll
    for (int o = 16; o; o >>= 1) ss += __shfl_xor_sync(0xffffffffu, ss, o);
    __shared__ float red[8];
    __shared__ float s_rinv;
    int wid = threadIdx.x >> 5, lane = threadIdx.x & 31;
    if (lane == 0) red[wid] = ss;
    __syncthreads();
    if (threadIdx.x == 0) {
        float t = 0.f;
        #pragma unroll
        for (int i = 0; i < 8; i++) t += red[i];
        s_rinv = rsqrtf(t / (float)DIM + REPS);
    }
    __syncthreads();
    float r = s_rinv;
    for (int d = threadIdx.x; d < DIM; d += 256)
        g_xn[(size_t)row * DIM + d] = xr[d] * r * nw[d];
}

// ---------------------------------------------------------------------------
// TF32 tensor-core GEMM core: 128x64 block tile, BK=32, 8 warps (4x2),
// warp tile 32x32 = 2(m) x 4(n) mma.m16n8k8 tiles.
// ---------------------------------------------------------------------------
struct GemmSmem {
    uint32_t As[BM][36];   // [m][k], stride 36: frag loads conflict-free (4r+c)
    uint32_t Bs[BKT][72];  // [k][n], stride 72: frag loads conflict-free (8k+n)
};

__device__ __forceinline__ uint32_t f2tf32(float f) {
    uint32_t u;
    asm("cvt.rna.tf32.f32 %0, %1;" : "=r"(u) : "f"(f));
    return u;
}

__device__ __forceinline__ void mma_tf32(float c[4], const uint32_t a[4], const uint32_t b[2]) {
    asm volatile(
        "mma.sync.aligned.m16n8k8.row.col.f32.tf32.tf32.f32 "
        "{%0,%1,%2,%3}, {%4,%5,%6,%7}, {%8,%9}, {%0,%1,%2,%3};\n"
        : "+f"(c[0]), "+f"(c[1]), "+f"(c[2]), "+f"(c[3])
        : "r"(a[0]), "r"(a[1]), "r"(a[2]), "r"(a[3]), "r"(b[0]), "r"(b[1]));
}

// Computes c[2][4][4] for this block's tile. A: row-major (M,GK); B: row-major (GK,GN).
__device__ __forceinline__ void gemm_core(
    GemmSmem* s, const float* __restrict__ A, const float* __restrict__ B,
    int m0, int n0, float c[2][4][4])
{
    int tid = threadIdx.x;
    int lane = tid & 31, wid = tid >> 5;
    int wm = wid & 3, wn = wid >> 2;     // 4 x 2 warp grid
    int r = lane >> 2, cq = lane & 3;

    for (int k0 = 0; k0 < GK; k0 += BKT) {
        float4 av[4], bv[2];
        #pragma unroll
        for (int p = 0; p < 4; p++) {               // A: 128 rows x 8 f4
            int idx = tid + p * 256;
            int row = idx >> 3, c4 = (idx & 7) * 4;
            av[p] = *(const float4*)(A + (size_t)(m0 + row) * GK + k0 + c4);
        }
        #pragma unroll
        for (int p = 0; p < 2; p++) {               // B: 32 rows x 16 f4
            int idx = tid + p * 256;
            int row = idx >> 4, c4 = (idx & 15) * 4;
            bv[p] = *(const float4*)(B + (size_t)(k0 + row) * GN + n0 + c4);
        }
        __syncthreads();
        #pragma unroll
        for (int p = 0; p < 4; p++) {
            int idx = tid + p * 256;
            int row = idx >> 3, c4 = (idx & 7) * 4;
            s->As[row][c4 + 0] = f2tf32(av[p].x);
            s->As[row][c4 + 1] = f2tf32(av[p].y);
            s->As[row][c4 + 2] = f2tf32(av[p].z);
            s->As[row][c4 + 3] = f2tf32(av[p].w);
        }
        #pragma unroll
        for (int p = 0; p < 2; p++) {
            int idx = tid + p * 256;
            int row = idx >> 4, c4 = (idx & 15) * 4;
            s->Bs[row][c4 + 0] = f2tf32(bv[p].x);
            s->Bs[row][c4 + 1] = f2tf32(bv[p].y);
            s->Bs[row][c4 + 2] = f2tf32(bv[p].z);
            s->Bs[row][c4 + 3] = f2tf32(bv[p].w);
        }
        __syncthreads();

        #pragma unroll
        for (int ks = 0; ks < 4; ks++) {
            int kb = ks * 8;
            uint32_t af[2][4];
            #pragma unroll
            for (int mt = 0; mt < 2; mt++) {
                int mr = wm * 32 + mt * 16 + r;
                af[mt][0] = s->As[mr    ][kb + cq];
                af[mt][1] = s->As[mr + 8][kb + cq];
                af[mt][2] = s->As[mr    ][kb + cq + 4];
                af[mt][3] = s->As[mr + 8][kb + cq + 4];
            }
            uint32_t bf[4][2];
            #pragma unroll
            for (int nt = 0; nt < 4; nt++) {
                int nc = wn * 32 + nt * 8 + r;
                bf[nt][0] = s->Bs[kb + cq    ][nc];
                bf[nt][1] = s->Bs[kb + cq + 4][nc];
            }
            #pragma unroll
            for (int mt = 0; mt < 2; mt++)
                #pragma unroll
                for (int nt = 0; nt < 4; nt++)
                    mma_tf32(c[mt][nt], af[mt], bf[nt]);
        }
    }
}

// ---------------------------------------------------------------------------
// Fused projection GEMMs: z selects {Wq,Wk,Wv,Wgq} -> {q,k,v,qg}; scatter BHTK.
// ---------------------------------------------------------------------------
__global__ __launch_bounds__(256) void proj_tc(
    const float* __restrict__ Xn,
    const float* __restrict__ Wq, const float* __restrict__ Wk,
    const float* __restrict__ Wv, const float* __restrict__ Wgq)
{
    __shared__ GemmSmem s;
    int z = blockIdx.z;
    const float* B = (z == 0) ? Wq : (z == 1) ? Wk : (z == 2) ? Wv : Wgq;
    float* C       = (z == 0) ? g_q : (z == 1) ? g_k : (z == 2) ? g_v : g_qg;
    bool relu = (z == 3);

    int m0 = blockIdx.y * BM, n0 = blockIdx.x * BN;
    float c[2][4][4] = {};
    gemm_core(&s, Xn, B, m0, n0, c);

    int lane = threadIdx.x & 31, wid = threadIdx.x >> 5;
    int wm = wid & 3, wn = wid >> 2;
    int r = lane >> 2, cq = lane & 3;
    #pragma unroll
    for (int mt = 0; mt < 2; mt++) {
        #pragma unroll
        for (int nt = 0; nt < 4; nt++) {
            int col = n0 + wn * 32 + nt * 8 + 2 * cq;
            int h = col >> 6, kk = col & 63;
            #pragma unroll
            for (int i = 0; i < 2; i++) {
                int row = m0 + wm * 32 + mt * 16 + r + i * 8;
                int b = row >> 11, t = row & (TSEQ - 1);
                float v0 = c[mt][nt][i * 2 + 0];
                float v1 = c[mt][nt][i * 2 + 1];
                if (relu) { v0 = fmaxf(v0, 0.f); v1 = fmaxf(v1, 0.f); }
                float2 o; o.x = v0; o.y = v1;
                *(float2*)(C + (((size_t)(b * NH + h) * TSEQ + t) << 6) + kk) = o;
            }
        }
    }
}

// ---------------------------------------------------------------------------
// Output GEMMs: C = epilogue(A @ B); row-major out with optional residual add,
// row-scale and accumulate.
// ---------------------------------------------------------------------------
__global__ __launch_bounds__(256) void gemm_out_tc(
    const float* __restrict__ A, const float* __restrict__ B, float* __restrict__ C,
    const float* __restrict__ addsrc, const float* __restrict__ rowscale, int accum)
{
    __shared__ GemmSmem s;
    int m0 = blockIdx.y * BM, n0 = blockIdx.x * BN;
    float c[2][4][4] = {};
    gemm_core(&s, A, B, m0, n0, c);

    int lane = threadIdx.x & 31, wid = threadIdx.x >> 5;
    int wm = wid & 3, wn = wid >> 2;
    int r = lane >> 2, cq = lane & 3;
    #pragma unroll
    for (int mt = 0; mt < 2; mt++) {
        #pragma unroll
        for (int i = 0; i < 2; i++) {
            int row = m0 + wm * 32 + mt * 16 + r + i * 8;
            float rs = rowscale ? rowscale[row] : 1.f;
            #pragma unroll
            for (int nt = 0; nt < 4; nt++) {
                int col = n0 + wn * 32 + nt * 8 + 2 * cq;
                float v0 = c[mt][nt][i * 2 + 0] * rs;
                float v1 = c[mt][nt][i * 2 + 1] * rs;
                size_t idx = (size_t)row * GN + col;
                if (addsrc) {
                    float2 a2 = *(const float2*)(addsrc + idx);
                    v0 += a2.x; v1 += a2.y;
                }
                if (accum) {
                    float2 p = *(const float2*)(C + idx);
                    v0 += p.x; v1 += p.y;
                }
                float2 o; o.x = v0; o.y = v1;
                *(float2*)(C + idx) = o;
            }
        }
    }
}

// ---------------------------------------------------------------------------
// Sliding-window causal attention, flash-style online softmax.
// One block per (b,h,64-query tile); 64 threads, one query per thread.
// ---------------------------------------------------------------------------
__global__ __launch_bounds__(64) void attn_k() {
    int bid = blockIdx.x;
    int qt = bid & 31;           // T/64 = 32 query tiles
    int bh = bid >> 5;           // b*NH + h
    int q0 = qt * 64;
    int tid = threadIdx.x;
    int q_idx = q0 + tid;
    const float scale = 0.125f;  // 64^-0.5
    size_t base = (size_t)bh * TSEQ * HD;

    float qv[64];
    #pragma unroll
    for (int cc = 0; cc < 16; cc++) {
        float4 t4 = *(const float4*)(g_q + base + (size_t)q_idx * HD + cc * 4);
        qv[cc*4+0] = t4.x; qv[cc*4+1] = t4.y; qv[cc*4+2] = t4.z; qv[cc*4+3] = t4.w;
    }
    float o[64];
    #pragma unroll
    for (int d = 0; d < 64; d++) o[d] = 0.f;
    float mrow = NEG_BIG, l = 0.f;

    __shared__ float ks[64][68];
    __shared__ float vs[64][68];

    int kstart = q0 - WIN; if (kstart < 0) kstart = 0;   // tile aligned (WIN%64==0)
    for (int s0 = kstart; s0 < q0 + 64; s0 += 64) {
        for (int i = tid; i < 64 * 16; i += 64) {
            int r = i >> 4, c4 = (i & 15) * 4;
            float4 k4 = *(const float4*)(g_k + base + (size_t)(s0 + r) * HD + c4);
            float4 v4 = *(const float4*)(g_v + base + (size_t)(s0 + r) * HD + c4);
            ks[r][c4+0] = k4.x; ks[r][c4+1] = k4.y; ks[r][c4+2] = k4.z; ks[r][c4+3] = k4.w;
            vs[r][c4+0] = v4.x; vs[r][c4+1] = v4.y; vs[r][c4+2] = v4.z; vs[r][c4+3] = v4.w;
        }
        __syncthreads();

        float s[64];
        float tmax = NEG_BIG;
        #pragma unroll 2
        for (int j = 0; j < 64; j++) {
            int key = s0 + j;
            float acc = 0.f;
            #pragma unroll
            for (int cc = 0; cc < 16; cc++) {
                float4 k4 = *(const float4*)&ks[j][cc * 4];
                acc += qv[cc*4+0]*k4.x + qv[cc*4+1]*k4.y
                     + qv[cc*4+2]*k4.z + qv[cc*4+3]*k4.w;
            }
            acc *= scale;
            bool ok = (key <= q_idx) && (key >= q_idx - WIN);
            s[j] = ok ? acc : NEG_BIG;
            tmax = fmaxf(tmax, s[j]);
        }

        float newm = fmaxf(mrow, tmax);
        if (newm > -1e29f) {
            float corr = (mrow <= -1e29f) ? 0.f : __expf(mrow - newm);
            l *= corr;
            #pragma unroll
            for (int d = 0; d < 64; d++) o[d] *= corr;
            #pragma unroll 2
            for (int j = 0; j < 64; j++) {
                if (s[j] > -1e29f) {
                    float p = __expf(s[j] - newm);
                    l += p;
                    #pragma unroll
                    for (int cc = 0; cc < 16; cc++) {
                        float4 v4 = *(const float4*)&vs[j][cc * 4];
                        o[cc*4+0] += p * v4.x; o[cc*4+1] += p * v4.y;
                        o[cc*4+2] += p * v4.z; o[cc*4+3] += p * v4.w;
                    }
                }
            }
            mrow = newm;
        }
        __syncthreads();
    }

    float inv = 1.f / l;
    int b = bh / NH, h = bh % NH;
    float* outp = g_local + ((size_t)(b * TSEQ + q_idx)) * HKD + h * HD;
    #pragma unroll
    for (int cc = 0; cc < 16; cc++) {
        float4 t4;
        t4.x = o[cc*4+0]*inv; t4.y = o[cc*4+1]*inv;
        t4.z = o[cc*4+2]*inv; t4.w = o[cc*4+3]*inv;
        *(float4*)(outp + cc * 4) = t4;
    }
}

// ---------------------------------------------------------------------------
// GDN retrieval: per (b,h): (T,K) @ (K,V). Block = (b,h, 128-row tile of T).
// ---------------------------------------------------------------------------
__global__ __launch_bounds__(128) void retr_k(const float* __restrict__ state) {
    int bid = blockIdx.x;
    int tt = bid & 15;           // T/128 = 16
    int bh = bid >> 4;
    __shared__ float st[64][68];
    __shared__ float qs[128][65];

    const float* sp = state + (size_t)bh * HD * HD;
    for (int i = threadIdx.x; i < HD * HD; i += 128)
        st[i >> 6][i & 63] = sp[i];
    size_t qbase = (size_t)bh * TSEQ * HD + (size_t)tt * 128 * HD;
    for (int i = threadIdx.x; i < 128 * HD; i += 128)
        qs[i >> 6][i & 63] = g_qg[qbase + i];
    __syncthreads();

    int t = tt * 128 + threadIdx.x;
    float acc[64];
    #pragma unroll
    for (int v = 0; v < 64; v++) acc[v] = 0.f;
    for (int k = 0; k < 64; k++) {
        float qk = qs[threadIdx.x][k];
        #pragma unroll
        for (int cc = 0; cc < 16; cc++) {
            float4 s4 = *(const float4*)&st[k][cc * 4];
            acc[cc*4+0] += qk * s4.x; acc[cc*4+1] += qk * s4.y;
            acc[cc*4+2] += qk * s4.z; acc[cc*4+3] += qk * s4.w;
        }
    }
    int b = bh / NH, h = bh % NH;
    float* outp = g_retr + ((size_t)(b * TSEQ + t)) * HKD + h * HD;
    #pragma unroll
    for (int cc = 0; cc < 16; cc++) {
        float4 t4;
        t4.x = acc[cc*4+0]; t4.y = acc[cc*4+1];
        t4.z = acc[cc*4+2]; t4.w = acc[cc*4+3];
        *(float4*)(outp + cc * 4) = t4;
    }
}

// ---------------------------------------------------------------------------
// Gate: g_gate[row] = mean_h sigmoid(xn[row]@Wg[:,h] + bg[h]). Block per row.
// ---------------------------------------------------------------------------
__global__ __launch_bounds__(256) void gate_k(const float* __restrict__ Wg,
                                              const float* __restrict__ bg) {
    int row = blockIdx.x;
    float acc[NH];
    #pragma unroll
    for (int h = 0; h < NH; h++) acc[h] = 0.f;
    for (int d = threadIdx.x; d < DIM; d += 256) {
        float xv = g_xn[(size_t)row * DIM + d];
        #pragma unroll
        for (int h = 0; h < NH; h++) acc[h] += xv * Wg[d * NH + h];
    }
    #pragma unroll
    for (int h = 0; h < NH; h++) {
        #pragma unroll
        for (int o = 16; o; o >>= 1) acc[h] += __shfl_xor_sync(0xffffffffu, acc[h], o);
    }
    __shared__ float red[8][NH];
    int wid = threadIdx.x >> 5, lane = threadIdx.x & 31;
    if (lane == 0) {
        #pragma unroll
        for (int h = 0; h < NH; h++) red[wid][h] = acc[h];
    }
    __syncthreads();
    if (threadIdx.x == 0) {
        float s = 0.f;
        #pragma unroll
        for (int h = 0; h < NH; h++) {
            float a = 0.f;
            #pragma unroll
            for (int w = 0; w < 8; w++) a += red[w][h];
            s += 1.f / (1.f + expf(-(a + bg[h])));
        }
        g_gate[row] = s * (1.f / (float)NH);
    }
}

// ---------------------------------------------------------------------------
// Launch
// ---------------------------------------------------------------------------
extern "C" void kernel_launch(void* const* d_in, const int* in_sizes, int n_in,
                              void* d_out, int out_size) {
    const float* x      = (const float*)d_in[0];
    const float* state  = (const float*)d_in[1];
    const float* Wq     = (const float*)d_in[2];
    const float* Wk     = (const float*)d_in[3];
    const float* Wv     = (const float*)d_in[4];
    const float* Wo     = (const float*)d_in[5];
    const float* Wgq    = (const float*)d_in[6];
    const float* Wro    = (const float*)d_in[7];
    const float* Wg     = (const float*)d_in[8];
    const float* bg     = (const float*)d_in[9];
    const float* norm_w = (const float*)d_in[10];
    float* out = (float*)d_out;

    float *p_xn, *p_local, *p_retr, *p_gate;
    cudaGetSymbolAddress((void**)&p_xn,    g_xn);
    cudaGetSymbolAddress((void**)&p_local, g_local);
    cudaGetSymbolAddress((void**)&p_retr,  g_retr);
    cudaGetSymbolAddress((void**)&p_gate,  g_gate);

    rmsnorm_k<<<ROWS, 256>>>(x, norm_w);

    // fused q/k/v/qg projections on tensor cores
    proj_tc<<<dim3(GN / BN, ROWS / BM, 4), 256>>>(p_xn, Wq, Wk, Wv, Wgq);

    gate_k<<<ROWS, 256>>>(Wg, bg);

    attn_k<<<BSZ * NH * (TSEQ / 64), 64>>>();                 // 768 blocks
    retr_k<<<BSZ * NH * (TSEQ / 128), 128>>>(state);          // 384 blocks

    // out = x + local @ Wo
    gemm_out_tc<<<dim3(GN / BN, ROWS / BM), 256>>>(p_local, Wo, out, x, nullptr, 0);
    // out += gate_mean .* (retr @ Wro)
    gemm_out_tc<<<dim3(GN / BN, ROWS / BM), 256>>>(p_retr, Wro, out, nullptr, p_gate, 1);
}

// round 3
// speedup vs baseline: 3.3083x; 1.8391x over previous
#include <cuda_runtime.h>
#include <math.h>
#include <stdint.h>

// Problem constants
#define BSZ  2
#define TSEQ 2048
#define DIM  768
#define NH   12
#define HD   64          // head dim (K == V == 64)
#define WIN  1024
#define ROWS (BSZ*TSEQ)  // 4096
#define HKD  (NH*HD)     // 768 == DIM
#define REPS 1e-6f
#define NEG_BIG (-1e30f)

// GEMM tiling (all big GEMMs are 4096 x 768 x 768)
#define GK   768
#define GN   768
#define BM   128
#define BN   64
#define BKT  32

// ---------------------------------------------------------------------------
// Scratch (static device globals; no allocation at runtime)
// ---------------------------------------------------------------------------
__device__ float g_xn[ROWS*DIM];            // rmsnorm(x)
__device__ float g_q [BSZ*NH*TSEQ*HD];      // (B,H,T,K)
__device__ float g_k [BSZ*NH*TSEQ*HD];
__device__ float g_v [BSZ*NH*TSEQ*HD];
__device__ float g_qg[BSZ*NH*TSEQ*HD];      // relu(xn@Wgq), (B,H,T,K)
__device__ float g_local[ROWS*HKD];         // attention out, (B,T,H*K)
__device__ float g_retr [ROWS*HKD];         // retrieval,     (B,T,H*V)
__device__ float g_gate [ROWS];             // mean sigmoid gate per row

// ---------------------------------------------------------------------------
// RMSNorm: one block per row
// ---------------------------------------------------------------------------
__global__ __launch_bounds__(256) void rmsnorm_k(const float* __restrict__ x,
                                                 const float* __restrict__ nw) {
    int row = blockIdx.x;
    const float* xr = x + (size_t)row * DIM;
    float ss = 0.f;
    for (int d = threadIdx.x; d < DIM; d += 256) { float v = xr[d]; ss += v * v; }
    #pragma unroll
    for (int o = 16; o; o >>= 1) ss += __shfl_xor_sync(0xffffffffu, ss, o);
    __shared__ float red[8];
    __shared__ float s_rinv;
    int wid = threadIdx.x >> 5, lane = threadIdx.x & 31;
    if (lane == 0) red[wid] = ss;
    __syncthreads();
    if (threadIdx.x == 0) {
        float t = 0.f;
        #pragma unroll
        for (int i = 0; i < 8; i++) t += red[i];
        s_rinv = rsqrtf(t / (float)DIM + REPS);
    }
    __syncthreads();
    float r = s_rinv;
    for (int d = threadIdx.x; d < DIM; d += 256)
        g_xn[(size_t)row * DIM + d] = xr[d] * r * nw[d];
}

// ---------------------------------------------------------------------------
// TF32 mma helpers
// ---------------------------------------------------------------------------
__device__ __forceinline__ uint32_t f2tf32(float f) {
    uint32_t u;
    asm("cvt.rna.tf32.f32 %0, %1;" : "=r"(u) : "f"(f));
    return u;
}

__device__ __forceinline__ void mma_tf32(float c[4], const uint32_t a[4], const uint32_t b[2]) {
    asm volatile(
        "mma.sync.aligned.m16n8k8.row.col.f32.tf32.tf32.f32 "
        "{%0,%1,%2,%3}, {%4,%5,%6,%7}, {%8,%9}, {%0,%1,%2,%3};\n"
        : "+f"(c[0]), "+f"(c[1]), "+f"(c[2]), "+f"(c[3])
        : "r"(a[0]), "r"(a[1]), "r"(a[2]), "r"(a[3]), "r"(b[0]), "r"(b[1]));
}

// fast 2^x for x <= 0 (clamped), rel err ~2e-6, FMA pipe only (no MUFU)
__device__ __forceinline__ float exp2_fast(float x) {
    x = fmaxf(x, -120.f);
    float t  = x + 12582912.f;          // 1.5*2^23: round-to-nearest
    float fl = t - 12582912.f;          // round(x)
    float f  = x - fl;                  // f in [-0.5, 0.5]
    int   n  = __float_as_int(t) - 0x4B400000;
    float r  = 1.3333558e-3f;           // ln2^5/120
    r = fmaf(r, f, 9.6181291e-3f);      // ln2^4/24
    r = fmaf(r, f, 5.5504109e-2f);      // ln2^3/6
    r = fmaf(r, f, 2.4022651e-1f);      // ln2^2/2
    r = fmaf(r, f, 6.9314718e-1f);      // ln2
    r = fmaf(r, f, 1.0f);
    return r * __int_as_float((n + 127) << 23);
}

// ---------------------------------------------------------------------------
// TF32 tensor-core GEMM core: 128x64 block tile, BK=32, 8 warps (4x2),
// warp tile 32x32 = 2(m) x 4(n) mma.m16n8k8 tiles.
// ---------------------------------------------------------------------------
struct GemmSmem {
    uint32_t As[BM][36];
    uint32_t Bs[BKT][72];
};

__device__ __forceinline__ void gemm_core(
    GemmSmem* s, const float* __restrict__ A, const float* __restrict__ B,
    int m0, int n0, float c[2][4][4])
{
    int tid = threadIdx.x;
    int lane = tid & 31, wid = tid >> 5;
    int wm = wid & 3, wn = wid >> 2;
    int r = lane >> 2, cq = lane & 3;

    for (int k0 = 0; k0 < GK; k0 += BKT) {
        float4 av[4], bv[2];
        #pragma unroll
        for (int p = 0; p < 4; p++) {
            int idx = tid + p * 256;
            int row = idx >> 3, c4 = (idx & 7) * 4;
            av[p] = *(const float4*)(A + (size_t)(m0 + row) * GK + k0 + c4);
        }
        #pragma unroll
        for (int p = 0; p < 2; p++) {
            int idx = tid + p * 256;
            int row = idx >> 4, c4 = (idx & 15) * 4;
            bv[p] = *(const float4*)(B + (size_t)(k0 + row) * GN + n0 + c4);
        }
        __syncthreads();
        #pragma unroll
        for (int p = 0; p < 4; p++) {
            int idx = tid + p * 256;
            int row = idx >> 3, c4 = (idx & 7) * 4;
            s->As[row][c4 + 0] = f2tf32(av[p].x);
            s->As[row][c4 + 1] = f2tf32(av[p].y);
            s->As[row][c4 + 2] = f2tf32(av[p].z);
            s->As[row][c4 + 3] = f2tf32(av[p].w);
        }
        #pragma unroll
        for (int p = 0; p < 2; p++) {
            int idx = tid + p * 256;
            int row = idx >> 4, c4 = (idx & 15) * 4;
            s->Bs[row][c4 + 0] = f2tf32(bv[p].x);
            s->Bs[row][c4 + 1] = f2tf32(bv[p].y);
            s->Bs[row][c4 + 2] = f2tf32(bv[p].z);
            s->Bs[row][c4 + 3] = f2tf32(bv[p].w);
        }
        __syncthreads();

        #pragma unroll
        for (int ks = 0; ks < 4; ks++) {
            int kb = ks * 8;
            uint32_t af[2][4];
            #pragma unroll
            for (int mt = 0; mt < 2; mt++) {
                int mr = wm * 32 + mt * 16 + r;
                af[mt][0] = s->As[mr    ][kb + cq];
                af[mt][1] = s->As[mr + 8][kb + cq];
                af[mt][2] = s->As[mr    ][kb + cq + 4];
                af[mt][3] = s->As[mr + 8][kb + cq + 4];
            }
            uint32_t bf[4][2];
            #pragma unroll
            for (int nt = 0; nt < 4; nt++) {
                int nc = wn * 32 + nt * 8 + r;
                bf[nt][0] = s->Bs[kb + cq    ][nc];
                bf[nt][1] = s->Bs[kb + cq + 4][nc];
            }
            #pragma unroll
            for (int mt = 0; mt < 2; mt++)
                #pragma unroll
                for (int nt = 0; nt < 4; nt++)
                    mma_tf32(c[mt][nt], af[mt], bf[nt]);
        }
    }
}

// ---------------------------------------------------------------------------
// Fused projection GEMMs: z selects {Wq,Wk,Wv,Wgq} -> {q,k,v,qg}; scatter BHTK.
// ---------------------------------------------------------------------------
__global__ __launch_bounds__(256) void proj_tc(
    const float* __restrict__ Xn,
    const float* __restrict__ Wq, const float* __restrict__ Wk,
    const float* __restrict__ Wv, const float* __restrict__ Wgq)
{
    __shared__ GemmSmem s;
    int z = blockIdx.z;
    const float* B = (z == 0) ? Wq : (z == 1) ? Wk : (z == 2) ? Wv : Wgq;
    float* C       = (z == 0) ? g_q : (z == 1) ? g_k : (z == 2) ? g_v : g_qg;
    bool relu = (z == 3);

    int m0 = blockIdx.y * BM, n0 = blockIdx.x * BN;
    float c[2][4][4] = {};
    gemm_core(&s, Xn, B, m0, n0, c);

    int lane = threadIdx.x & 31, wid = threadIdx.x >> 5;
    int wm = wid & 3, wn = wid >> 2;
    int r = lane >> 2, cq = lane & 3;
    #pragma unroll
    for (int mt = 0; mt < 2; mt++) {
        #pragma unroll
        for (int nt = 0; nt < 4; nt++) {
            int col = n0 + wn * 32 + nt * 8 + 2 * cq;
            int h = col >> 6, kk = col & 63;
            #pragma unroll
            for (int i = 0; i < 2; i++) {
                int row = m0 + wm * 32 + mt * 16 + r + i * 8;
                int b = row >> 11, t = row & (TSEQ - 1);
                float v0 = c[mt][nt][i * 2 + 0];
                float v1 = c[mt][nt][i * 2 + 1];
                if (relu) { v0 = fmaxf(v0, 0.f); v1 = fmaxf(v1, 0.f); }
                float2 o; o.x = v0; o.y = v1;
                *(float2*)(C + (((size_t)(b * NH + h) * TSEQ + t) << 6) + kk) = o;
            }
        }
    }
}

// ---------------------------------------------------------------------------
// Output GEMMs with fused epilogues.
// ---------------------------------------------------------------------------
__global__ __launch_bounds__(256) void gemm_out_tc(
    const float* __restrict__ A, const float* __restrict__ B, float* __restrict__ C,
    const float* __restrict__ addsrc, const float* __restrict__ rowscale, int accum)
{
    __shared__ GemmSmem s;
    int m0 = blockIdx.y * BM, n0 = blockIdx.x * BN;
    float c[2][4][4] = {};
    gemm_core(&s, A, B, m0, n0, c);

    int lane = threadIdx.x & 31, wid = threadIdx.x >> 5;
    int wm = wid & 3, wn = wid >> 2;
    int r = lane >> 2, cq = lane & 3;
    #pragma unroll
    for (int mt = 0; mt < 2; mt++) {
        #pragma unroll
        for (int i = 0; i < 2; i++) {
            int row = m0 + wm * 32 + mt * 16 + r + i * 8;
            float rs = rowscale ? rowscale[row] : 1.f;
            #pragma unroll
            for (int nt = 0; nt < 4; nt++) {
                int col = n0 + wn * 32 + nt * 8 + 2 * cq;
                float v0 = c[mt][nt][i * 2 + 0] * rs;
                float v1 = c[mt][nt][i * 2 + 1] * rs;
                size_t idx = (size_t)row * GN + col;
                if (addsrc) {
                    float2 a2 = *(const float2*)(addsrc + idx);
                    v0 += a2.x; v1 += a2.y;
                }
                if (accum) {
                    float2 p = *(const float2*)(C + idx);
                    v0 += p.x; v1 += p.y;
                }
                float2 o; o.x = v0; o.y = v1;
                *(float2*)(C + idx) = o;
            }
        }
    }
}

// ---------------------------------------------------------------------------
// Tensor-core sliding-window flash attention.
// Block: 128 queries x (b,h). 8 warps; warp w owns query rows [w*16, w*16+16).
// Per 64-key tile: S = Q@K^T (mma), online softmax (poly exp2), O += P@V (mma).
// Dynamic smem: Qs[128][68] | Ps[128][68] | Ks[64][72] | Vs[64][72]  (104 KB)
// ---------------------------------------------------------------------------
#define ATTN_SMEM_WORDS (2*128*68 + 2*64*72)
#define ATTN_SMEM_BYTES (ATTN_SMEM_WORDS * 4)

__global__ __launch_bounds__(256, 2) void attn_tc() {
    extern __shared__ uint32_t sm[];
    uint32_t (*Qs)[68] = (uint32_t(*)[68])(sm);
    uint32_t (*Ps)[68] = (uint32_t(*)[68])(sm + 128*68);
    uint32_t (*Ks)[72] = (uint32_t(*)[72])(sm + 2*128*68);
    uint32_t (*Vs)[72] = (uint32_t(*)[72])(sm + 2*128*68 + 64*72);

    int qt = blockIdx.x;           // 16 query tiles of 128
    int bh = blockIdx.y;           // 24
    int q0 = qt * 128;
    int tid = threadIdx.x, lane = tid & 31, wid = tid >> 5;
    int r = lane >> 2, cq = lane & 3;
    size_t base = (size_t)bh * TSEQ * HD;

    // stage Q once (tf32, A-fragment layout)
    {
        const float* Qg = g_q + base + (size_t)q0 * HD;
        #pragma unroll
        for (int p = 0; p < 8; p++) {
            int idx = tid + p * 256;             // 2048 float4 loads
            int row = idx >> 4, d4 = (idx & 15) * 4;
            float4 t4 = *(const float4*)(Qg + (size_t)row * HD + d4);
            uint4 u; u.x = f2tf32(t4.x); u.y = f2tf32(t4.y);
                     u.z = f2tf32(t4.z); u.w = f2tf32(t4.w);
            *(uint4*)&Qs[row][d4] = u;
        }
    }
    __syncthreads();

    float of[8][4] = {};                 // O accum (rows r, r+8 of warp tile)
    float mz[2] = {NEG_BIG, NEG_BIG};    // running max (log2 domain)
    float lv[2] = {0.f, 0.f};            // running denom
    const float zscale = 0.125f * 1.44269504f;   // scale * log2(e)
    int mr = wid * 16 + r;

    int kstart = q0 - WIN; if (kstart < 0) kstart = 0;
    for (int s0 = kstart; s0 <= q0 + 64; s0 += 64) {
        __syncthreads();   // prior mma2 done before K/V overwrite
        // K tile, transposed: Ks[d][key]
        #pragma unroll
        for (int p = 0; p < 4; p++) {
            int idx = tid + p * 256;
            int key = idx & 63, d4 = (idx >> 6) * 4;
            float4 t4 = *(const float4*)(g_k + base + (size_t)(s0 + key) * HD + d4);
            Ks[d4 + 0][key] = f2tf32(t4.x);
            Ks[d4 + 1][key] = f2tf32(t4.y);
            Ks[d4 + 2][key] = f2tf32(t4.z);
            Ks[d4 + 3][key] = f2tf32(t4.w);
        }
        // V tile, direct: Vs[key][d]
        #pragma unroll
        for (int p = 0; p < 4; p++) {
            int idx = tid + p * 256;
            int key = idx >> 4, d4 = (idx & 15) * 4;
            float4 t4 = *(const float4*)(g_v + base + (size_t)(s0 + key) * HD + d4);
            uint4 u; u.x = f2tf32(t4.x); u.y = f2tf32(t4.y);
                     u.z = f2tf32(t4.z); u.w = f2tf32(t4.w);
            *(uint4*)&Vs[key][d4] = u;
        }
        __syncthreads();

        // ---- S = Q @ K^T ----
        float sf[8][4] = {};
        #pragma unroll
        for (int ks = 0; ks < 8; ks++) {
            uint32_t a[4];
            a[0] = Qs[mr    ][ks * 8 + cq];
            a[1] = Qs[mr + 8][ks * 8 + cq];
            a[2] = Qs[mr    ][ks * 8 + cq + 4];
            a[3] = Qs[mr + 8][ks * 8 + cq + 4];
            #pragma unroll
            for (int nt = 0; nt < 8; nt++) {
                uint32_t b[2];
                b[0] = Ks[ks * 8 + cq    ][nt * 8 + r];
                b[1] = Ks[ks * 8 + cq + 4][nt * 8 + r];
                mma_tf32(sf[nt], a, b);
            }
        }

        // ---- scale to log2 domain (+ mask on boundary tiles) ----
        bool need_mask = (s0 >= q0) || (s0 + WIN < q0 + 128);
        if (need_mask) {
            int q_lo = q0 + wid * 16 + r;
            #pragma unroll
            for (int nt = 0; nt < 8; nt++) {
                #pragma unroll
                for (int j = 0; j < 4; j++) {
                    int key = s0 + nt * 8 + 2 * cq + (j & 1);
                    int q = q_lo + (j >> 1) * 8;
                    bool ok = (key <= q) && (key >= q - WIN);
                    sf[nt][j] = ok ? sf[nt][j] * zscale : NEG_BIG;
                }
            }
        } else {
            #pragma unroll
            for (int nt = 0; nt < 8; nt++)
                #pragma unroll
                for (int j = 0; j < 4; j++) sf[nt][j] *= zscale;
        }

        // ---- online softmax (rows r and r+8) ----
        float mx0 = NEG_BIG, mx1 = NEG_BIG;
        #pragma unroll
        for (int nt = 0; nt < 8; nt++) {
            mx0 = fmaxf(mx0, fmaxf(sf[nt][0], sf[nt][1]));
            mx1 = fmaxf(mx1, fmaxf(sf[nt][2], sf[nt][3]));
        }
        mx0 = fmaxf(mx0, __shfl_xor_sync(0xffffffffu, mx0, 1));
        mx0 = fmaxf(mx0, __shfl_xor_sync(0xffffffffu, mx0, 2));
        mx1 = fmaxf(mx1, __shfl_xor_sync(0xffffffffu, mx1, 1));
        mx1 = fmaxf(mx1, __shfl_xor_sync(0xffffffffu, mx1, 2));
        float nm0 = fmaxf(mz[0], mx0);
        float nm1 = fmaxf(mz[1], mx1);
        float c0 = exp2_fast(mz[0] - nm0);
        float c1 = exp2_fast(mz[1] - nm1);

        float rs0 = 0.f, rs1 = 0.f;
        #pragma unroll
        for (int nt = 0; nt < 8; nt++) {
            float p00 = exp2_fast(sf[nt][0] - nm0);
            float p01 = exp2_fast(sf[nt][1] - nm0);
            float p10 = exp2_fast(sf[nt][2] - nm1);
            float p11 = exp2_fast(sf[nt][3] - nm1);
            rs0 += p00 + p01;
            rs1 += p10 + p11;
            uint2 u0; u0.x = f2tf32(p00); u0.y = f2tf32(p01);
            uint2 u1; u1.x = f2tf32(p10); u1.y = f2tf32(p11);
            *(uint2*)&Ps[mr    ][nt * 8 + 2 * cq] = u0;
            *(uint2*)&Ps[mr + 8][nt * 8 + 2 * cq] = u1;
        }
        rs0 += __shfl_xor_sync(0xffffffffu, rs0, 1);
        rs0 += __shfl_xor_sync(0xffffffffu, rs0, 2);
        rs1 += __shfl_xor_sync(0xffffffffu, rs1, 1);
        rs1 += __shfl_xor_sync(0xffffffffu, rs1, 2);
        lv[0] = lv[0] * c0 + rs0;
        lv[1] = lv[1] * c1 + rs1;
        mz[0] = nm0; mz[1] = nm1;
        #pragma unroll
        for (int nt = 0; nt < 8; nt++) {
            of[nt][0] *= c0; of[nt][1] *= c0;
            of[nt][2] *= c1; of[nt][3] *= c1;
        }
        __syncwarp();   // P visible across lanes of this warp

        // ---- O += P @ V ----
        #pragma unroll
        for (int ks = 0; ks < 8; ks++) {
            uint32_t a[4];
            a[0] = Ps[mr    ][ks * 8 + cq];
            a[1] = Ps[mr + 8][ks * 8 + cq];
            a[2] = Ps[mr    ][ks * 8 + cq + 4];
            a[3] = Ps[mr + 8][ks * 8 + cq + 4];
            #pragma unroll
            for (int nt = 0; nt < 8; nt++) {
                uint32_t b[2];
                b[0] = Vs[ks * 8 + cq    ][nt * 8 + r];
                b[1] = Vs[ks * 8 + cq + 4][nt * 8 + r];
                mma_tf32(of[nt], a, b);
            }
        }
    }

    // ---- normalize + write to g_local (B,T,H*64) ----
    int b = bh / NH, h = bh % NH;
    float inv0 = 1.f / lv[0], inv1 = 1.f / lv[1];
    int qa = q0 + wid * 16 + r;
    #pragma unroll
    for (int nt = 0; nt < 8; nt++) {
        int col = h * HD + nt * 8 + 2 * cq;
        float2 o0; o0.x = of[nt][0] * inv0; o0.y = of[nt][1] * inv0;
        float2 o1; o1.x = of[nt][2] * inv1; o1.y = of[nt][3] * inv1;
        *(float2*)(g_local + ((size_t)(b * TSEQ + qa    )) * HKD + col) = o0;
        *(float2*)(g_local + ((size_t)(b * TSEQ + qa + 8)) * HKD + col) = o1;
    }
}

// ---------------------------------------------------------------------------
// GDN retrieval: per (b,h): (T,K) @ (K,V). Block = (b,h, 128-row tile of T).
// ---------------------------------------------------------------------------
__global__ __launch_bounds__(128) void retr_k(const float* __restrict__ state) {
    int bid = blockIdx.x;
    int tt = bid & 15;
    int bh = bid >> 4;
    __shared__ float st[64][68];
    __shared__ float qs[128][65];

    const float* sp = state + (size_t)bh * HD * HD;
    for (int i = threadIdx.x; i < HD * HD; i += 128)
        st[i >> 6][i & 63] = sp[i];
    size_t qbase = (size_t)bh * TSEQ * HD + (size_t)tt * 128 * HD;
    for (int i = threadIdx.x; i < 128 * HD; i += 128)
        qs[i >> 6][i & 63] = g_qg[qbase + i];
    __syncthreads();

    int t = tt * 128 + threadIdx.x;
    float acc[64];
    #pragma unroll
    for (int v = 0; v < 64; v++) acc[v] = 0.f;
    for (int k = 0; k < 64; k++) {
        float qk = qs[threadIdx.x][k];
        #pragma unroll
        for (int cc = 0; cc < 16; cc++) {
            float4 s4 = *(const float4*)&st[k][cc * 4];
            acc[cc*4+0] += qk * s4.x; acc[cc*4+1] += qk * s4.y;
            acc[cc*4+2] += qk * s4.z; acc[cc*4+3] += qk * s4.w;
        }
    }
    int b = bh / NH, h = bh % NH;
    float* outp = g_retr + ((size_t)(b * TSEQ + t)) * HKD + h * HD;
    #pragma unroll
    for (int cc = 0; cc < 16; cc++) {
        float4 t4;
        t4.x = acc[cc*4+0]; t4.y = acc[cc*4+1];
        t4.z = acc[cc*4+2]; t4.w = acc[cc*4+3];
        *(float4*)(outp + cc * 4) = t4;
    }
}

// ---------------------------------------------------------------------------
// Gate: g_gate[row] = mean_h sigmoid(xn[row]@Wg[:,h] + bg[h]). Block per row.
// ---------------------------------------------------------------------------
__global__ __launch_bounds__(256) void gate_k(const float* __restrict__ Wg,
                                              const float* __restrict__ bg) {
    int row = blockIdx.x;
    float acc[NH];
    #pragma unroll
    for (int h = 0; h < NH; h++) acc[h] = 0.f;
    for (int d = threadIdx.x; d < DIM; d += 256) {
        float xv = g_xn[(size_t)row * DIM + d];
        #pragma unroll
        for (int h = 0; h < NH; h++) acc[h] += xv * Wg[d * NH + h];
    }
    #pragma unroll
    for (int h = 0; h < NH; h++) {
        #pragma unroll
        for (int o = 16; o; o >>= 1) acc[h] += __shfl_xor_sync(0xffffffffu, acc[h], o);
    }
    __shared__ float red[8][NH];
    int wid = threadIdx.x >> 5, lane = threadIdx.x & 31;
    if (lane == 0) {
        #pragma unroll
        for (int h = 0; h < NH; h++) red[wid][h] = acc[h];
    }
    __syncthreads();
    if (threadIdx.x == 0) {
        float s = 0.f;
        #pragma unroll
        for (int h = 0; h < NH; h++) {
            float a = 0.f;
            #pragma unroll
            for (int w = 0; w < 8; w++) a += red[w][h];
            s += 1.f / (1.f + expf(-(a + bg[h])));
        }
        g_gate[row] = s * (1.f / (float)NH);
    }
}

// ---------------------------------------------------------------------------
// Launch
// ---------------------------------------------------------------------------
extern "C" void kernel_launch(void* const* d_in, const int* in_sizes, int n_in,
                              void* d_out, int out_size) {
    const float* x      = (const float*)d_in[0];
    const float* state  = (const float*)d_in[1];
    const float* Wq     = (const float*)d_in[2];
    const float* Wk     = (const float*)d_in[3];
    const float* Wv     = (const float*)d_in[4];
    const float* Wo     = (const float*)d_in[5];
    const float* Wgq    = (const float*)d_in[6];
    const float* Wro    = (const float*)d_in[7];
    const float* Wg     = (const float*)d_in[8];
    const float* bg     = (const float*)d_in[9];
    const float* norm_w = (const float*)d_in[10];
    float* out = (float*)d_out;

    float *p_xn, *p_local, *p_retr, *p_gate;
    cudaGetSymbolAddress((void**)&p_xn,    g_xn);
    cudaGetSymbolAddress((void**)&p_local, g_local);
    cudaGetSymbolAddress((void**)&p_retr,  g_retr);
    cudaGetSymbolAddress((void**)&p_gate,  g_gate);

    cudaFuncSetAttribute(attn_tc, cudaFuncAttributeMaxDynamicSharedMemorySize,
                         ATTN_SMEM_BYTES);

    rmsnorm_k<<<ROWS, 256>>>(x, norm_w);

    // fused q/k/v/qg projections on tensor cores
    proj_tc<<<dim3(GN / BN, ROWS / BM, 4), 256>>>(p_xn, Wq, Wk, Wv, Wgq);

    gate_k<<<ROWS, 256>>>(Wg, bg);

    attn_tc<<<dim3(TSEQ / 128, BSZ * NH), 256, ATTN_SMEM_BYTES>>>();
    retr_k<<<BSZ * NH * (TSEQ / 128), 128>>>(state);

    // out = x + local @ Wo
    gemm_out_tc<<<dim3(GN / BN, ROWS / BM), 256>>>(p_local, Wo, out, x, nullptr, 0);
    // out += gate_mean .* (retr @ Wro)
    gemm_out_tc<<<dim3(GN / BN, ROWS / BM), 256>>>(p_retr, Wro, out, nullptr, p_gate, 1);
}

// round 4
// speedup vs baseline: 3.7755x; 1.1412x over previous
#include <cuda_runtime.h>
#include <cuda_bf16.h>
#include <math.h>
#include <stdint.h>

// Problem constants
#define BSZ  2
#define TSEQ 2048
#define DIM  768
#define NH   12
#define HD   64
#define WIN  1024
#define ROWS (BSZ*TSEQ)  // 4096
#define HKD  (NH*HD)     // 768
#define REPS 1e-6f
#define NEG_BIG (-1e30f)

#define GK   768
#define GN   768
#define BM   128
#define BN   64
#define BKT  32

// ---------------------------------------------------------------------------
// Scratch
// ---------------------------------------------------------------------------
__device__ float          g_xn[ROWS*DIM];
__device__ __nv_bfloat16  g_qb[BSZ*NH*TSEQ*HD];   // bf16 (B,H,T,K)
__device__ __nv_bfloat16  g_kb[BSZ*NH*TSEQ*HD];
__device__ __nv_bfloat16  g_vb[BSZ*NH*TSEQ*HD];
__device__ float          g_qg[BSZ*NH*TSEQ*HD];   // relu(xn@Wgq) f32
__device__ float          g_local[ROWS*HKD];
__device__ float          g_retr [ROWS*HKD];      // gate-scaled retrieval
__device__ float          g_gate [ROWS];

// ---------------------------------------------------------------------------
// RMSNorm
// ---------------------------------------------------------------------------
__global__ __launch_bounds__(256) void rmsnorm_k(const float* __restrict__ x,
                                                 const float* __restrict__ nw) {
    int row = blockIdx.x;
    const float* xr = x + (size_t)row * DIM;
    float ss = 0.f;
    for (int d = threadIdx.x; d < DIM; d += 256) { float v = xr[d]; ss += v * v; }
    #pragma unroll
    for (int o = 16; o; o >>= 1) ss += __shfl_xor_sync(0xffffffffu, ss, o);
    __shared__ float red[8];
    __shared__ float s_rinv;
    int wid = threadIdx.x >> 5, lane = threadIdx.x & 31;
    if (lane == 0) red[wid] = ss;
    __syncthreads();
    if (threadIdx.x == 0) {
        float t = 0.f;
        #pragma unroll
        for (int i = 0; i < 8; i++) t += red[i];
        s_rinv = rsqrtf(t / (float)DIM + REPS);
    }
    __syncthreads();
    float r = s_rinv;
    for (int d = threadIdx.x; d < DIM; d += 256)
        g_xn[(size_t)row * DIM + d] = xr[d] * r * nw[d];
}

// ---------------------------------------------------------------------------
// mma helpers
// ---------------------------------------------------------------------------
__device__ __forceinline__ uint32_t f2tf32(float f) {
    uint32_t u;
    asm("cvt.rna.tf32.f32 %0, %1;" : "=r"(u) : "f"(f));
    return u;
}
__device__ __forceinline__ uint32_t pack_bf16(float lo, float hi) {
    uint32_t d;
    asm("cvt.rn.bf16x2.f32 %0, %1, %2;" : "=r"(d) : "f"(hi), "f"(lo));
    return d;
}
__device__ __forceinline__ void mma_tf32(float c[4], const uint32_t a[4], const uint32_t b[2]) {
    asm volatile(
        "mma.sync.aligned.m16n8k8.row.col.f32.tf32.tf32.f32 "
        "{%0,%1,%2,%3}, {%4,%5,%6,%7}, {%8,%9}, {%0,%1,%2,%3};\n"
        : "+f"(c[0]), "+f"(c[1]), "+f"(c[2]), "+f"(c[3])
        : "r"(a[0]), "r"(a[1]), "r"(a[2]), "r"(a[3]), "r"(b[0]), "r"(b[1]));
}
__device__ __forceinline__ void mma_bf16(float c[4], const uint32_t a[4], const uint32_t b[2]) {
    asm volatile(
        "mma.sync.aligned.m16n8k16.row.col.f32.bf16.bf16.f32 "
        "{%0,%1,%2,%3}, {%4,%5,%6,%7}, {%8,%9}, {%0,%1,%2,%3};\n"
        : "+f"(c[0]), "+f"(c[1]), "+f"(c[2]), "+f"(c[3])
        : "r"(a[0]), "r"(a[1]), "r"(a[2]), "r"(a[3]), "r"(b[0]), "r"(b[1]));
}

// fast 2^x for x <= 0 (clamped), FMA pipe only
__device__ __forceinline__ float exp2_fast(float x) {
    x = fmaxf(x, -120.f);
    float t  = x + 12582912.f;
    float fl = t - 12582912.f;
    float f  = x - fl;
    int   n  = __float_as_int(t) - 0x4B400000;
    float r  = 1.3333558e-3f;
    r = fmaf(r, f, 9.6181291e-3f);
    r = fmaf(r, f, 5.5504109e-2f);
    r = fmaf(r, f, 2.4022651e-1f);
    r = fmaf(r, f, 6.9314718e-1f);
    r = fmaf(r, f, 1.0f);
    return r * __int_as_float((n + 127) << 23);
}

// ---------------------------------------------------------------------------
// Pipelined TF32 GEMM core: 128x64 tile, BK=32, double-buffered smem,
// register prefetch of next K-slab. K dimension may be split at 768 between
// (A1,B1) and (A2,B2). One __syncthreads per K-iteration.
// smem: As[2][128][36] | Bs[2][32][72]  = 55.3 KB dynamic
// ---------------------------------------------------------------------------
#define GEMM_SMEM_WORDS (2*(BM*36 + BKT*72))
#define GEMM_SMEM_BYTES (GEMM_SMEM_WORDS*4)

__device__ __forceinline__ void gemm_loadAB(
    const float* __restrict__ A1, const float* __restrict__ B1,
    const float* __restrict__ A2, const float* __restrict__ B2,
    int k0, int m0, int n0, float4 av[4], float4 bv[2])
{
    const float* A = (k0 < 768) ? A1 : A2;
    const float* B = (k0 < 768) ? B1 : B2;
    int kk = (k0 < 768) ? k0 : k0 - 768;
    int tid = threadIdx.x;
    #pragma unroll
    for (int p = 0; p < 4; p++) {
        int idx = tid + p * 256;
        int row = idx >> 3, c4 = (idx & 7) * 4;
        av[p] = *(const float4*)(A + (size_t)(m0 + row) * GK + kk + c4);
    }
    #pragma unroll
    for (int p = 0; p < 2; p++) {
        int idx = tid + p * 256;
        int row = idx >> 4, c4 = (idx & 15) * 4;
        bv[p] = *(const float4*)(B + (size_t)(kk + row) * GN + n0 + c4);
    }
}

__device__ __forceinline__ void gemm_core(
    uint32_t* sm,
    const float* __restrict__ A1, const float* __restrict__ B1,
    const float* __restrict__ A2, const float* __restrict__ B2,
    int Kd, int m0, int n0, float c[2][4][4])
{
    uint32_t (*As)[BM][36] = (uint32_t(*)[BM][36])sm;
    uint32_t (*Bs)[BKT][72] = (uint32_t(*)[BKT][72])(sm + 2*BM*36);

    int tid = threadIdx.x;
    int lane = tid & 31, wid = tid >> 5;
    int wm = wid & 3, wn = wid >> 2;
    int r = lane >> 2, cq = lane & 3;

    float4 av[4], bv[2];
    gemm_loadAB(A1, B1, A2, B2, 0, m0, n0, av, bv);
    int buf = 0;

    for (int k0 = 0; k0 < Kd; k0 += BKT) {
        #pragma unroll
        for (int p = 0; p < 4; p++) {
            int idx = tid + p * 256;
            int row = idx >> 3, c4 = (idx & 7) * 4;
            As[buf][row][c4 + 0] = f2tf32(av[p].x);
            As[buf][row][c4 + 1] = f2tf32(av[p].y);
            As[buf][row][c4 + 2] = f2tf32(av[p].z);
            As[buf][row][c4 + 3] = f2tf32(av[p].w);
        }
        #pragma unroll
        for (int p = 0; p < 2; p++) {
            int idx = tid + p * 256;
            int row = idx >> 4, c4 = (idx & 15) * 4;
            Bs[buf][row][c4 + 0] = f2tf32(bv[p].x);
            Bs[buf][row][c4 + 1] = f2tf32(bv[p].y);
            Bs[buf][row][c4 + 2] = f2tf32(bv[p].z);
            Bs[buf][row][c4 + 3] = f2tf32(bv[p].w);
        }
        __syncthreads();
        if (k0 + BKT < Kd)
            gemm_loadAB(A1, B1, A2, B2, k0 + BKT, m0, n0, av, bv);  // overlaps mma

        #pragma unroll
        for (int ks = 0; ks < 4; ks++) {
            int kb = ks * 8;
            uint32_t af[2][4];
            #pragma unroll
            for (int mt = 0; mt < 2; mt++) {
                int mr = wm * 32 + mt * 16 + r;
                af[mt][0] = As[buf][mr    ][kb + cq];
                af[mt][1] = As[buf][mr + 8][kb + cq];
                af[mt][2] = As[buf][mr    ][kb + cq + 4];
                af[mt][3] = As[buf][mr + 8][kb + cq + 4];
            }
            uint32_t bf[4][2];
            #pragma unroll
            for (int nt = 0; nt < 4; nt++) {
                int nc = wn * 32 + nt * 8 + r;
                bf[nt][0] = Bs[buf][kb + cq    ][nc];
                bf[nt][1] = Bs[buf][kb + cq + 4][nc];
            }
            #pragma unroll
            for (int mt = 0; mt < 2; mt++)
                #pragma unroll
                for (int nt = 0; nt < 4; nt++)
                    mma_tf32(c[mt][nt], af[mt], bf[nt]);
        }
        buf ^= 1;
    }
}

// ---------------------------------------------------------------------------
// Fused projection GEMMs: z in {0,1,2}: bf16 q/k/v scatter BHTK; z=3: f32 relu qg.
// ---------------------------------------------------------------------------
__global__ __launch_bounds__(256) void proj_tc(
    const float* __restrict__ Xn,
    const float* __restrict__ Wq, const float* __restrict__ Wk,
    const float* __restrict__ Wv, const float* __restrict__ Wgq)
{
    extern __shared__ uint32_t sm[];
    int z = blockIdx.z;
    const float* B = (z == 0) ? Wq : (z == 1) ? Wk : (z == 2) ? Wv : Wgq;

    int m0 = blockIdx.y * BM, n0 = blockIdx.x * BN;
    float c[2][4][4] = {};
    gemm_core(sm, Xn, B, Xn, B, GK, m0, n0, c);

    int lane = threadIdx.x & 31, wid = threadIdx.x >> 5;
    int wm = wid & 3, wn = wid >> 2;
    int r = lane >> 2, cq = lane & 3;
    __nv_bfloat16* Cb = (z == 0) ? g_qb : (z == 1) ? g_kb : g_vb;

    #pragma unroll
    for (int mt = 0; mt < 2; mt++) {
        #pragma unroll
        for (int nt = 0; nt < 4; nt++) {
            int col = n0 + wn * 32 + nt * 8 + 2 * cq;
            int h = col >> 6, kk = col & 63;
            #pragma unroll
            for (int i = 0; i < 2; i++) {
                int row = m0 + wm * 32 + mt * 16 + r + i * 8;
                int b = row >> 11, t = row & (TSEQ - 1);
                float v0 = c[mt][nt][i * 2 + 0];
                float v1 = c[mt][nt][i * 2 + 1];
                size_t idx = (((size_t)(b * NH + h) * TSEQ + t) << 6) + kk;
                if (z == 3) {
                    float2 o; o.x = fmaxf(v0, 0.f); o.y = fmaxf(v1, 0.f);
                    *(float2*)(g_qg + idx) = o;
                } else {
                    *((uint32_t*)Cb + (idx >> 1)) = pack_bf16(v0, v1);
                }
            }
        }
    }
}

// ---------------------------------------------------------------------------
// Fused output GEMM: out = x + [local | retr_scaled] @ [Wo ; Wro], K=1536.
// ---------------------------------------------------------------------------
__global__ __launch_bounds__(256) void gemm_out_tc(
    const float* __restrict__ A1, const float* __restrict__ A2,
    const float* __restrict__ B1, const float* __restrict__ B2,
    float* __restrict__ C, const float* __restrict__ addsrc)
{
    extern __shared__ uint32_t sm[];
    int m0 = blockIdx.y * BM, n0 = blockIdx.x * BN;
    float c[2][4][4] = {};
    gemm_core(sm, A1, B1, A2, B2, 1536, m0, n0, c);

    int lane = threadIdx.x & 31, wid = threadIdx.x >> 5;
    int wm = wid & 3, wn = wid >> 2;
    int r = lane >> 2, cq = lane & 3;
    #pragma unroll
    for (int mt = 0; mt < 2; mt++) {
        #pragma unroll
        for (int i = 0; i < 2; i++) {
            int row = m0 + wm * 32 + mt * 16 + r + i * 8;
            #pragma unroll
            for (int nt = 0; nt < 4; nt++) {
                int col = n0 + wn * 32 + nt * 8 + 2 * cq;
                size_t idx = (size_t)row * GN + col;
                float2 a2 = *(const float2*)(addsrc + idx);
                float2 o;
                o.x = c[mt][nt][i * 2 + 0] + a2.x;
                o.y = c[mt][nt][i * 2 + 1] + a2.y;
                *(float2*)(C + idx) = o;
            }
        }
    }
}

// ---------------------------------------------------------------------------
// bf16 tensor-core sliding-window flash attention (FA2-style, register P).
// Block: 128 queries x (b,h); 8 warps x 16 query rows. m16n8k16 bf16 mma.
// smem: Qs[128][36w] | Ks[64][36w] | Vs[64][36w]  (bf16 rows, stride 72B) = 36KB
// ---------------------------------------------------------------------------
#define ATTN_SMEM_WORDS (128*36 + 64*36 + 64*36)
#define ATTN_SMEM_BYTES (ATTN_SMEM_WORDS*4)

__global__ __launch_bounds__(256, 2) void attn_tc() {
    extern __shared__ uint32_t sm[];
    uint32_t (*Qs)[36] = (uint32_t(*)[36])(sm);
    uint32_t (*Ks)[36] = (uint32_t(*)[36])(sm + 128*36);
    uint32_t (*Vs)[36] = (uint32_t(*)[36])(sm + 128*36 + 64*36);
    const unsigned short* Vh = (const unsigned short*)(sm + 128*36 + 64*36);

    int qt = blockIdx.x;
    int bh = blockIdx.y;
    int q0 = qt * 128;
    int tid = threadIdx.x, lane = tid & 31, wid = tid >> 5;
    int r = lane >> 2, cq = lane & 3;
    size_t base = (size_t)bh * TSEQ * HD;
    int mr = wid * 16 + r;

    // stage Q (bf16, row-major, stride 36 words)
    {
        const __nv_bfloat16* Qg = g_qb + base + (size_t)q0 * HD;
        #pragma unroll
        for (int p = 0; p < 4; p++) {
            int idx = tid + p * 256;            // 1024 uint4
            int row = idx >> 3, seg = idx & 7;
            uint4 u = *(const uint4*)(Qg + (size_t)row * HD + seg * 8);
            *(uint4*)&Qs[row][seg * 4] = u;
        }
    }
    __syncthreads();

    float of[8][4] = {};
    float mz[2] = {NEG_BIG, NEG_BIG};
    float lv[2] = {0.f, 0.f};
    const float zscale = 0.125f * 1.44269504f;

    int kstart = q0 - WIN; if (kstart < 0) kstart = 0;
    for (int s0 = kstart; s0 <= q0 + 64; s0 += 64) {
        __syncthreads();
        #pragma unroll
        for (int p = 0; p < 2; p++) {           // K tile: 512 uint4
            int idx = tid + p * 256;
            int key = idx >> 3, seg = idx & 7;
            uint4 u = *(const uint4*)(g_kb + base + (size_t)(s0 + key) * HD + seg * 8);
            *(uint4*)&Ks[key][seg * 4] = u;
        }
        #pragma unroll
        for (int p = 0; p < 2; p++) {           // V tile: 512 uint4 (row-major)
            int idx = tid + p * 256;
            int key = idx >> 3, seg = idx & 7;
            uint4 u = *(const uint4*)(g_vb + base + (size_t)(s0 + key) * HD + seg * 8);
            *(uint4*)&Vs[key][seg * 4] = u;
        }
        __syncthreads();

        // ---- S = Q @ K^T (bf16 m16n8k16) ----
        float sf[8][4] = {};
        #pragma unroll
        for (int ks = 0; ks < 4; ks++) {
            uint32_t a[4];
            a[0] = Qs[mr    ][ks * 8 + cq];
            a[1] = Qs[mr + 8][ks * 8 + cq];
            a[2] = Qs[mr    ][ks * 8 + cq + 4];
            a[3] = Qs[mr + 8][ks * 8 + cq + 4];
            #pragma unroll
            for (int nt = 0; nt < 8; nt++) {
                uint32_t b[2];
                b[0] = Ks[nt * 8 + r][ks * 8 + cq];
                b[1] = Ks[nt * 8 + r][ks * 8 + cq + 4];
                mma_bf16(sf[nt], a, b);
            }
        }

        // ---- scale to log2 domain (+ mask on boundary tiles) ----
        bool need_mask = (s0 >= q0) || (s0 + WIN < q0 + 128);
        if (need_mask) {
            int q_lo = q0 + wid * 16 + r;
            #pragma unroll
            for (int nt = 0; nt < 8; nt++) {
                #pragma unroll
                for (int j = 0; j < 4; j++) {
                    int key = s0 + nt * 8 + 2 * cq + (j & 1);
                    int q = q_lo + (j >> 1) * 8;
                    bool ok = (key <= q) && (key >= q - WIN);
                    sf[nt][j] = ok ? sf[nt][j] * zscale : NEG_BIG;
                }
            }
        } else {
            #pragma unroll
            for (int nt = 0; nt < 8; nt++)
                #pragma unroll
                for (int j = 0; j < 4; j++) sf[nt][j] *= zscale;
        }

        // ---- online softmax ----
        float mx0 = NEG_BIG, mx1 = NEG_BIG;
        #pragma unroll
        for (int nt = 0; nt < 8; nt++) {
            mx0 = fmaxf(mx0, fmaxf(sf[nt][0], sf[nt][1]));
            mx1 = fmaxf(mx1, fmaxf(sf[nt][2], sf[nt][3]));
        }
        mx0 = fmaxf(mx0, __shfl_xor_sync(0xffffffffu, mx0, 1));
        mx0 = fmaxf(mx0, __shfl_xor_sync(0xffffffffu, mx0, 2));
        mx1 = fmaxf(mx1, __shfl_xor_sync(0xffffffffu, mx1, 1));
        mx1 = fmaxf(mx1, __shfl_xor_sync(0xffffffffu, mx1, 2));
        float nm0 = fmaxf(mz[0], mx0);
        float nm1 = fmaxf(mz[1], mx1);
        float c0 = exp2_fast(mz[0] - nm0);
        float c1 = exp2_fast(mz[1] - nm1);

        float rs0 = 0.f, rs1 = 0.f;
        #pragma unroll
        for (int nt = 0; nt < 8; nt++) {
            sf[nt][0] = exp2_fast(sf[nt][0] - nm0);
            sf[nt][1] = exp2_fast(sf[nt][1] - nm0);
            sf[nt][2] = exp2_fast(sf[nt][2] - nm1);
            sf[nt][3] = exp2_fast(sf[nt][3] - nm1);
            rs0 += sf[nt][0] + sf[nt][1];
            rs1 += sf[nt][2] + sf[nt][3];
        }
        rs0 += __shfl_xor_sync(0xffffffffu, rs0, 1);
        rs0 += __shfl_xor_sync(0xffffffffu, rs0, 2);
        rs1 += __shfl_xor_sync(0xffffffffu, rs1, 1);
        rs1 += __shfl_xor_sync(0xffffffffu, rs1, 2);
        lv[0] = lv[0] * c0 + rs0;
        lv[1] = lv[1] * c1 + rs1;
        mz[0] = nm0; mz[1] = nm1;
        #pragma unroll
        for (int nt = 0; nt < 8; nt++) {
            of[nt][0] *= c0; of[nt][1] *= c0;
            of[nt][2] *= c1; of[nt][3] *= c1;
        }

        // ---- O += P @ V : P packed from registers (C-frag -> A-frag) ----
        #pragma unroll
        for (int ks = 0; ks < 4; ks++) {
            uint32_t a[4];
            a[0] = pack_bf16(sf[2*ks    ][0], sf[2*ks    ][1]);
            a[1] = pack_bf16(sf[2*ks    ][2], sf[2*ks    ][3]);
            a[2] = pack_bf16(sf[2*ks + 1][0], sf[2*ks + 1][1]);
            a[3] = pack_bf16(sf[2*ks + 1][2], sf[2*ks + 1][3]);
            int k0 = ks * 16 + 2 * cq;
            #pragma unroll
            for (int nt = 0; nt < 8; nt++) {
                int d = nt * 8 + r;
                uint32_t lo0 = Vh[(k0    ) * 72 + d];
                uint32_t hi0 = Vh[(k0 + 1) * 72 + d];
                uint32_t lo1 = Vh[(k0 + 8) * 72 + d];
                uint32_t hi1 = Vh[(k0 + 9) * 72 + d];
                uint32_t b[2];
                b[0] = lo0 | (hi0 << 16);
                b[1] = lo1 | (hi1 << 16);
                mma_bf16(of[nt], a, b);
            }
        }
    }

    // ---- normalize + write ----
    int b = bh / NH, h = bh % NH;
    float inv0 = 1.f / lv[0], inv1 = 1.f / lv[1];
    int qa = q0 + wid * 16 + r;
    #pragma unroll
    for (int nt = 0; nt < 8; nt++) {
        int col = h * HD + nt * 8 + 2 * cq;
        float2 o0; o0.x = of[nt][0] * inv0; o0.y = of[nt][1] * inv0;
        float2 o1; o1.x = of[nt][2] * inv1; o1.y = of[nt][3] * inv1;
        *(float2*)(g_local + ((size_t)(b * TSEQ + qa    )) * HKD + col) = o0;
        *(float2*)(g_local + ((size_t)(b * TSEQ + qa + 8)) * HKD + col) = o1;
    }
}

// ---------------------------------------------------------------------------
// GDN retrieval with fused gate scale: out = gate[row] * (qg @ state)
// ---------------------------------------------------------------------------
__global__ __launch_bounds__(128) void retr_k(const float* __restrict__ state) {
    int bid = blockIdx.x;
    int tt = bid & 15;
    int bh = bid >> 4;
    __shared__ float st[64][68];
    __shared__ float qs[128][65];

    const float* sp = state + (size_t)bh * HD * HD;
    for (int i = threadIdx.x; i < HD * HD; i += 128)
        st[i >> 6][i & 63] = sp[i];
    size_t qbase = (size_t)bh * TSEQ * HD + (size_t)tt * 128 * HD;
    for (int i = threadIdx.x; i < 128 * HD; i += 128)
        qs[i >> 6][i & 63] = g_qg[qbase + i];
    __syncthreads();

    int t = tt * 128 + threadIdx.x;
    float acc[64];
    #pragma unroll
    for (int v = 0; v < 64; v++) acc[v] = 0.f;
    for (int k = 0; k < 64; k++) {
        float qk = qs[threadIdx.x][k];
        #pragma unroll
        for (int cc = 0; cc < 16; cc++) {
            float4 s4 = *(const float4*)&st[k][cc * 4];
            acc[cc*4+0] += qk * s4.x; acc[cc*4+1] += qk * s4.y;
            acc[cc*4+2] += qk * s4.z; acc[cc*4+3] += qk * s4.w;
        }
    }
    int b = bh / NH, h = bh % NH;
    int row = b * TSEQ + t;
    float gv = g_gate[row];
    float* outp = g_retr + (size_t)row * HKD + h * HD;
    #pragma unroll
    for (int cc = 0; cc < 16; cc++) {
        float4 t4;
        t4.x = acc[cc*4+0] * gv; t4.y = acc[cc*4+1] * gv;
        t4.z = acc[cc*4+2] * gv; t4.w = acc[cc*4+3] * gv;
        *(float4*)(outp + cc * 4) = t4;
    }
}

// ---------------------------------------------------------------------------
// Gate
// ---------------------------------------------------------------------------
__global__ __launch_bounds__(256) void gate_k(const float* __restrict__ Wg,
                                              const float* __restrict__ bg) {
    int row = blockIdx.x;
    float acc[NH];
    #pragma unroll
    for (int h = 0; h < NH; h++) acc[h] = 0.f;
    for (int d = threadIdx.x; d < DIM; d += 256) {
        float xv = g_xn[(size_t)row * DIM + d];
        #pragma unroll
        for (int h = 0; h < NH; h++) acc[h] += xv * Wg[d * NH + h];
    }
    #pragma unroll
    for (int h = 0; h < NH; h++) {
        #pragma unroll
        for (int o = 16; o; o >>= 1) acc[h] += __shfl_xor_sync(0xffffffffu, acc[h], o);
    }
    __shared__ float red[8][NH];
    int wid = threadIdx.x >> 5, lane = threadIdx.x & 31;
    if (lane == 0) {
        #pragma unroll
        for (int h = 0; h < NH; h++) red[wid][h] = acc[h];
    }
    __syncthreads();
    if (threadIdx.x == 0) {
        float s = 0.f;
        #pragma unroll
        for (int h = 0; h < NH; h++) {
            float a = 0.f;
            #pragma unroll
            for (int w = 0; w < 8; w++) a += red[w][h];
            s += 1.f / (1.f + expf(-(a + bg[h])));
        }
        g_gate[row] = s * (1.f / (float)NH);
    }
}

// ---------------------------------------------------------------------------
// Launch
// ---------------------------------------------------------------------------
extern "C" void kernel_launch(void* const* d_in, const int* in_sizes, int n_in,
                              void* d_out, int out_size) {
    const float* x      = (const float*)d_in[0];
    const float* state  = (const float*)d_in[1];
    const float* Wq     = (const float*)d_in[2];
    const float* Wk     = (const float*)d_in[3];
    const float* Wv     = (const float*)d_in[4];
    const float* Wo     = (const float*)d_in[5];
    const float* Wgq    = (const float*)d_in[6];
    const float* Wro    = (const float*)d_in[7];
    const float* Wg     = (const float*)d_in[8];
    const float* bg     = (const float*)d_in[9];
    const float* norm_w = (const float*)d_in[10];
    float* out = (float*)d_out;

    float *p_xn, *p_local, *p_retr;
    cudaGetSymbolAddress((void**)&p_xn,    g_xn);
    cudaGetSymbolAddress((void**)&p_local, g_local);
    cudaGetSymbolAddress((void**)&p_retr,  g_retr);

    cudaFuncSetAttribute(proj_tc, cudaFuncAttributeMaxDynamicSharedMemorySize,
                         GEMM_SMEM_BYTES);
    cudaFuncSetAttribute(gemm_out_tc, cudaFuncAttributeMaxDynamicSharedMemorySize,
                         GEMM_SMEM_BYTES);

    rmsnorm_k<<<ROWS, 256>>>(x, norm_w);

    proj_tc<<<dim3(GN / BN, ROWS / BM, 4), 256, GEMM_SMEM_BYTES>>>(
        p_xn, Wq, Wk, Wv, Wgq);

    gate_k<<<ROWS, 256>>>(Wg, bg);
    retr_k<<<BSZ * NH * (TSEQ / 128), 128>>>(state);

    attn_tc<<<dim3(TSEQ / 128, BSZ * NH), 256, ATTN_SMEM_BYTES>>>();

    gemm_out_tc<<<dim3(GN / BN, ROWS / BM), 256, GEMM_SMEM_BYTES>>>(
        p_local, p_retr, Wo, Wro, out, x);
}

// round 6
// speedup vs baseline: 5.7676x; 1.5276x over previous
#include <cuda_runtime.h>
#include <cuda_bf16.h>
#include <cuda_fp16.h>
#include <math.h>
#include <stdint.h>

// Problem constants
#define BSZ  2
#define TSEQ 2048
#define DIM  768
#define NH   12
#define HD   64
#define WIN  1024
#define ROWS (BSZ*TSEQ)  // 4096
#define HKD  (NH*HD)     // 768
#define REPS 1e-6f
#define NEG_BIG (-1e30f)

#define BM   128
#define BN   64
#define BKH  64          // K-step in halves

// ---------------------------------------------------------------------------
// Scratch
// ---------------------------------------------------------------------------
__device__ __half         g_xnh[ROWS*DIM];          // rmsnorm(x) fp16
__device__ __nv_bfloat16  g_qb[BSZ*NH*TSEQ*HD];     // bf16 (B,H,T,K)
__device__ __nv_bfloat16  g_kb[BSZ*NH*TSEQ*HD];
__device__ __nv_bfloat16  g_vb[BSZ*NH*TSEQ*HD];
__device__ __half         g_qgg[ROWS*HKD];          // gate * relu(xn@Wgq), row-major fp16
__device__ __half         g_localh[ROWS*HKD];       // attention out fp16 (B,T,HK)
__device__ __half         g_wt[5*DIM*DIM];          // Wq,Wk,Wv,Wgq,Wo transposed fp16 [n][k]
__device__ __half         g_mt[BSZ*DIM*DIM];        // M_b^T fp16 [d][hk]
__device__ float          g_gate[ROWS];

// ---------------------------------------------------------------------------
// helpers
// ---------------------------------------------------------------------------
__device__ __forceinline__ uint32_t pack_bf16(float lo, float hi) {
    uint32_t d;
    asm("cvt.rn.bf16x2.f32 %0, %1, %2;" : "=r"(d) : "f"(hi), "f"(lo));
    return d;
}
__device__ __forceinline__ uint32_t pack_f16(float lo, float hi) {
    uint32_t d;
    asm("cvt.rn.f16x2.f32 %0, %1, %2;" : "=r"(d) : "f"(hi), "f"(lo));
    return d;
}
__device__ __forceinline__ void mma_bf16(float c[4], const uint32_t a[4], const uint32_t b[2]) {
    asm volatile(
        "mma.sync.aligned.m16n8k16.row.col.f32.bf16.bf16.f32 "
        "{%0,%1,%2,%3}, {%4,%5,%6,%7}, {%8,%9}, {%0,%1,%2,%3};\n"
        : "+f"(c[0]), "+f"(c[1]), "+f"(c[2]), "+f"(c[3])
        : "r"(a[0]), "r"(a[1]), "r"(a[2]), "r"(a[3]), "r"(b[0]), "r"(b[1]));
}
__device__ __forceinline__ void mma_f16(float c[4], const uint32_t a[4], const uint32_t b[2]) {
    asm volatile(
        "mma.sync.aligned.m16n8k16.row.col.f32.f16.f16.f32 "
        "{%0,%1,%2,%3}, {%4,%5,%6,%7}, {%8,%9}, {%0,%1,%2,%3};\n"
        : "+f"(c[0]), "+f"(c[1]), "+f"(c[2]), "+f"(c[3])
        : "r"(a[0]), "r"(a[1]), "r"(a[2]), "r"(a[3]), "r"(b[0]), "r"(b[1]));
}
// fast 2^x for x <= 0 (clamped), FMA pipe only
__device__ __forceinline__ float exp2_fast(float x) {
    x = fmaxf(x, -120.f);
    float t  = x + 12582912.f;
    float fl = t - 12582912.f;
    float f  = x - fl;
    int   n  = __float_as_int(t) - 0x4B400000;
    float r  = 1.3333558e-3f;
    r = fmaf(r, f, 9.6181291e-3f);
    r = fmaf(r, f, 5.5504109e-2f);
    r = fmaf(r, f, 2.4022651e-1f);
    r = fmaf(r, f, 6.9314718e-1f);
    r = fmaf(r, f, 1.0f);
    return r * __int_as_float((n + 127) << 23);
}

// ---------------------------------------------------------------------------
// Weight transpose + fp16 convert: Wt[n][k] = W[k][n].  z selects matrix.
// ---------------------------------------------------------------------------
__global__ __launch_bounds__(256) void wt_k(
    const float* __restrict__ W0, const float* __restrict__ W1,
    const float* __restrict__ W2, const float* __restrict__ W3,
    const float* __restrict__ W4)
{
    int z = blockIdx.z;
    const float* W = (z == 0) ? W0 : (z == 1) ? W1 : (z == 2) ? W2 : (z == 3) ? W3 : W4;
    __shared__ float t[32][33];
    int tx = threadIdx.x, ty = threadIdx.y;   // 32 x 8
    #pragma unroll
    for (int i = 0; i < 4; i++)
        t[ty + i * 8][tx] = W[(size_t)(blockIdx.y * 32 + ty + i * 8) * DIM + blockIdx.x * 32 + tx];
    __syncthreads();
    __half* out = g_wt + (size_t)z * DIM * DIM;
    #pragma unroll
    for (int i = 0; i < 4; i++)
        out[(size_t)(blockIdx.x * 32 + ty + i * 8) * DIM + blockIdx.y * 32 + tx] =
            __float2half(t[tx][ty + i * 8]);
}

// ---------------------------------------------------------------------------
// Build Mt[b][d][hk] = sum_v state[b,h,k,v] * Wro[h*64+v][d]  (fp16)
// grid (12 d-tiles, NH, BSZ), 256 threads
// ---------------------------------------------------------------------------
__global__ __launch_bounds__(256) void mkm_k(
    const float* __restrict__ state, const float* __restrict__ Wro)
{
    int dt = blockIdx.x, h = blockIdx.y, b = blockIdx.z;
    __shared__ float st[64][68];   // st[v][k] = state[k][v]
    __shared__ float wr[64][65];   // wr[v][d]
    const float* sp = state + ((size_t)(b * NH + h)) * HD * HD;
    for (int i = threadIdx.x; i < HD * HD; i += 256) {
        int k = i >> 6, v = i & 63;
        st[v][k] = sp[i];
    }
    const float* wp = Wro + (size_t)(h * HD) * DIM + dt * 64;
    for (int i = threadIdx.x; i < HD * 64; i += 256) {
        int v = i >> 6, d = i & 63;
        wr[v][d] = wp[(size_t)v * DIM + d];
    }
    __syncthreads();

    int d = threadIdx.x & 63;
    int rep = threadIdx.x >> 6;     // k block: rep*16 .. +16
    float acc[16] = {};
    for (int v = 0; v < 64; v++) {
        float w = wr[v][d];
        #pragma unroll
        for (int c = 0; c < 4; c++) {
            float4 s4 = *(const float4*)&st[v][rep * 16 + c * 4];
            acc[c*4+0] += w * s4.x; acc[c*4+1] += w * s4.y;
            acc[c*4+2] += w * s4.z; acc[c*4+3] += w * s4.w;
        }
    }
    __half* out = g_mt + ((size_t)b * DIM + dt * 64 + d) * DIM + h * HD + rep * 16;
    #pragma unroll
    for (int c = 0; c < 8; c++)
        *((uint32_t*)out + c) = pack_f16(acc[2*c], acc[2*c+1]);
}

// ---------------------------------------------------------------------------
// RMSNorm + gate (fused): writes xn fp16 and g_gate.
// ---------------------------------------------------------------------------
__global__ __launch_bounds__(256) void rmsnorm_k(
    const float* __restrict__ x, const float* __restrict__ nw,
    const float* __restrict__ Wg, const float* __restrict__ bg)
{
    int row = blockIdx.x;
    const float* xr = x + (size_t)row * DIM;
    float ss = 0.f;
    for (int d = threadIdx.x; d < DIM; d += 256) { float v = xr[d]; ss += v * v; }
    #pragma unroll
    for (int o = 16; o; o >>= 1) ss += __shfl_xor_sync(0xffffffffu, ss, o);
    __shared__ float red[8];
    __shared__ float s_rinv;
    int wid = threadIdx.x >> 5, lane = threadIdx.x & 31;
    if (lane == 0) red[wid] = ss;
    __syncthreads();
    if (threadIdx.x == 0) {
        float t = 0.f;
        #pragma unroll
        for (int i = 0; i < 8; i++) t += red[i];
        s_rinv = rsqrtf(t / (float)DIM + REPS);
    }
    __syncthreads();
    float r = s_rinv;
    float acc[NH];
    #pragma unroll
    for (int h = 0; h < NH; h++) acc[h] = 0.f;
    for (int d = threadIdx.x; d < DIM; d += 256) {
        float xv = xr[d] * r * nw[d];
        g_xnh[(size_t)row * DIM + d] = __float2half(xv);
        #pragma unroll
        for (int h = 0; h < NH; h++) acc[h] += xv * Wg[d * NH + h];
    }
    #pragma unroll
    for (int h = 0; h < NH; h++) {
        #pragma unroll
        for (int o = 16; o; o >>= 1) acc[h] += __shfl_xor_sync(0xffffffffu, acc[h], o);
    }
    __shared__ float red2[8][NH];
    if (lane == 0) {
        #pragma unroll
        for (int h = 0; h < NH; h++) red2[wid][h] = acc[h];
    }
    __syncthreads();
    if (threadIdx.x == 0) {
        float s = 0.f;
        #pragma unroll
        for (int h = 0; h < NH; h++) {
            float a = 0.f;
            #pragma unroll
            for (int w = 0; w < 8; w++) a += red2[w][h];
            s += 1.f / (1.f + expf(-(a + bg[h])));
        }
        g_gate[row] = s * (1.f / (float)NH);
    }
}

// ---------------------------------------------------------------------------
// fp16 tensor-core GEMM core: 128x64 tile, BK=64 halves, double-buffered.
// A fp16 row-major [m][k]; B fp16 TRANSPOSED [n][k]. K may split at 768.
// smem: As[2][128][36w] | Bs[2][64][36w]  (words = 2 halves) = 55.3 KB
// ---------------------------------------------------------------------------
#define GEMM_SMEM_WORDS (2*(BM*36 + BN*36))
#define GEMM_SMEM_BYTES (GEMM_SMEM_WORDS*4)

__device__ __forceinline__ void gload_f16(
    const __half* __restrict__ A1, const __half* __restrict__ B1,
    const __half* __restrict__ A2, const __half* __restrict__ B2,
    int k0, int m0, int n0, uint4 av[4], uint4 bv[2])
{
    const __half* A = (k0 < DIM) ? A1 : A2;
    const __half* B = (k0 < DIM) ? B1 : B2;
    int kk = (k0 < DIM) ? k0 : k0 - DIM;
    int tid = threadIdx.x;
    #pragma unroll
    for (int p = 0; p < 4; p++) {            // A: 128 rows x 8 uint4
        int idx = tid + p * 256;
        int row = idx >> 3, seg = idx & 7;
        av[p] = *(const uint4*)(A + (size_t)(m0 + row) * DIM + kk + seg * 8);
    }
    #pragma unroll
    for (int p = 0; p < 2; p++) {            // B: 64 rows x 8 uint4
        int idx = tid + p * 256;
        int row = idx >> 3, seg = idx & 7;
        bv[p] = *(const uint4*)(B + (size_t)(n0 + row) * DIM + kk + seg * 8);
    }
}

__device__ __forceinline__ void gemm_core_f16(
    uint32_t* sm,
    const __half* __restrict__ A1, const __half* __restrict__ B1,
    const __half* __restrict__ A2, const __half* __restrict__ B2,
    int Kd, int m0, int n0, float c[2][4][4])
{
    uint32_t (*As)[BM][36] = (uint32_t(*)[BM][36])sm;
    uint32_t (*Bs)[BN][36] = (uint32_t(*)[BN][36])(sm + 2*BM*36);

    int tid = threadIdx.x;
    int lane = tid & 31, wid = tid >> 5;
    int wm = wid & 3, wn = wid >> 2;
    int r = lane >> 2, cq = lane & 3;

    uint4 av[4], bv[2];
    gload_f16(A1, B1, A2, B2, 0, m0, n0, av, bv);
    int buf = 0;

    for (int k0 = 0; k0 < Kd; k0 += BKH) {
        #pragma unroll
        for (int p = 0; p < 4; p++) {
            int idx = tid + p * 256;
            int row = idx >> 3, seg = idx & 7;
            *(uint4*)&As[buf][row][seg * 4] = av[p];
        }
        #pragma unroll
        for (int p = 0; p < 2; p++) {
            int idx = tid + p * 256;
            int row = idx >> 3, seg = idx & 7;
            *(uint4*)&Bs[buf][row][seg * 4] = bv[p];
        }
        __syncthreads();
        if (k0 + BKH < Kd)
            gload_f16(A1, B1, A2, B2, k0 + BKH, m0, n0, av, bv);

        #pragma unroll
        for (int ks = 0; ks < 4; ks++) {
            uint32_t af[2][4];
            #pragma unroll
            for (int mt = 0; mt < 2; mt++) {
                int mr = wm * 32 + mt * 16 + r;
                af[mt][0] = As[buf][mr    ][ks * 8 + cq];
                af[mt][1] = As[buf][mr + 8][ks * 8 + cq];
                af[mt][2] = As[buf][mr    ][ks * 8 + cq + 4];
                af[mt][3] = As[buf][mr + 8][ks * 8 + cq + 4];
            }
            uint32_t bf[4][2];
            #pragma unroll
            for (int nt = 0; nt < 4; nt++) {
                int nc = wn * 32 + nt * 8 + r;
                bf[nt][0] = Bs[buf][nc][ks * 8 + cq];
                bf[nt][1] = Bs[buf][nc][ks * 8 + cq + 4];
            }
            #pragma unroll
            for (int mt = 0; mt < 2; mt++)
                #pragma unroll
                for (int nt = 0; nt < 4; nt++)
                    mma_f16(c[mt][nt], af[mt], bf[nt]);
        }
        buf ^= 1;
    }
}

// ---------------------------------------------------------------------------
// Projection GEMMs: z in {0,1,2}: bf16 q/k/v scatter BHTK; z=3: gated qg fp16.
// ---------------------------------------------------------------------------
__global__ __launch_bounds__(256) void proj_tc() {
    extern __shared__ uint32_t sm[];
    int z = blockIdx.z;
    const __half* Bt = g_wt + (size_t)z * DIM * DIM;

    int m0 = blockIdx.y * BM, n0 = blockIdx.x * BN;
    float c[2][4][4] = {};
    gemm_core_f16(sm, g_xnh, Bt, g_xnh, Bt, DIM, m0, n0, c);

    int lane = threadIdx.x & 31, wid = threadIdx.x >> 5;
    int wm = wid & 3, wn = wid >> 2;
    int r = lane >> 2, cq = lane & 3;
    __nv_bfloat16* Cb = (z == 0) ? g_qb : (z == 1) ? g_kb : g_vb;

    #pragma unroll
    for (int mt = 0; mt < 2; mt++) {
        #pragma unroll
        for (int i = 0; i < 2; i++) {
            int row = m0 + wm * 32 + mt * 16 + r + i * 8;
            float gv = (z == 3) ? g_gate[row] : 0.f;
            #pragma unroll
            for (int nt = 0; nt < 4; nt++) {
                int col = n0 + wn * 32 + nt * 8 + 2 * cq;
                float v0 = c[mt][nt][i * 2 + 0];
                float v1 = c[mt][nt][i * 2 + 1];
                if (z == 3) {
                    v0 = fmaxf(v0, 0.f) * gv;
                    v1 = fmaxf(v1, 0.f) * gv;
                    *(uint32_t*)(g_qgg + (size_t)row * HKD + col) = pack_f16(v0, v1);
                } else {
                    int h = col >> 6, kk = col & 63;
                    int b = row >> 11, t = row & (TSEQ - 1);
                    size_t idx = (((size_t)(b * NH + h) * TSEQ + t) << 6) + kk;
                    *((uint32_t*)Cb + (idx >> 1)) = pack_bf16(v0, v1);
                }
            }
        }
    }
}

// ---------------------------------------------------------------------------
// Final GEMM: out = x + [local | qgg] @ [Wo^T ; Mt_b], K=1536.
// ---------------------------------------------------------------------------
__global__ __launch_bounds__(256) void out_tc(float* __restrict__ C,
                                              const float* __restrict__ addsrc) {
    extern __shared__ uint32_t sm[];
    int m0 = blockIdx.y * BM, n0 = blockIdx.x * BN;
    int b = m0 >> 11;
    float c[2][4][4] = {};
    gemm_core_f16(sm, g_localh, g_wt + (size_t)4 * DIM * DIM,
                  g_qgg, g_mt + (size_t)b * DIM * DIM,
                  2 * DIM, m0, n0, c);

    int lane = threadIdx.x & 31, wid = threadIdx.x >> 5;
    int wm = wid & 3, wn = wid >> 2;
    int r = lane >> 2, cq = lane & 3;
    #pragma unroll
    for (int mt = 0; mt < 2; mt++) {
        #pragma unroll
        for (int i = 0; i < 2; i++) {
            int row = m0 + wm * 32 + mt * 16 + r + i * 8;
            #pragma unroll
            for (int nt = 0; nt < 4; nt++) {
                int col = n0 + wn * 32 + nt * 8 + 2 * cq;
                size_t idx = (size_t)row * DIM + col;
                float2 a2 = *(const float2*)(addsrc + idx);
                float2 o;
                o.x = c[mt][nt][i * 2 + 0] + a2.x;
                o.y = c[mt][nt][i * 2 + 1] + a2.y;
                *(float2*)(C + idx) = o;
            }
        }
    }
}

// ---------------------------------------------------------------------------
// bf16 tensor-core sliding-window flash attention (unchanged core),
// output packed to fp16 g_localh.
// ---------------------------------------------------------------------------
#define ATTN_SMEM_WORDS (128*36 + 64*36 + 64*36)
#define ATTN_SMEM_BYTES (ATTN_SMEM_WORDS*4)

__global__ __launch_bounds__(256, 2) void attn_tc() {
    extern __shared__ uint32_t sm[];
    uint32_t (*Qs)[36] = (uint32_t(*)[36])(sm);
    uint32_t (*Ks)[36] = (uint32_t(*)[36])(sm + 128*36);
    uint32_t (*Vs)[36] = (uint32_t(*)[36])(sm + 128*36 + 64*36);
    const unsigned short* Vh = (const unsigned short*)(sm + 128*36 + 64*36);

    int qt = blockIdx.x;
    int bh = blockIdx.y;
    int q0 = qt * 128;
    int tid = threadIdx.x, lane = tid & 31, wid = tid >> 5;
    int r = lane >> 2, cq = lane & 3;
    size_t base = (size_t)bh * TSEQ * HD;
    int mr = wid * 16 + r;

    {
        const __nv_bfloat16* Qg = g_qb + base + (size_t)q0 * HD;
        #pragma unroll
        for (int p = 0; p < 4; p++) {
            int idx = tid + p * 256;
            int row = idx >> 3, seg = idx & 7;
            uint4 u = *(const uint4*)(Qg + (size_t)row * HD + seg * 8);
            *(uint4*)&Qs[row][seg * 4] = u;
        }
    }
    __syncthreads();

    float of[8][4] = {};
    float mz[2] = {NEG_BIG, NEG_BIG};
    float lv[2] = {0.f, 0.f};
    const float zscale = 0.125f * 1.44269504f;

    int kstart = q0 - WIN; if (kstart < 0) kstart = 0;
    for (int s0 = kstart; s0 <= q0 + 64; s0 += 64) {
        __syncthreads();
        #pragma unroll
        for (int p = 0; p < 2; p++) {
            int idx = tid + p * 256;
            int key = idx >> 3, seg = idx & 7;
            uint4 u = *(const uint4*)(g_kb + base + (size_t)(s0 + key) * HD + seg * 8);
            *(uint4*)&Ks[key][seg * 4] = u;
        }
        #pragma unroll
        for (int p = 0; p < 2; p++) {
            int idx = tid + p * 256;
            int key = idx >> 3, seg = idx & 7;
            uint4 u = *(const uint4*)(g_vb + base + (size_t)(s0 + key) * HD + seg * 8);
            *(uint4*)&Vs[key][seg * 4] = u;
        }
        __syncthreads();

        float sf[8][4] = {};
        #pragma unroll
        for (int ks = 0; ks < 4; ks++) {
            uint32_t a[4];
            a[0] = Qs[mr    ][ks * 8 + cq];
            a[1] = Qs[mr + 8][ks * 8 + cq];
            a[2] = Qs[mr    ][ks * 8 + cq + 4];
            a[3] = Qs[mr + 8][ks * 8 + cq + 4];
            #pragma unroll
            for (int nt = 0; nt < 8; nt++) {
                uint32_t b[2];
                b[0] = Ks[nt * 8 + r][ks * 8 + cq];
                b[1] = Ks[nt * 8 + r][ks * 8 + cq + 4];
                mma_bf16(sf[nt], a, b);
            }
        }

        bool need_mask = (s0 >= q0) || (s0 + WIN < q0 + 128);
        if (need_mask) {
            int q_lo = q0 + wid * 16 + r;
            #pragma unroll
            for (int nt = 0; nt < 8; nt++) {
                #pragma unroll
                for (int j = 0; j < 4; j++) {
                    int key = s0 + nt * 8 + 2 * cq + (j & 1);
                    int q = q_lo + (j >> 1) * 8;
                    bool ok = (key <= q) && (key >= q - WIN);
                    sf[nt][j] = ok ? sf[nt][j] * zscale : NEG_BIG;
                }
            }
        } else {
            #pragma unroll
            for (int nt = 0; nt < 8; nt++)
                #pragma unroll
                for (int j = 0; j < 4; j++) sf[nt][j] *= zscale;
        }

        float mx0 = NEG_BIG, mx1 = NEG_BIG;
        #pragma unroll
        for (int nt = 0; nt < 8; nt++) {
            mx0 = fmaxf(mx0, fmaxf(sf[nt][0], sf[nt][1]));
            mx1 = fmaxf(mx1, fmaxf(sf[nt][2], sf[nt][3]));
        }
        mx0 = fmaxf(mx0, __shfl_xor_sync(0xffffffffu, mx0, 1));
        mx0 = fmaxf(mx0, __shfl_xor_sync(0xffffffffu, mx0, 2));
        mx1 = fmaxf(mx1, __shfl_xor_sync(0xffffffffu, mx1, 1));
        mx1 = fmaxf(mx1, __shfl_xor_sync(0xffffffffu, mx1, 2));
        float nm0 = fmaxf(mz[0], mx0);
        float nm1 = fmaxf(mz[1], mx1);
        float c0 = exp2_fast(mz[0] - nm0);
        float c1 = exp2_fast(mz[1] - nm1);

        float rs0 = 0.f, rs1 = 0.f;
        #pragma unroll
        for (int nt = 0; nt < 8; nt++) {
            sf[nt][0] = exp2_fast(sf[nt][0] - nm0);
            sf[nt][1] = exp2_fast(sf[nt][1] - nm0);
            sf[nt][2] = exp2_fast(sf[nt][2] - nm1);
            sf[nt][3] = exp2_fast(sf[nt][3] - nm1);
            rs0 += sf[nt][0] + sf[nt][1];
            rs1 += sf[nt][2] + sf[nt][3];
        }
        rs0 += __shfl_xor_sync(0xffffffffu, rs0, 1);
        rs0 += __shfl_xor_sync(0xffffffffu, rs0, 2);
        rs1 += __shfl_xor_sync(0xffffffffu, rs1, 1);
        rs1 += __shfl_xor_sync(0xffffffffu, rs1, 2);
        lv[0] = lv[0] * c0 + rs0;
        lv[1] = lv[1] * c1 + rs1;
        mz[0] = nm0; mz[1] = nm1;
        #pragma unroll
        for (int nt = 0; nt < 8; nt++) {
            of[nt][0] *= c0; of[nt][1] *= c0;
            of[nt][2] *= c1; of[nt][3] *= c1;
        }

        #pragma unroll
        for (int ks = 0; ks < 4; ks++) {
            uint32_t a[4];
            a[0] = pack_bf16(sf[2*ks    ][0], sf[2*ks    ][1]);
            a[1] = pack_bf16(sf[2*ks    ][2], sf[2*ks    ][3]);
            a[2] = pack_bf16(sf[2*ks + 1][0], sf[2*ks + 1][1]);
            a[3] = pack_bf16(sf[2*ks + 1][2], sf[2*ks + 1][3]);
            int k0 = ks * 16 + 2 * cq;
            #pragma unroll
            for (int nt = 0; nt < 8; nt++) {
                int d = nt * 8 + r;
                uint32_t lo0 = Vh[(k0    ) * 72 + d];
                uint32_t hi0 = Vh[(k0 + 1) * 72 + d];
                uint32_t lo1 = Vh[(k0 + 8) * 72 + d];
                uint32_t hi1 = Vh[(k0 + 9) * 72 + d];
                uint32_t b[2];
                b[0] = lo0 | (hi0 << 16);
                b[1] = lo1 | (hi1 << 16);
                mma_bf16(of[nt], a, b);
            }
        }
    }

    int b = bh / NH, h = bh % NH;
    float inv0 = 1.f / lv[0], inv1 = 1.f / lv[1];
    int qa = q0 + wid * 16 + r;
    #pragma unroll
    for (int nt = 0; nt < 8; nt++) {
        int col = h * HD + nt * 8 + 2 * cq;
        *(uint32_t*)(g_localh + ((size_t)(b * TSEQ + qa    )) * HKD + col) =
            pack_f16(of[nt][0] * inv0, of[nt][1] * inv0);
        *(uint32_t*)(g_localh + ((size_t)(b * TSEQ + qa + 8)) * HKD + col) =
            pack_f16(of[nt][2] * inv1, of[nt][3] * inv1);
    }
}

// ---------------------------------------------------------------------------
// Launch
// ---------------------------------------------------------------------------
extern "C" void kernel_launch(void* const* d_in, const int* in_sizes, int n_in,
                              void* d_out, int out_size) {
    const float* x      = (const float*)d_in[0];
    const float* state  = (const float*)d_in[1];
    const float* Wq     = (const float*)d_in[2];
    const float* Wk     = (const float*)d_in[3];
    const float* Wv     = (const float*)d_in[4];
    const float* Wo     = (const float*)d_in[5];
    const float* Wgq    = (const float*)d_in[6];
    const float* Wro    = (const float*)d_in[7];
    const float* Wg     = (const float*)d_in[8];
    const float* bg     = (const float*)d_in[9];
    const float* norm_w = (const float*)d_in[10];
    float* out = (float*)d_out;

    cudaFuncSetAttribute(proj_tc, cudaFuncAttributeMaxDynamicSharedMemorySize,
                         GEMM_SMEM_BYTES);
    cudaFuncSetAttribute(out_tc, cudaFuncAttributeMaxDynamicSharedMemorySize,
                         GEMM_SMEM_BYTES);

    wt_k<<<dim3(24, 24, 5), dim3(32, 8)>>>(Wq, Wk, Wv, Wgq, Wo);
    mkm_k<<<dim3(12, NH, BSZ), 256>>>(state, Wro);
    rmsnorm_k<<<ROWS, 256>>>(x, norm_w, Wg, bg);

    proj_tc<<<dim3(DIM / BN, ROWS / BM, 4), 256, GEMM_SMEM_BYTES>>>();

    attn_tc<<<dim3(TSEQ / 128, BSZ * NH), 256, ATTN_SMEM_BYTES>>>();

    out_tc<<<dim3(DIM / BN, ROWS / BM), 256, GEMM_SMEM_BYTES>>>(out, x);
}

// round 9
// speedup vs baseline: 6.1055x; 1.0586x over previous
#include <cuda_runtime.h>
#include <cuda_bf16.h>
#include <cuda_fp16.h>
#include <math.h>
#include <stdint.h>

// Problem constants
#define BSZ  2
#define TSEQ 2048
#define DIM  768
#define NH   12
#define HD   64
#define WIN  1024
#define ROWS (BSZ*TSEQ)  // 4096
#define HKD  (NH*HD)     // 768
#define REPS 1e-6f
#define NEG_BIG (-1e30f)

#define BM   128
#define BN   64
#define BKH  64          // K-step in halves

// ---------------------------------------------------------------------------
// Scratch
// ---------------------------------------------------------------------------
__device__ __half         g_xnh[ROWS*DIM];          // rmsnorm(x) fp16
__device__ __nv_bfloat16  g_qb[BSZ*NH*TSEQ*HD];     // bf16 (B,H,T,K)
__device__ __nv_bfloat16  g_kb[BSZ*NH*TSEQ*HD];
__device__ __nv_bfloat16  g_vb[BSZ*NH*TSEQ*HD];
__device__ __half         g_qgg[ROWS*HKD];          // gate * relu(xn@Wgq) fp16
__device__ __half         g_localh[ROWS*HKD];       // attention out fp16 (B,T,HK)
__device__ __half         g_wt[5*DIM*DIM];          // Wq,Wk,Wv,Wgq,Wo transposed fp16 [n][k]
__device__ __half         g_mt[BSZ*DIM*DIM];        // M_b^T fp16 [d][hk]
__device__ float          g_gate[ROWS];

// ---------------------------------------------------------------------------
// helpers
// ---------------------------------------------------------------------------
__device__ __forceinline__ uint32_t pack_bf16(float lo, float hi) {
    uint32_t d;
    asm("cvt.rn.bf16x2.f32 %0, %1, %2;" : "=r"(d) : "f"(hi), "f"(lo));
    return d;
}
__device__ __forceinline__ uint32_t pack_f16(float lo, float hi) {
    uint32_t d;
    asm("cvt.rn.f16x2.f32 %0, %1, %2;" : "=r"(d) : "f"(hi), "f"(lo));
    return d;
}
__device__ __forceinline__ void mma_bf16(float c[4], const uint32_t a[4], const uint32_t b[2]) {
    asm volatile(
        "mma.sync.aligned.m16n8k16.row.col.f32.bf16.bf16.f32 "
        "{%0,%1,%2,%3}, {%4,%5,%6,%7}, {%8,%9}, {%0,%1,%2,%3};\n"
        : "+f"(c[0]), "+f"(c[1]), "+f"(c[2]), "+f"(c[3])
        : "r"(a[0]), "r"(a[1]), "r"(a[2]), "r"(a[3]), "r"(b[0]), "r"(b[1]));
}
__device__ __forceinline__ void mma_f16(float c[4], const uint32_t a[4], const uint32_t b[2]) {
    asm volatile(
        "mma.sync.aligned.m16n8k16.row.col.f32.f16.f16.f32 "
        "{%0,%1,%2,%3}, {%4,%5,%6,%7}, {%8,%9}, {%0,%1,%2,%3};\n"
        : "+f"(c[0]), "+f"(c[1]), "+f"(c[2]), "+f"(c[3])
        : "r"(a[0]), "r"(a[1]), "r"(a[2]), "r"(a[3]), "r"(b[0]), "r"(b[1]));
}
// ldmatrix x4: four 8x8 b16 fragments, one instruction
__device__ __forceinline__ void ldsm_x4(uint32_t* r, const void* p) {
    uint32_t a = (uint32_t)__cvta_generic_to_shared(p);
    asm volatile("ldmatrix.sync.aligned.m8n8.x4.shared.b16 {%0,%1,%2,%3}, [%4];"
        : "=r"(r[0]), "=r"(r[1]), "=r"(r[2]), "=r"(r[3]) : "r"(a));
}
__device__ __forceinline__ void ldsm_x4t(uint32_t* r, const void* p) {
    uint32_t a = (uint32_t)__cvta_generic_to_shared(p);
    asm volatile("ldmatrix.sync.aligned.m8n8.x4.trans.shared.b16 {%0,%1,%2,%3}, [%4];"
        : "=r"(r[0]), "=r"(r[1]), "=r"(r[2]), "=r"(r[3]) : "r"(a));
}
// fast 2^x for x <= 0 (clamped), FMA pipe only
__device__ __forceinline__ float exp2_fast(float x) {
    x = fmaxf(x, -120.f);
    float t  = x + 12582912.f;
    float fl = t - 12582912.f;
    float f  = x - fl;
    int   n  = __float_as_int(t) - 0x4B400000;
    float r  = 1.3333558e-3f;
    r = fmaf(r, f, 9.6181291e-3f);
    r = fmaf(r, f, 5.5504109e-2f);
    r = fmaf(r, f, 2.4022651e-1f);
    r = fmaf(r, f, 6.9314718e-1f);
    r = fmaf(r, f, 1.0f);
    return r * __int_as_float((n + 127) << 23);
}

// ---------------------------------------------------------------------------
// Weight transpose + fp16 convert: Wt[n][k] = W[k][n].  z selects matrix.
// ---------------------------------------------------------------------------
__global__ __launch_bounds__(256) void wt_k(
    const float* __restrict__ W0, const float* __restrict__ W1,
    const float* __restrict__ W2, const float* __restrict__ W3,
    const float* __restrict__ W4)
{
    int z = blockIdx.z;
    const float* W = (z == 0) ? W0 : (z == 1) ? W1 : (z == 2) ? W2 : (z == 3) ? W3 : W4;
    __shared__ float t[32][33];
    int tx = threadIdx.x, ty = threadIdx.y;   // 32 x 8
    #pragma unroll
    for (int i = 0; i < 4; i++)
        t[ty + i * 8][tx] = W[(size_t)(blockIdx.y * 32 + ty + i * 8) * DIM + blockIdx.x * 32 + tx];
    __syncthreads();
    __half* out = g_wt + (size_t)z * DIM * DIM;
    #pragma unroll
    for (int i = 0; i < 4; i++)
        out[(size_t)(blockIdx.x * 32 + ty + i * 8) * DIM + blockIdx.y * 32 + tx] =
            __float2half(t[tx][ty + i * 8]);
}

// ---------------------------------------------------------------------------
// Build Mt[b][d][hk] = sum_v state[b,h,k,v] * Wro[h*64+v][d]  (fp16)
// ---------------------------------------------------------------------------
__global__ __launch_bounds__(256) void mkm_k(
    const float* __restrict__ state, const float* __restrict__ Wro)
{
    int dt = blockIdx.x, h = blockIdx.y, b = blockIdx.z;
    __shared__ float st[64][68];
    __shared__ float wr[64][65];
    const float* sp = state + ((size_t)(b * NH + h)) * HD * HD;
    for (int i = threadIdx.x; i < HD * HD; i += 256) {
        int k = i >> 6, v = i & 63;
        st[v][k] = sp[i];
    }
    const float* wp = Wro + (size_t)(h * HD) * DIM + dt * 64;
    for (int i = threadIdx.x; i < HD * 64; i += 256) {
        int v = i >> 6, d = i & 63;
        wr[v][d] = wp[(size_t)v * DIM + d];
    }
    __syncthreads();

    int d = threadIdx.x & 63;
    int rep = threadIdx.x >> 6;
    float acc[16] = {};
    for (int v = 0; v < 64; v++) {
        float w = wr[v][d];
        #pragma unroll
        for (int c = 0; c < 4; c++) {
            float4 s4 = *(const float4*)&st[v][rep * 16 + c * 4];
            acc[c*4+0] += w * s4.x; acc[c*4+1] += w * s4.y;
            acc[c*4+2] += w * s4.z; acc[c*4+3] += w * s4.w;
        }
    }
    __half* out = g_mt + ((size_t)b * DIM + dt * 64 + d) * DIM + h * HD + rep * 16;
    #pragma unroll
    for (int c = 0; c < 8; c++)
        *((uint32_t*)out + c) = pack_f16(acc[2*c], acc[2*c+1]);
}

// ---------------------------------------------------------------------------
// RMSNorm + gate (fused): writes xn fp16 and g_gate.
// ---------------------------------------------------------------------------
__global__ __launch_bounds__(256) void rmsnorm_k(
    const float* __restrict__ x, const float* __restrict__ nw,
    const float* __restrict__ Wg, const float* __restrict__ bg)
{
    int row = blockIdx.x;
    const float* xr = x + (size_t)row * DIM;
    float ss = 0.f;
    for (int d = threadIdx.x; d < DIM; d += 256) { float v = xr[d]; ss += v * v; }
    #pragma unroll
    for (int o = 16; o; o >>= 1) ss += __shfl_xor_sync(0xffffffffu, ss, o);
    __shared__ float red[8];
    __shared__ float s_rinv;
    int wid = threadIdx.x >> 5, lane = threadIdx.x & 31;
    if (lane == 0) red[wid] = ss;
    __syncthreads();
    if (threadIdx.x == 0) {
        float t = 0.f;
        #pragma unroll
        for (int i = 0; i < 8; i++) t += red[i];
        s_rinv = rsqrtf(t / (float)DIM + REPS);
    }
    __syncthreads();
    float r = s_rinv;
    float acc[NH];
    #pragma unroll
    for (int h = 0; h < NH; h++) acc[h] = 0.f;
    for (int d = threadIdx.x; d < DIM; d += 256) {
        float xv = xr[d] * r * nw[d];
        g_xnh[(size_t)row * DIM + d] = __float2half(xv);
        #pragma unroll
        for (int h = 0; h < NH; h++) acc[h] += xv * Wg[d * NH + h];
    }
    #pragma unroll
    for (int h = 0; h < NH; h++) {
        #pragma unroll
        for (int o = 16; o; o >>= 1) acc[h] += __shfl_xor_sync(0xffffffffu, acc[h], o);
    }
    __shared__ float red2[8][NH];
    if (lane == 0) {
        #pragma unroll
        for (int h = 0; h < NH; h++) red2[wid][h] = acc[h];
    }
    __syncthreads();
    if (threadIdx.x == 0) {
        float s = 0.f;
        #pragma unroll
        for (int h = 0; h < NH; h++) {
            float a = 0.f;
            #pragma unroll
            for (int w = 0; w < 8; w++) a += red2[w][h];
            s += 1.f / (1.f + expf(-(a + bg[h])));
        }
        g_gate[row] = s * (1.f / (float)NH);
    }
}

// ---------------------------------------------------------------------------
// fp16 tensor-core GEMM core: 128x64 tile, BK=64 halves, double-buffered,
// ldmatrix fragment loads. A fp16 [m][k]; B fp16 TRANSPOSED [n][k].
// smem: As[2][128][36w] | Bs[2][64][36w] = 55.3 KB
// ---------------------------------------------------------------------------
#define GEMM_SMEM_WORDS (2*(BM*36 + BN*36))
#define GEMM_SMEM_BYTES (GEMM_SMEM_WORDS*4)

__device__ __forceinline__ void gload_f16(
    const __half* __restrict__ A1, const __half* __restrict__ B1,
    const __half* __restrict__ A2, const __half* __restrict__ B2,
    int k0, int m0, int n0, uint4 av[4], uint4 bv[2])
{
    const __half* A = (k0 < DIM) ? A1 : A2;
    const __half* B = (k0 < DIM) ? B1 : B2;
    int kk = (k0 < DIM) ? k0 : k0 - DIM;
    int tid = threadIdx.x;
    #pragma unroll
    for (int p = 0; p < 4; p++) {            // A: 128 rows x 8 uint4
        int idx = tid + p * 256;
        int row = idx >> 3, seg = idx & 7;
        av[p] = *(const uint4*)(A + (size_t)(m0 + row) * DIM + kk + seg * 8);
    }
    #pragma unroll
    for (int p = 0; p < 2; p++) {            // B: 64 rows x 8 uint4
        int idx = tid + p * 256;
        int row = idx >> 3, seg = idx & 7;
        bv[p] = *(const uint4*)(B + (size_t)(n0 + row) * DIM + kk + seg * 8);
    }
}

__device__ __forceinline__ void gemm_core_f16(
    uint32_t* sm,
    const __half* __restrict__ A1, const __half* __restrict__ B1,
    const __half* __restrict__ A2, const __half* __restrict__ B2,
    int Kd, int m0, int n0, float c[2][4][4])
{
    uint32_t (*As)[BM][36] = (uint32_t(*)[BM][36])sm;
    uint32_t (*Bs)[BN][36] = (uint32_t(*)[BN][36])(sm + 2*BM*36);

    int tid = threadIdx.x;
    int lane = tid & 31, wid = tid >> 5;
    int wm = wid & 3, wn = wid >> 2;

    // ldmatrix lane-address components
    int a_row = (lane & 7) + ((lane >> 3) & 1) * 8;   // + mt*16 + wm*32
    int a_col = (lane >> 4) * 4;                      // + ks*8
    int b_row = (lane & 7) + (lane >> 4) * 8;         // + np*16 + wn*32
    int b_col = ((lane >> 3) & 1) * 4;                // + ks*8

    uint4 av[4], bv[2];
    gload_f16(A1, B1, A2, B2, 0, m0, n0, av, bv);
    int buf = 0;

    for (int k0 = 0; k0 < Kd; k0 += BKH) {
        #pragma unroll
        for (int p = 0; p < 4; p++) {
            int idx = tid + p * 256;
            int row = idx >> 3, seg = idx & 7;
            *(uint4*)&As[buf][row][seg * 4] = av[p];
        }
        #pragma unroll
        for (int p = 0; p < 2; p++) {
            int idx = tid + p * 256;
            int row = idx >> 3, seg = idx & 7;
            *(uint4*)&Bs[buf][row][seg * 4] = bv[p];
        }
        __syncthreads();
        if (k0 + BKH < Kd)
            gload_f16(A1, B1, A2, B2, k0 + BKH, m0, n0, av, bv);

        #pragma unroll
        for (int ks = 0; ks < 4; ks++) {
            uint32_t af[2][4];
            #pragma unroll
            for (int mt = 0; mt < 2; mt++)
                ldsm_x4(af[mt], &As[buf][wm * 32 + mt * 16 + a_row][ks * 8 + a_col]);
            uint32_t bf4[2][4];
            #pragma unroll
            for (int np = 0; np < 2; np++)
                ldsm_x4(bf4[np], &Bs[buf][wn * 32 + np * 16 + b_row][ks * 8 + b_col]);
            #pragma unroll
            for (int mt = 0; mt < 2; mt++)
                #pragma unroll
                for (int np = 0; np < 2; np++) {
                    mma_f16(c[mt][2 * np    ], af[mt], &bf4[np][0]);
                    mma_f16(c[mt][2 * np + 1], af[mt], &bf4[np][2]);
                }
        }
        buf ^= 1;
    }
}

// ---------------------------------------------------------------------------
// Projection GEMMs: z in {0,1,2}: bf16 q/k/v scatter BHTK; z=3: gated qg fp16.
// ---------------------------------------------------------------------------
__global__ __launch_bounds__(256) void proj_tc() {
    extern __shared__ uint32_t sm[];
    int z = blockIdx.z;
    const __half* Bt = g_wt + (size_t)z * DIM * DIM;

    int m0 = blockIdx.y * BM, n0 = blockIdx.x * BN;
    float c[2][4][4] = {};
    gemm_core_f16(sm, g_xnh, Bt, g_xnh, Bt, DIM, m0, n0, c);

    int lane = threadIdx.x & 31, wid = threadIdx.x >> 5;
    int wm = wid & 3, wn = wid >> 2;
    int r = lane >> 2, cq = lane & 3;
    __nv_bfloat16* Cb = (z == 0) ? g_qb : (z == 1) ? g_kb : g_vb;

    #pragma unroll
    for (int mt = 0; mt < 2; mt++) {
        #pragma unroll
        for (int i = 0; i < 2; i++) {
            int row = m0 + wm * 32 + mt * 16 + r + i * 8;
            float gv = (z == 3) ? g_gate[row] : 0.f;
            #pragma unroll
            for (int nt = 0; nt < 4; nt++) {
                int col = n0 + wn * 32 + nt * 8 + 2 * cq;
                float v0 = c[mt][nt][i * 2 + 0];
                float v1 = c[mt][nt][i * 2 + 1];
                if (z == 3) {
                    v0 = fmaxf(v0, 0.f) * gv;
                    v1 = fmaxf(v1, 0.f) * gv;
                    *(uint32_t*)(g_qgg + (size_t)row * HKD + col) = pack_f16(v0, v1);
                } else {
                    int h = col >> 6, kk = col & 63;
                    int b = row >> 11, t = row & (TSEQ - 1);
                    size_t idx = (((size_t)(b * NH + h) * TSEQ + t) << 6) + kk;
                    *((uint32_t*)Cb + (idx >> 1)) = pack_bf16(v0, v1);
                }
            }
        }
    }
}

// ---------------------------------------------------------------------------
// Final GEMM: out = x + [local | qgg] @ [Wo^T ; Mt_b], K=1536.
// ---------------------------------------------------------------------------
__global__ __launch_bounds__(256) void out_tc(float* __restrict__ C,
                                              const float* __restrict__ addsrc) {
    extern __shared__ uint32_t sm[];
    int m0 = blockIdx.y * BM, n0 = blockIdx.x * BN;
    int b = m0 >> 11;
    float c[2][4][4] = {};
    gemm_core_f16(sm, g_localh, g_wt + (size_t)4 * DIM * DIM,
                  g_qgg, g_mt + (size_t)b * DIM * DIM,
                  2 * DIM, m0, n0, c);

    int lane = threadIdx.x & 31, wid = threadIdx.x >> 5;
    int wm = wid & 3, wn = wid >> 2;
    int r = lane >> 2, cq = lane & 3;
    #pragma unroll
    for (int mt = 0; mt < 2; mt++) {
        #pragma unroll
        for (int i = 0; i < 2; i++) {
            int row = m0 + wm * 32 + mt * 16 + r + i * 8;
            #pragma unroll
            for (int nt = 0; nt < 4; nt++) {
                int col = n0 + wn * 32 + nt * 8 + 2 * cq;
                size_t idx = (size_t)row * DIM + col;
                float2 a2 = *(const float2*)(addsrc + idx);
                float2 o;
                o.x = c[mt][nt][i * 2 + 0] + a2.x;
                o.y = c[mt][nt][i * 2 + 1] + a2.y;
                *(float2*)(C + idx) = o;
            }
        }
    }
}

// ---------------------------------------------------------------------------
// bf16 tensor-core sliding-window flash attention, ldmatrix fragment loads,
// Q fragments register-resident, register P (FA2), V via ldmatrix.trans.
// smem: Qs[128][36w] | Ks[64][36w] | Vs[64][36w] = 36KB
// ---------------------------------------------------------------------------
#define ATTN_SMEM_WORDS (128*36 + 64*36 + 64*36)
#define ATTN_SMEM_BYTES (ATTN_SMEM_WORDS*4)

__global__ __launch_bounds__(256, 2) void attn_tc() {
    extern __shared__ uint32_t sm[];
    uint32_t (*Qs)[36] = (uint32_t(*)[36])(sm);
    uint32_t (*Ks)[36] = (uint32_t(*)[36])(sm + 128*36);
    uint32_t (*Vs)[36] = (uint32_t(*)[36])(sm + 128*36 + 64*36);

    int qt = blockIdx.x;
    int bh = blockIdx.y;
    int q0 = qt * 128;
    int tid = threadIdx.x, lane = tid & 31, wid = tid >> 5;
    int r = lane >> 2, cq = lane & 3;
    size_t base = (size_t)bh * TSEQ * HD;

    // ldmatrix lane-address components
    int a_row = (lane & 7) + ((lane >> 3) & 1) * 8;   // A-frag row (+tile base)
    int a_col = (lane >> 4) * 4;                      // A-frag word (+ks*8)
    int b_row = (lane & 7) + (lane >> 4) * 8;         // B-frag row (K tiles)
    int b_col = ((lane >> 3) & 1) * 4;                // B-frag word (+ks*8)
    int v_row = (lane & 7) + ((lane >> 3) & 1) * 8;   // V trans row (+ks*16)
    int v_col = (lane >> 4) * 4;                      // V trans word (+np*8)

    // stage Q, then hoist Q fragments to registers (read once)
    {
        const __nv_bfloat16* Qg = g_qb + base + (size_t)q0 * HD;
        #pragma unroll
        for (int p = 0; p < 4; p++) {
            int idx = tid + p * 256;
            int row = idx >> 3, seg = idx & 7;
            uint4 u = *(const uint4*)(Qg + (size_t)row * HD + seg * 8);
            *(uint4*)&Qs[row][seg * 4] = u;
        }
    }
    __syncthreads();
    uint32_t qf[4][4];
    #pragma unroll
    for (int ks = 0; ks < 4; ks++)
        ldsm_x4(qf[ks], &Qs[wid * 16 + a_row][ks * 8 + a_col]);

    float of[8][4] = {};
    float mz[2] = {NEG_BIG, NEG_BIG};
    float lv[2] = {0.f, 0.f};
    const float zscale = 0.125f * 1.44269504f;

    int kstart = q0 - WIN; if (kstart < 0) kstart = 0;
    for (int s0 = kstart; s0 <= q0 + 64; s0 += 64) {
        __syncthreads();
        #pragma unroll
        for (int p = 0; p < 2; p++) {           // K tile
            int idx = tid + p * 256;
            int key = idx >> 3, seg = idx & 7;
            uint4 u = *(const uint4*)(g_kb + base + (size_t)(s0 + key) * HD + seg * 8);
            *(uint4*)&Ks[key][seg * 4] = u;
        }
        #pragma unroll
        for (int p = 0; p < 2; p++) {           // V tile
            int idx = tid + p * 256;
            int key = idx >> 3, seg = idx & 7;
            uint4 u = *(const uint4*)(g_vb + base + (size_t)(s0 + key) * HD + seg * 8);
            *(uint4*)&Vs[key][seg * 4] = u;
        }
        __syncthreads();

        // ---- S = Q @ K^T ----
        float sf[8][4] = {};
        #pragma unroll
        for (int ks = 0; ks < 4; ks++) {
            #pragma unroll
            for (int np = 0; np < 4; np++) {
                uint32_t b4[4];
                ldsm_x4(b4, &Ks[np * 16 + b_row][ks * 8 + b_col]);
                mma_bf16(sf[2 * np    ], qf[ks], &b4[0]);
                mma_bf16(sf[2 * np + 1], qf[ks], &b4[2]);
            }
        }

        // ---- scale to log2 domain (+ mask on boundary tiles) ----
        bool need_mask = (s0 >= q0) || (s0 + WIN < q0 + 128);
        if (need_mask) {
            int q_lo = q0 + wid * 16 + r;
            #pragma unroll
            for (int nt = 0; nt < 8; nt++) {
                #pragma unroll
                for (int j = 0; j < 4; j++) {
                    int key = s0 + nt * 8 + 2 * cq + (j & 1);
                    int q = q_lo + (j >> 1) * 8;
                    bool ok = (key <= q) && (key >= q - WIN);
                    sf[nt][j] = ok ? sf[nt][j] * zscale : NEG_BIG;
                }
            }
        } else {
            #pragma unroll
            for (int nt = 0; nt < 8; nt++)
                #pragma unroll
                for (int j = 0; j < 4; j++) sf[nt][j] *= zscale;
        }

        // ---- online softmax ----
        float mx0 = NEG_BIG, mx1 = NEG_BIG;
        #pragma unroll
        for (int nt = 0; nt < 8; nt++) {
            mx0 = fmaxf(mx0, fmaxf(sf[nt][0], sf[nt][1]));
            mx1 = fmaxf(mx1, fmaxf(sf[nt][2], sf[nt][3]));
        }
        mx0 = fmaxf(mx0, __shfl_xor_sync(0xffffffffu, mx0, 1));
        mx0 = fmaxf(mx0, __shfl_xor_sync(0xffffffffu, mx0, 2));
        mx1 = fmaxf(mx1, __shfl_xor_sync(0xffffffffu, mx1, 1));
        mx1 = fmaxf(mx1, __shfl_xor_sync(0xffffffffu, mx1, 2));
        float nm0 = fmaxf(mz[0], mx0);
        float nm1 = fmaxf(mz[1], mx1);
        float c0 = exp2_fast(mz[0] - nm0);
        float c1 = exp2_fast(mz[1] - nm1);

        float rs0 = 0.f, rs1 = 0.f;
        #pragma unroll
        for (int nt = 0; nt < 8; nt++) {
            sf[nt][0] = exp2_fast(sf[nt][0] - nm0);
            sf[nt][1] = exp2_fast(sf[nt][1] - nm0);
            sf[nt][2] = exp2_fast(sf[nt][2] - nm1);
            sf[nt][3] = exp2_fast(sf[nt][3] - nm1);
            rs0 += sf[nt][0] + sf[nt][1];
            rs1 += sf[nt][2] + sf[nt][3];
        }
        rs0 += __shfl_xor_sync(0xffffffffu, rs0, 1);
        rs0 += __shfl_xor_sync(0xffffffffu, rs0, 2);
        rs1 += __shfl_xor_sync(0xffffffffu, rs1, 1);
        rs1 += __shfl_xor_sync(0xffffffffu, rs1, 2);
        lv[0] = lv[0] * c0 + rs0;
        lv[1] = lv[1] * c1 + rs1;
        mz[0] = nm0; mz[1] = nm1;
        #pragma unroll
        for (int nt = 0; nt < 8; nt++) {
            of[nt][0] *= c0; of[nt][1] *= c0;
            of[nt][2] *= c1; of[nt][3] *= c1;
        }

        // ---- O += P @ V : P packed from registers, V via ldmatrix.trans ----
        #pragma unroll
        for (int ks = 0; ks < 4; ks++) {
            uint32_t a[4];
            a[0] = pack_bf16(sf[2*ks    ][0], sf[2*ks    ][1]);
            a[1] = pack_bf16(sf[2*ks    ][2], sf[2*ks    ][3]);
            a[2] = pack_bf16(sf[2*ks + 1][0], sf[2*ks + 1][1]);
            a[3] = pack_bf16(sf[2*ks + 1][2], sf[2*ks + 1][3]);
            #pragma unroll
            for (int np = 0; np < 4; np++) {
                uint32_t b4[4];
                ldsm_x4t(b4, &Vs[ks * 16 + v_row][np * 8 + v_col]);
                mma_bf16(of[2 * np    ], a, &b4[0]);
                mma_bf16(of[2 * np + 1], a, &b4[2]);
            }
        }
    }

    // ---- normalize + write (fp16) ----
    int b = bh / NH, h = bh % NH;
    float inv0 = 1.f / lv[0], inv1 = 1.f / lv[1];
    int qa = q0 + wid * 16 + r;
    #pragma unroll
    for (int nt = 0; nt < 8; nt++) {
        int col = h * HD + nt * 8 + 2 * cq;
        *(uint32_t*)(g_localh + ((size_t)(b * TSEQ + qa    )) * HKD + col) =
            pack_f16(of[nt][0] * inv0, of[nt][1] * inv0);
        *(uint32_t*)(g_localh + ((size_t)(b * TSEQ + qa + 8)) * HKD + col) =
            pack_f16(of[nt][2] * inv1, of[nt][3] * inv1);
    }
}

// ---------------------------------------------------------------------------
// Launch
// ---------------------------------------------------------------------------
extern "C" void kernel_launch(void* const* d_in, const int* in_sizes, int n_in,
                              void* d_out, int out_size) {
    const float* x      = (const float*)d_in[0];
    const float* state  = (const float*)d_in[1];
    const float* Wq     = (const float*)d_in[2];
    const float* Wk     = (const float*)d_in[3];
    const float* Wv     = (const float*)d_in[4];
    const float* Wo     = (const float*)d_in[5];
    const float* Wgq    = (const float*)d_in[6];
    const float* Wro    = (const float*)d_in[7];
    const float* Wg     = (const float*)d_in[8];
    const float* bg     = (const float*)d_in[9];
    const float* norm_w = (const float*)d_in[10];
    float* out = (float*)d_out;

    cudaFuncSetAttribute(proj_tc, cudaFuncAttributeMaxDynamicSharedMemorySize,
                         GEMM_SMEM_BYTES);
    cudaFuncSetAttribute(out_tc, cudaFuncAttributeMaxDynamicSharedMemorySize,
                         GEMM_SMEM_BYTES);

    wt_k<<<dim3(24, 24, 5), dim3(32, 8)>>>(Wq, Wk, Wv, Wgq, Wo);
    mkm_k<<<dim3(12, NH, BSZ), 256>>>(state, Wro);
    rmsnorm_k<<<ROWS, 256>>>(x, norm_w, Wg, bg);

    proj_tc<<<dim3(DIM / BN, ROWS / BM, 4), 256, GEMM_SMEM_BYTES>>>();

    attn_tc<<<dim3(TSEQ / 128, BSZ * NH), 256, ATTN_SMEM_BYTES>>>();

    out_tc<<<dim3(DIM / BN, ROWS / BM), 256, GEMM_SMEM_BYTES>>>(out, x);
}

// round 12
// speedup vs baseline: 6.2976x; 1.0315x over previous
#include <cuda_runtime.h>
#include <cuda_bf16.h>
#include <cuda_fp16.h>
#include <math.h>
#include <stdint.h>

// Problem constants
#define BSZ  2
#define TSEQ 2048
#define DIM  768
#define NH   12
#define HD   64
#define WIN  1024
#define ROWS (BSZ*TSEQ)  // 4096
#define HKD  (NH*HD)     // 768
#define REPS 1e-6f
#define NEG_BIG (-1e30f)

#define BM   128
#define BN   128         // widened output tile
#define BKH  64          // K-step in halves

// ---------------------------------------------------------------------------
// Scratch
// ---------------------------------------------------------------------------
__device__ __half         g_xnh[ROWS*DIM];          // rmsnorm(x) fp16
__device__ __nv_bfloat16  g_qb[BSZ*NH*TSEQ*HD];     // bf16 (B,H,T,K)
__device__ __nv_bfloat16  g_kb[BSZ*NH*TSEQ*HD];
__device__ __nv_bfloat16  g_vb[BSZ*NH*TSEQ*HD];
__device__ __half         g_qgg[ROWS*HKD];          // gate * relu(xn@Wgq) fp16
__device__ __half         g_localh[ROWS*HKD];       // attention out fp16 (B,T,HK)
__device__ __half         g_wt[5*DIM*DIM];          // Wq,Wk,Wv,Wgq,Wo transposed fp16 [n][k]
__device__ __half         g_mt[BSZ*DIM*DIM];        // M_b^T fp16 [d][hk]
__device__ float          g_gate[ROWS];

// ---------------------------------------------------------------------------
// helpers
// ---------------------------------------------------------------------------
__device__ __forceinline__ uint32_t pack_bf16(float lo, float hi) {
    uint32_t d;
    asm("cvt.rn.bf16x2.f32 %0, %1, %2;" : "=r"(d) : "f"(hi), "f"(lo));
    return d;
}
__device__ __forceinline__ uint32_t pack_f16(float lo, float hi) {
    uint32_t d;
    asm("cvt.rn.f16x2.f32 %0, %1, %2;" : "=r"(d) : "f"(hi), "f"(lo));
    return d;
}
__device__ __forceinline__ void mma_bf16(float c[4], const uint32_t a[4], const uint32_t b[2]) {
    asm volatile(
        "mma.sync.aligned.m16n8k16.row.col.f32.bf16.bf16.f32 "
        "{%0,%1,%2,%3}, {%4,%5,%6,%7}, {%8,%9}, {%0,%1,%2,%3};\n"
        : "+f"(c[0]), "+f"(c[1]), "+f"(c[2]), "+f"(c[3])
        : "r"(a[0]), "r"(a[1]), "r"(a[2]), "r"(a[3]), "r"(b[0]), "r"(b[1]));
}
__device__ __forceinline__ void mma_f16(float c[4], const uint32_t a[4], const uint32_t b[2]) {
    asm volatile(
        "mma.sync.aligned.m16n8k16.row.col.f32.f16.f16.f32 "
        "{%0,%1,%2,%3}, {%4,%5,%6,%7}, {%8,%9}, {%0,%1,%2,%3};\n"
        : "+f"(c[0]), "+f"(c[1]), "+f"(c[2]), "+f"(c[3])
        : "r"(a[0]), "r"(a[1]), "r"(a[2]), "r"(a[3]), "r"(b[0]), "r"(b[1]));
}
__device__ __forceinline__ void ldsm_x4(uint32_t* r, const void* p) {
    uint32_t a = (uint32_t)__cvta_generic_to_shared(p);
    asm volatile("ldmatrix.sync.aligned.m8n8.x4.shared.b16 {%0,%1,%2,%3}, [%4];"
        : "=r"(r[0]), "=r"(r[1]), "=r"(r[2]), "=r"(r[3]) : "r"(a));
}
__device__ __forceinline__ void ldsm_x4t(uint32_t* r, const void* p) {
    uint32_t a = (uint32_t)__cvta_generic_to_shared(p);
    asm volatile("ldmatrix.sync.aligned.m8n8.x4.trans.shared.b16 {%0,%1,%2,%3}, [%4];"
        : "=r"(r[0]), "=r"(r[1]), "=r"(r[2]), "=r"(r[3]) : "r"(a));
}
#define CP_ASYNC16(saddr, gptr) \
    asm volatile("cp.async.cg.shared.global [%0], [%1], 16;" :: "r"(saddr), "l"(gptr))
#define CP_COMMIT() asm volatile("cp.async.commit_group;" ::: "memory")
#define CP_WAIT0()  asm volatile("cp.async.wait_group 0;" ::: "memory")
#define CP_WAIT1()  asm volatile("cp.async.wait_group 1;" ::: "memory")
// fast 2^x for x <= 0 (clamped), FMA pipe only
__device__ __forceinline__ float exp2_fast(float x) {
    x = fmaxf(x, -120.f);
    float t  = x + 12582912.f;
    float fl = t - 12582912.f;
    float f  = x - fl;
    int   n  = __float_as_int(t) - 0x4B400000;
    float r  = 1.3333558e-3f;
    r = fmaf(r, f, 9.6181291e-3f);
    r = fmaf(r, f, 5.5504109e-2f);
    r = fmaf(r, f, 2.4022651e-1f);
    r = fmaf(r, f, 6.9314718e-1f);
    r = fmaf(r, f, 1.0f);
    return r * __int_as_float((n + 127) << 23);
}

// ---------------------------------------------------------------------------
// Weight transpose + fp16 convert: Wt[n][k] = W[k][n].
// ---------------------------------------------------------------------------
__global__ __launch_bounds__(256) void wt_k(
    const float* __restrict__ W0, const float* __restrict__ W1,
    const float* __restrict__ W2, const float* __restrict__ W3,
    const float* __restrict__ W4)
{
    int z = blockIdx.z;
    const float* W = (z == 0) ? W0 : (z == 1) ? W1 : (z == 2) ? W2 : (z == 3) ? W3 : W4;
    __shared__ float t[32][33];
    int tx = threadIdx.x, ty = threadIdx.y;   // 32 x 8
    #pragma unroll
    for (int i = 0; i < 4; i++)
        t[ty + i * 8][tx] = W[(size_t)(blockIdx.y * 32 + ty + i * 8) * DIM + blockIdx.x * 32 + tx];
    __syncthreads();
    __half* out = g_wt + (size_t)z * DIM * DIM;
    #pragma unroll
    for (int i = 0; i < 4; i++)
        out[(size_t)(blockIdx.x * 32 + ty + i * 8) * DIM + blockIdx.y * 32 + tx] =
            __float2half(t[tx][ty + i * 8]);
}

// ---------------------------------------------------------------------------
// Build Mt[b][d][hk] = sum_v state[b,h,k,v] * Wro[h*64+v][d]  (fp16)
// ---------------------------------------------------------------------------
__global__ __launch_bounds__(256) void mkm_k(
    const float* __restrict__ state, const float* __restrict__ Wro)
{
    int dt = blockIdx.x, h = blockIdx.y, b = blockIdx.z;
    __shared__ float st[64][68];
    __shared__ float wr[64][65];
    const float* sp = state + ((size_t)(b * NH + h)) * HD * HD;
    for (int i = threadIdx.x; i < HD * HD; i += 256) {
        int k = i >> 6, v = i & 63;
        st[v][k] = sp[i];
    }
    const float* wp = Wro + (size_t)(h * HD) * DIM + dt * 64;
    for (int i = threadIdx.x; i < HD * 64; i += 256) {
        int v = i >> 6, d = i & 63;
        wr[v][d] = wp[(size_t)v * DIM + d];
    }
    __syncthreads();

    int d = threadIdx.x & 63;
    int rep = threadIdx.x >> 6;
    float acc[16] = {};
    for (int v = 0; v < 64; v++) {
        float w = wr[v][d];
        #pragma unroll
        for (int c = 0; c < 4; c++) {
            float4 s4 = *(const float4*)&st[v][rep * 16 + c * 4];
            acc[c*4+0] += w * s4.x; acc[c*4+1] += w * s4.y;
            acc[c*4+2] += w * s4.z; acc[c*4+3] += w * s4.w;
        }
    }
    __half* out = g_mt + ((size_t)b * DIM + dt * 64 + d) * DIM + h * HD + rep * 16;
    #pragma unroll
    for (int c = 0; c < 8; c++)
        *((uint32_t*)out + c) = pack_f16(acc[2*c], acc[2*c+1]);
}

// ---------------------------------------------------------------------------
// RMSNorm + gate (fused): writes xn fp16 and g_gate.
// ---------------------------------------------------------------------------
__global__ __launch_bounds__(256) void rmsnorm_k(
    const float* __restrict__ x, const float* __restrict__ nw,
    const float* __restrict__ Wg, const float* __restrict__ bg)
{
    int row = blockIdx.x;
    const float* xr = x + (size_t)row * DIM;
    float ss = 0.f;
    for (int d = threadIdx.x; d < DIM; d += 256) { float v = xr[d]; ss += v * v; }
    #pragma unroll
    for (int o = 16; o; o >>= 1) ss += __shfl_xor_sync(0xffffffffu, ss, o);
    __shared__ float red[8];
    __shared__ float s_rinv;
    int wid = threadIdx.x >> 5, lane = threadIdx.x & 31;
    if (lane == 0) red[wid] = ss;
    __syncthreads();
    if (threadIdx.x == 0) {
        float t = 0.f;
        #pragma unroll
        for (int i = 0; i < 8; i++) t += red[i];
        s_rinv = rsqrtf(t / (float)DIM + REPS);
    }
    __syncthreads();
    float r = s_rinv;
    float acc[NH];
    #pragma unroll
    for (int h = 0; h < NH; h++) acc[h] = 0.f;
    for (int d = threadIdx.x; d < DIM; d += 256) {
        float xv = xr[d] * r * nw[d];
        g_xnh[(size_t)row * DIM + d] = __float2half(xv);
        #pragma unroll
        for (int h = 0; h < NH; h++) acc[h] += xv * Wg[d * NH + h];
    }
    #pragma unroll
    for (int h = 0; h < NH; h++) {
        #pragma unroll
        for (int o = 16; o; o >>= 1) acc[h] += __shfl_xor_sync(0xffffffffu, acc[h], o);
    }
    __shared__ float red2[8][NH];
    if (lane == 0) {
        #pragma unroll
        for (int h = 0; h < NH; h++) red2[wid][h] = acc[h];
    }
    __syncthreads();
    if (threadIdx.x == 0) {
        float s = 0.f;
        #pragma unroll
        for (int h = 0; h < NH; h++) {
            float a = 0.f;
            #pragma unroll
            for (int w = 0; w < 8; w++) a += red2[w][h];
            s += 1.f / (1.f + expf(-(a + bg[h])));
        }
        g_gate[row] = s * (1.f / (float)NH);
    }
}

// ---------------------------------------------------------------------------
// fp16 tensor-core GEMM core: 128x128 tile, BK=64 halves, cp.async
// double-buffered staging, ldmatrix fragments, warp tile 32x64.
// A fp16 [m][k]; B fp16 TRANSPOSED [n][k]. K may split at 768.
// smem: As[2][128][36w] | Bs[2][128][36w] = 72 KB
// ---------------------------------------------------------------------------
#define GEMM_SMEM_WORDS (2*(BM*36 + BN*36))
#define GEMM_SMEM_BYTES (GEMM_SMEM_WORDS*4)

__device__ __forceinline__ void stage_async(
    uint32_t sa, uint32_t sbb,
    const __half* __restrict__ A1, const __half* __restrict__ B1,
    const __half* __restrict__ A2, const __half* __restrict__ B2,
    int k0, int m0, int n0)
{
    const __half* A = (k0 < DIM) ? A1 : A2;
    const __half* B = (k0 < DIM) ? B1 : B2;
    int kk = (k0 < DIM) ? k0 : k0 - DIM;
    int tid = threadIdx.x;
    #pragma unroll
    for (int p = 0; p < 4; p++) {            // A: 128 rows x 8 x 16B
        int idx = tid + p * 256;
        int row = idx >> 3, seg = idx & 7;
        CP_ASYNC16(sa + (row * 36 + seg * 4) * 4,
                   A + (size_t)(m0 + row) * DIM + kk + seg * 8);
    }
    #pragma unroll
    for (int p = 0; p < 4; p++) {            // B: 128 rows x 8 x 16B
        int idx = tid + p * 256;
        int row = idx >> 3, seg = idx & 7;
        CP_ASYNC16(sbb + (row * 36 + seg * 4) * 4,
                   B + (size_t)(n0 + row) * DIM + kk + seg * 8);
    }
}

__device__ __forceinline__ void gemm_core_f16(
    uint32_t* sm,
    const __half* __restrict__ A1, const __half* __restrict__ B1,
    const __half* __restrict__ A2, const __half* __restrict__ B2,
    int Kd, int m0, int n0, float c[2][8][4])
{
    uint32_t (*As)[BM][36] = (uint32_t(*)[BM][36])sm;
    uint32_t (*Bs)[BN][36] = (uint32_t(*)[BN][36])(sm + 2*BM*36);
    uint32_t s_base = (uint32_t)__cvta_generic_to_shared(sm);
    uint32_t sA[2], sB[2];
    sA[0] = s_base;                     sA[1] = s_base + BM*36*4;
    sB[0] = s_base + 2*BM*36*4;         sB[1] = s_base + 2*BM*36*4 + BN*36*4;

    int tid = threadIdx.x;
    int lane = tid & 31, wid = tid >> 5;
    int wm = wid & 3, wn = wid >> 2;    // 4 x 2 warp grid; warp tile 32m x 64n

    // ldmatrix lane-address components
    int a_row = (lane & 7) + ((lane >> 3) & 1) * 8;   // + mt*16 + wm*32
    int a_col = (lane >> 4) * 4;                      // + ks*8
    int b_row = (lane & 7) + (lane >> 4) * 8;         // + np*16 + wn*64
    int b_col = ((lane >> 3) & 1) * 4;                // + ks*8

    stage_async(sA[0], sB[0], A1, B1, A2, B2, 0, m0, n0);
    CP_COMMIT();

    int NC = Kd / BKH;
    for (int cc = 0; cc < NC; cc++) {
        int buf = cc & 1;
        __syncthreads();   // everyone done reading buf^1 (from iter cc-1)
        if (cc + 1 < NC) {
            stage_async(sA[buf ^ 1], sB[buf ^ 1], A1, B1, A2, B2,
                        (cc + 1) * BKH, m0, n0);
            CP_COMMIT();
            CP_WAIT1();    // group for THIS buf complete; next overlaps compute
        } else {
            CP_WAIT0();
        }
        __syncthreads();

        #pragma unroll
        for (int ks = 0; ks < 4; ks++) {
            uint32_t af[2][4];
            #pragma unroll
            for (int mt = 0; mt < 2; mt++)
                ldsm_x4(af[mt], &As[buf][wm * 32 + mt * 16 + a_row][ks * 8 + a_col]);
            #pragma unroll
            for (int np = 0; np < 4; np++) {
                uint32_t b4[4];
                ldsm_x4(b4, &Bs[buf][wn * 64 + np * 16 + b_row][ks * 8 + b_col]);
                #pragma unroll
                for (int mt = 0; mt < 2; mt++) {
                    mma_f16(c[mt][2 * np    ], af[mt], &b4[0]);
                    mma_f16(c[mt][2 * np + 1], af[mt], &b4[2]);
                }
            }
        }
    }
}

// ---------------------------------------------------------------------------
// Projection GEMMs: z in {0,1,2}: bf16 q/k/v scatter BHTK; z=3: gated qg fp16.
// grid (6, 32, 4)
// ---------------------------------------------------------------------------
__global__ __launch_bounds__(256, 2) void proj_tc() {
    extern __shared__ uint32_t sm[];
    int z = blockIdx.z;
    const __half* Bt = g_wt + (size_t)z * DIM * DIM;

    int m0 = blockIdx.y * BM, n0 = blockIdx.x * BN;
    float c[2][8][4] = {};
    gemm_core_f16(sm, g_xnh, Bt, g_xnh, Bt, DIM, m0, n0, c);

    int lane = threadIdx.x & 31, wid = threadIdx.x >> 5;
    int wm = wid & 3, wn = wid >> 2;
    int r = lane >> 2, cq = lane & 3;
    __nv_bfloat16* Cb = (z == 0) ? g_qb : (z == 1) ? g_kb : g_vb;

    #pragma unroll
    for (int mt = 0; mt < 2; mt++) {
        #pragma unroll
        for (int i = 0; i < 2; i++) {
            int row = m0 + wm * 32 + mt * 16 + r + i * 8;
            float gv = (z == 3) ? g_gate[row] : 0.f;
            #pragma unroll
            for (int nt = 0; nt < 8; nt++) {
                int col = n0 + wn * 64 + nt * 8 + 2 * cq;
                float v0 = c[mt][nt][i * 2 + 0];
                float v1 = c[mt][nt][i * 2 + 1];
                if (z == 3) {
                    v0 = fmaxf(v0, 0.f) * gv;
                    v1 = fmaxf(v1, 0.f) * gv;
                    *(uint32_t*)(g_qgg + (size_t)row * HKD + col) = pack_f16(v0, v1);
                } else {
                    int h = col >> 6, kk = col & 63;
                    int b = row >> 11, t = row & (TSEQ - 1);
                    size_t idx = (((size_t)(b * NH + h) * TSEQ + t) << 6) + kk;
                    *((uint32_t*)Cb + (idx >> 1)) = pack_bf16(v0, v1);
                }
            }
        }
    }
}

// ---------------------------------------------------------------------------
// Final GEMM: out = x + [local | qgg] @ [Wo^T ; Mt_b], K=1536.  grid (6, 32)
// ---------------------------------------------------------------------------
__global__ __launch_bounds__(256, 2) void out_tc(float* __restrict__ C,
                                                 const float* __restrict__ addsrc) {
    extern __shared__ uint32_t sm[];
    int m0 = blockIdx.y * BM, n0 = blockIdx.x * BN;
    int b = m0 >> 11;
    float c[2][8][4] = {};
    gemm_core_f16(sm, g_localh, g_wt + (size_t)4 * DIM * DIM,
                  g_qgg, g_mt + (size_t)b * DIM * DIM,
                  2 * DIM, m0, n0, c);

    int lane = threadIdx.x & 31, wid = threadIdx.x >> 5;
    int wm = wid & 3, wn = wid >> 2;
    int r = lane >> 2, cq = lane & 3;
    #pragma unroll
    for (int mt = 0; mt < 2; mt++) {
        #pragma unroll
        for (int i = 0; i < 2; i++) {
            int row = m0 + wm * 32 + mt * 16 + r + i * 8;
            #pragma unroll
            for (int nt = 0; nt < 8; nt++) {
                int col = n0 + wn * 64 + nt * 8 + 2 * cq;
                size_t idx = (size_t)row * DIM + col;
                float2 a2 = *(const float2*)(addsrc + idx);
                float2 o;
                o.x = c[mt][nt][i * 2 + 0] + a2.x;
                o.y = c[mt][nt][i * 2 + 1] + a2.y;
                *(float2*)(C + idx) = o;
            }
        }
    }
}

// ---------------------------------------------------------------------------
// bf16 tensor-core sliding-window flash attention (unchanged from R8 pass).
// ---------------------------------------------------------------------------
#define ATTN_SMEM_WORDS (128*36 + 64*36 + 64*36)
#define ATTN_SMEM_BYTES (ATTN_SMEM_WORDS*4)

__global__ __launch_bounds__(256, 2) void attn_tc() {
    extern __shared__ uint32_t sm[];
    uint32_t (*Qs)[36] = (uint32_t(*)[36])(sm);
    uint32_t (*Ks)[36] = (uint32_t(*)[36])(sm + 128*36);
    uint32_t (*Vs)[36] = (uint32_t(*)[36])(sm + 128*36 + 64*36);

    int qt = blockIdx.x;
    int bh = blockIdx.y;
    int q0 = qt * 128;
    int tid = threadIdx.x, lane = tid & 31, wid = tid >> 5;
    int r = lane >> 2, cq = lane & 3;
    size_t base = (size_t)bh * TSEQ * HD;

    int a_row = (lane & 7) + ((lane >> 3) & 1) * 8;
    int a_col = (lane >> 4) * 4;
    int b_row = (lane & 7) + (lane >> 4) * 8;
    int b_col = ((lane >> 3) & 1) * 4;
    int v_row = (lane & 7) + ((lane >> 3) & 1) * 8;
    int v_col = (lane >> 4) * 4;

    {
        const __nv_bfloat16* Qg = g_qb + base + (size_t)q0 * HD;
        #pragma unroll
        for (int p = 0; p < 4; p++) {
            int idx = tid + p * 256;
            int row = idx >> 3, seg = idx & 7;
            uint4 u = *(const uint4*)(Qg + (size_t)row * HD + seg * 8);
            *(uint4*)&Qs[row][seg * 4] = u;
        }
    }
    __syncthreads();
    uint32_t qf[4][4];
    #pragma unroll
    for (int ks = 0; ks < 4; ks++)
        ldsm_x4(qf[ks], &Qs[wid * 16 + a_row][ks * 8 + a_col]);

    float of[8][4] = {};
    float mz[2] = {NEG_BIG, NEG_BIG};
    float lv[2] = {0.f, 0.f};
    const float zscale = 0.125f * 1.44269504f;

    int kstart = q0 - WIN; if (kstart < 0) kstart = 0;
    for (int s0 = kstart; s0 <= q0 + 64; s0 += 64) {
        __syncthreads();
        #pragma unroll
        for (int p = 0; p < 2; p++) {
            int idx = tid + p * 256;
            int key = idx >> 3, seg = idx & 7;
            uint4 u = *(const uint4*)(g_kb + base + (size_t)(s0 + key) * HD + seg * 8);
            *(uint4*)&Ks[key][seg * 4] = u;
        }
        #pragma unroll
        for (int p = 0; p < 2; p++) {
            int idx = tid + p * 256;
            int key = idx >> 3, seg = idx & 7;
            uint4 u = *(const uint4*)(g_vb + base + (size_t)(s0 + key) * HD + seg * 8);
            *(uint4*)&Vs[key][seg * 4] = u;
        }
        __syncthreads();

        float sf[8][4] = {};
        #pragma unroll
        for (int ks = 0; ks < 4; ks++) {
            #pragma unroll
            for (int np = 0; np < 4; np++) {
                uint32_t b4[4];
                ldsm_x4(b4, &Ks[np * 16 + b_row][ks * 8 + b_col]);
                mma_bf16(sf[2 * np    ], qf[ks], &b4[0]);
                mma_bf16(sf[2 * np + 1], qf[ks], &b4[2]);
            }
        }

        bool need_mask = (s0 >= q0) || (s0 + WIN < q0 + 128);
        if (need_mask) {
            int q_lo = q0 + wid * 16 + r;
            #pragma unroll
            for (int nt = 0; nt < 8; nt++) {
                #pragma unroll
                for (int j = 0; j < 4; j++) {
                    int key = s0 + nt * 8 + 2 * cq + (j & 1);
                    int q = q_lo + (j >> 1) * 8;
                    bool ok = (key <= q) && (key >= q - WIN);
                    sf[nt][j] = ok ? sf[nt][j] * zscale : NEG_BIG;
                }
            }
        } else {
            #pragma unroll
            for (int nt = 0; nt < 8; nt++)
                #pragma unroll
                for (int j = 0; j < 4; j++) sf[nt][j] *= zscale;
        }

        float mx0 = NEG_BIG, mx1 = NEG_BIG;
        #pragma unroll
        for (int nt = 0; nt < 8; nt++) {
            mx0 = fmaxf(mx0, fmaxf(sf[nt][0], sf[nt][1]));
            mx1 = fmaxf(mx1, fmaxf(sf[nt][2], sf[nt][3]));
        }
        mx0 = fmaxf(mx0, __shfl_xor_sync(0xffffffffu, mx0, 1));
        mx0 = fmaxf(mx0, __shfl_xor_sync(0xffffffffu, mx0, 2));
        mx1 = fmaxf(mx1, __shfl_xor_sync(0xffffffffu, mx1, 1));
        mx1 = fmaxf(mx1, __shfl_xor_sync(0xffffffffu, mx1, 2));
        float nm0 = fmaxf(mz[0], mx0);
        float nm1 = fmaxf(mz[1], mx1);
        float c0 = exp2_fast(mz[0] - nm0);
        float c1 = exp2_fast(mz[1] - nm1);

        float rs0 = 0.f, rs1 = 0.f;
        #pragma unroll
        for (int nt = 0; nt < 8; nt++) {
            sf[nt][0] = exp2_fast(sf[nt][0] - nm0);
            sf[nt][1] = exp2_fast(sf[nt][1] - nm0);
            sf[nt][2] = exp2_fast(sf[nt][2] - nm1);
            sf[nt][3] = exp2_fast(sf[nt][3] - nm1);
            rs0 += sf[nt][0] + sf[nt][1];
            rs1 += sf[nt][2] + sf[nt][3];
        }
        rs0 += __shfl_xor_sync(0xffffffffu, rs0, 1);
        rs0 += __shfl_xor_sync(0xffffffffu, rs0, 2);
        rs1 += __shfl_xor_sync(0xffffffffu, rs1, 1);
        rs1 += __shfl_xor_sync(0xffffffffu, rs1, 2);
        lv[0] = lv[0] * c0 + rs0;
        lv[1] = lv[1] * c1 + rs1;
        mz[0] = nm0; mz[1] = nm1;
        #pragma unroll
        for (int nt = 0; nt < 8; nt++) {
            of[nt][0] *= c0; of[nt][1] *= c0;
            of[nt][2] *= c1; of[nt][3] *= c1;
        }

        #pragma unroll
        for (int ks = 0; ks < 4; ks++) {
            uint32_t a[4];
            a[0] = pack_bf16(sf[2*ks    ][0], sf[2*ks    ][1]);
            a[1] = pack_bf16(sf[2*ks    ][2], sf[2*ks    ][3]);
            a[2] = pack_bf16(sf[2*ks + 1][0], sf[2*ks + 1][1]);
            a[3] = pack_bf16(sf[2*ks + 1][2], sf[2*ks + 1][3]);
            #pragma unroll
            for (int np = 0; np < 4; np++) {
                uint32_t b4[4];
                ldsm_x4t(b4, &Vs[ks * 16 + v_row][np * 8 + v_col]);
                mma_bf16(of[2 * np    ], a, &b4[0]);
                mma_bf16(of[2 * np + 1], a, &b4[2]);
            }
        }
    }

    int b = bh / NH, h = bh % NH;
    float inv0 = 1.f / lv[0], inv1 = 1.f / lv[1];
    int qa = q0 + wid * 16 + r;
    #pragma unroll
    for (int nt = 0; nt < 8; nt++) {
        int col = h * HD + nt * 8 + 2 * cq;
        *(uint32_t*)(g_localh + ((size_t)(b * TSEQ + qa    )) * HKD + col) =
            pack_f16(of[nt][0] * inv0, of[nt][1] * inv0);
        *(uint32_t*)(g_localh + ((size_t)(b * TSEQ + qa + 8)) * HKD + col) =
            pack_f16(of[nt][2] * inv1, of[nt][3] * inv1);
    }
}

// ---------------------------------------------------------------------------
// Launch
// ---------------------------------------------------------------------------
extern "C" void kernel_launch(void* const* d_in, const int* in_sizes, int n_in,
                              void* d_out, int out_size) {
    const float* x      = (const float*)d_in[0];
    const float* state  = (const float*)d_in[1];
    const float* Wq     = (const float*)d_in[2];
    const float* Wk     = (const float*)d_in[3];
    const float* Wv     = (const float*)d_in[4];
    const float* Wo     = (const float*)d_in[5];
    const float* Wgq    = (const float*)d_in[6];
    const float* Wro    = (const float*)d_in[7];
    const float* Wg     = (const float*)d_in[8];
    const float* bg     = (const float*)d_in[9];
    const float* norm_w = (const float*)d_in[10];
    float* out = (float*)d_out;

    cudaFuncSetAttribute(proj_tc, cudaFuncAttributeMaxDynamicSharedMemorySize,
                         GEMM_SMEM_BYTES);
    cudaFuncSetAttribute(out_tc, cudaFuncAttributeMaxDynamicSharedMemorySize,
                         GEMM_SMEM_BYTES);

    wt_k<<<dim3(24, 24, 5), dim3(32, 8)>>>(Wq, Wk, Wv, Wgq, Wo);
    mkm_k<<<dim3(12, NH, BSZ), 256>>>(state, Wro);
    rmsnorm_k<<<ROWS, 256>>>(x, norm_w, Wg, bg);

    proj_tc<<<dim3(DIM / BN, ROWS / BM, 4), 256, GEMM_SMEM_BYTES>>>();

    attn_tc<<<dim3(TSEQ / 128, BSZ * NH), 256, ATTN_SMEM_BYTES>>>();

    out_tc<<<dim3(DIM / BN, ROWS / BM), 256, GEMM_SMEM_BYTES>>>(out, x);
}

// round 16
// speedup vs baseline: 6.3730x; 1.0120x over previous
#include <cuda_runtime.h>
#include <cuda_bf16.h>
#include <cuda_fp16.h>
#include <math.h>
#include <stdint.h>

// Problem constants
#define BSZ  2
#define TSEQ 2048
#define DIM  768
#define NH   12
#define HD   64
#define WIN  1024
#define ROWS (BSZ*TSEQ)  // 4096
#define HKD  (NH*HD)     // 768
#define REPS 1e-6f
#define NEG_BIG (-1e30f)

#define BM   128
#define BN   128
#define BKH  64          // K-step in halves

// ---------------------------------------------------------------------------
// Scratch
// ---------------------------------------------------------------------------
__device__ __half         g_xnh[ROWS*DIM];          // rmsnorm(x) fp16
__device__ __nv_bfloat16  g_qb[BSZ*NH*TSEQ*HD];     // bf16 (B,H,T,K)
__device__ __nv_bfloat16  g_kb[BSZ*NH*TSEQ*HD];
__device__ __nv_bfloat16  g_vb[BSZ*NH*TSEQ*HD];
__device__ __half         g_qgg[ROWS*HKD];          // gate * relu(xn@Wgq) fp16
__device__ __half         g_localh[ROWS*HKD];       // attention out fp16 (B,T,HK)
__device__ __half         g_wt[5*DIM*DIM];          // Wq,Wk,Wv,Wgq,Wo transposed fp16 [n][k]
__device__ __half         g_mt[BSZ*DIM*DIM];        // M_b^T fp16 [d][hk]
__device__ float          g_gate[ROWS];

// ---------------------------------------------------------------------------
// helpers
// ---------------------------------------------------------------------------
__device__ __forceinline__ uint32_t pack_bf16(float lo, float hi) {
    uint32_t d;
    asm("cvt.rn.bf16x2.f32 %0, %1, %2;" : "=r"(d) : "f"(hi), "f"(lo));
    return d;
}
__device__ __forceinline__ uint32_t pack_f16(float lo, float hi) {
    uint32_t d;
    asm("cvt.rn.f16x2.f32 %0, %1, %2;" : "=r"(d) : "f"(hi), "f"(lo));
    return d;
}
__device__ __forceinline__ void mma_bf16(float c[4], const uint32_t a[4], const uint32_t b[2]) {
    asm volatile(
        "mma.sync.aligned.m16n8k16.row.col.f32.bf16.bf16.f32 "
        "{%0,%1,%2,%3}, {%4,%5,%6,%7}, {%8,%9}, {%0,%1,%2,%3};\n"
        : "+f"(c[0]), "+f"(c[1]), "+f"(c[2]), "+f"(c[3])
        : "r"(a[0]), "r"(a[1]), "r"(a[2]), "r"(a[3]), "r"(b[0]), "r"(b[1]));
}
__device__ __forceinline__ void mma_f16(float c[4], const uint32_t a[4], const uint32_t b[2]) {
    asm volatile(
        "mma.sync.aligned.m16n8k16.row.col.f32.f16.f16.f32 "
        "{%0,%1,%2,%3}, {%4,%5,%6,%7}, {%8,%9}, {%0,%1,%2,%3};\n"
        : "+f"(c[0]), "+f"(c[1]), "+f"(c[2]), "+f"(c[3])
        : "r"(a[0]), "r"(a[1]), "r"(a[2]), "r"(a[3]), "r"(b[0]), "r"(b[1]));
}
__device__ __forceinline__ void ldsm_x4(uint32_t* r, const void* p) {
    uint32_t a = (uint32_t)__cvta_generic_to_shared(p);
    asm volatile("ldmatrix.sync.aligned.m8n8.x4.shared.b16 {%0,%1,%2,%3}, [%4];"
        : "=r"(r[0]), "=r"(r[1]), "=r"(r[2]), "=r"(r[3]) : "r"(a));
}
__device__ __forceinline__ void ldsm_x4t(uint32_t* r, const void* p) {
    uint32_t a = (uint32_t)__cvta_generic_to_shared(p);
    asm volatile("ldmatrix.sync.aligned.m8n8.x4.trans.shared.b16 {%0,%1,%2,%3}, [%4];"
        : "=r"(r[0]), "=r"(r[1]), "=r"(r[2]), "=r"(r[3]) : "r"(a));
}
#define CP_ASYNC16(saddr, gptr) \
    asm volatile("cp.async.cg.shared.global [%0], [%1], 16;" :: "r"(saddr), "l"(gptr))
#define CP_COMMIT() asm volatile("cp.async.commit_group;" ::: "memory")
#define CP_WAIT0()  asm volatile("cp.async.wait_group 0;" ::: "memory")
#define CP_WAIT1()  asm volatile("cp.async.wait_group 1;" ::: "memory")
// fast 2^x for x <= 0 (clamped), FMA pipe only
__device__ __forceinline__ float exp2_fast(float x) {
    x = fmaxf(x, -120.f);
    float t  = x + 12582912.f;
    float fl = t - 12582912.f;
    float f  = x - fl;
    int   n  = __float_as_int(t) - 0x4B400000;
    float r  = 1.3333558e-3f;
    r = fmaf(r, f, 9.6181291e-3f);
    r = fmaf(r, f, 5.5504109e-2f);
    r = fmaf(r, f, 2.4022651e-1f);
    r = fmaf(r, f, 6.9314718e-1f);
    r = fmaf(r, f, 1.0f);
    return r * __int_as_float((n + 127) << 23);
}

// ---------------------------------------------------------------------------
// Weight transpose + fp16 convert: Wt[n][k] = W[k][n].
// ---------------------------------------------------------------------------
__global__ __launch_bounds__(256) void wt_k(
    const float* __restrict__ W0, const float* __restrict__ W1,
    const float* __restrict__ W2, const float* __restrict__ W3,
    const float* __restrict__ W4)
{
    int z = blockIdx.z;
    const float* W = (z == 0) ? W0 : (z == 1) ? W1 : (z == 2) ? W2 : (z == 3) ? W3 : W4;
    __shared__ float t[32][33];
    int tx = threadIdx.x, ty = threadIdx.y;   // 32 x 8
    #pragma unroll
    for (int i = 0; i < 4; i++)
        t[ty + i * 8][tx] = W[(size_t)(blockIdx.y * 32 + ty + i * 8) * DIM + blockIdx.x * 32 + tx];
    __syncthreads();
    __half* out = g_wt + (size_t)z * DIM * DIM;
    #pragma unroll
    for (int i = 0; i < 4; i++)
        out[(size_t)(blockIdx.x * 32 + ty + i * 8) * DIM + blockIdx.y * 32 + tx] =
            __float2half(t[tx][ty + i * 8]);
}

// ---------------------------------------------------------------------------
// Build Mt[b][d][hk] = sum_v state[b,h,k,v] * Wro[h*64+v][d]  (fp16)
// ---------------------------------------------------------------------------
__global__ __launch_bounds__(256) void mkm_k(
    const float* __restrict__ state, const float* __restrict__ Wro)
{
    int dt = blockIdx.x, h = blockIdx.y, b = blockIdx.z;
    __shared__ float st[64][68];
    __shared__ float wr[64][65];
    const float* sp = state + ((size_t)(b * NH + h)) * HD * HD;
    for (int i = threadIdx.x; i < HD * HD; i += 256) {
        int k = i >> 6, v = i & 63;
        st[v][k] = sp[i];
    }
    const float* wp = Wro + (size_t)(h * HD) * DIM + dt * 64;
    for (int i = threadIdx.x; i < HD * 64; i += 256) {
        int v = i >> 6, d = i & 63;
        wr[v][d] = wp[(size_t)v * DIM + d];
    }
    __syncthreads();

    int d = threadIdx.x & 63;
    int rep = threadIdx.x >> 6;
    float acc[16] = {};
    for (int v = 0; v < 64; v++) {
        float w = wr[v][d];
        #pragma unroll
        for (int c = 0; c < 4; c++) {
            float4 s4 = *(const float4*)&st[v][rep * 16 + c * 4];
            acc[c*4+0] += w * s4.x; acc[c*4+1] += w * s4.y;
            acc[c*4+2] += w * s4.z; acc[c*4+3] += w * s4.w;
        }
    }
    __half* out = g_mt + ((size_t)b * DIM + dt * 64 + d) * DIM + h * HD + rep * 16;
    #pragma unroll
    for (int c = 0; c < 8; c++)
        *((uint32_t*)out + c) = pack_f16(acc[2*c], acc[2*c+1]);
}

// ---------------------------------------------------------------------------
// RMSNorm + gate (fused): writes xn fp16 and g_gate.
// ---------------------------------------------------------------------------
__global__ __launch_bounds__(256) void rmsnorm_k(
    const float* __restrict__ x, const float* __restrict__ nw,
    const float* __restrict__ Wg, const float* __restrict__ bg)
{
    int row = blockIdx.x;
    const float* xr = x + (size_t)row * DIM;
    float ss = 0.f;
    for (int d = threadIdx.x; d < DIM; d += 256) { float v = xr[d]; ss += v * v; }
    #pragma unroll
    for (int o = 16; o; o >>= 1) ss += __shfl_xor_sync(0xffffffffu, ss, o);
    __shared__ float red[8];
    __shared__ float s_rinv;
    int wid = threadIdx.x >> 5, lane = threadIdx.x & 31;
    if (lane == 0) red[wid] = ss;
    __syncthreads();
    if (threadIdx.x == 0) {
        float t = 0.f;
        #pragma unroll
        for (int i = 0; i < 8; i++) t += red[i];
        s_rinv = rsqrtf(t / (float)DIM + REPS);
    }
    __syncthreads();
    float r = s_rinv;
    float acc[NH];
    #pragma unroll
    for (int h = 0; h < NH; h++) acc[h] = 0.f;
    for (int d = threadIdx.x; d < DIM; d += 256) {
        float xv = xr[d] * r * nw[d];
        g_xnh[(size_t)row * DIM + d] = __float2half(xv);
        #pragma unroll
        for (int h = 0; h < NH; h++) acc[h] += xv * Wg[d * NH + h];
    }
    #pragma unroll
    for (int h = 0; h < NH; h++) {
        #pragma unroll
        for (int o = 16; o; o >>= 1) acc[h] += __shfl_xor_sync(0xffffffffu, acc[h], o);
    }
    __shared__ float red2[8][NH];
    if (lane == 0) {
        #pragma unroll
        for (int h = 0; h < NH; h++) red2[wid][h] = acc[h];
    }
    __syncthreads();
    if (threadIdx.x == 0) {
        float s = 0.f;
        #pragma unroll
        for (int h = 0; h < NH; h++) {
            float a = 0.f;
            #pragma unroll
            for (int w = 0; w < 8; w++) a += red2[w][h];
            s += 1.f / (1.f + expf(-(a + bg[h])));
        }
        g_gate[row] = s * (1.f / (float)NH);
    }
}

// ---------------------------------------------------------------------------
// fp16 tensor-core GEMM core: 128x128 tile, BK=64 halves, cp.async
// double-buffered staging, ldmatrix fragments, warp tile 32x64.
// ---------------------------------------------------------------------------
#define GEMM_SMEM_WORDS (2*(BM*36 + BN*36))
#define GEMM_SMEM_BYTES (GEMM_SMEM_WORDS*4)

__device__ __forceinline__ void stage_async(
    uint32_t sa, uint32_t sbb,
    const __half* __restrict__ A1, const __half* __restrict__ B1,
    const __half* __restrict__ A2, const __half* __restrict__ B2,
    int k0, int m0, int n0)
{
    const __half* A = (k0 < DIM) ? A1 : A2;
    const __half* B = (k0 < DIM) ? B1 : B2;
    int kk = (k0 < DIM) ? k0 : k0 - DIM;
    int tid = threadIdx.x;
    #pragma unroll
    for (int p = 0; p < 4; p++) {
        int idx = tid + p * 256;
        int row = idx >> 3, seg = idx & 7;
        CP_ASYNC16(sa + (row * 36 + seg * 4) * 4,
                   A + (size_t)(m0 + row) * DIM + kk + seg * 8);
    }
    #pragma unroll
    for (int p = 0; p < 4; p++) {
        int idx = tid + p * 256;
        int row = idx >> 3, seg = idx & 7;
        CP_ASYNC16(sbb + (row * 36 + seg * 4) * 4,
                   B + (size_t)(n0 + row) * DIM + kk + seg * 8);
    }
}

__device__ __forceinline__ void gemm_core_f16(
    uint32_t* sm,
    const __half* __restrict__ A1, const __half* __restrict__ B1,
    const __half* __restrict__ A2, const __half* __restrict__ B2,
    int Kd, int m0, int n0, float c[2][8][4])
{
    uint32_t (*As)[BM][36] = (uint32_t(*)[BM][36])sm;
    uint32_t (*Bs)[BN][36] = (uint32_t(*)[BN][36])(sm + 2*BM*36);
    uint32_t s_base = (uint32_t)__cvta_generic_to_shared(sm);
    uint32_t sA[2], sB[2];
    sA[0] = s_base;                     sA[1] = s_base + BM*36*4;
    sB[0] = s_base + 2*BM*36*4;         sB[1] = s_base + 2*BM*36*4 + BN*36*4;

    int tid = threadIdx.x;
    int lane = tid & 31, wid = tid >> 5;
    int wm = wid & 3, wn = wid >> 2;

    int a_row = (lane & 7) + ((lane >> 3) & 1) * 8;
    int a_col = (lane >> 4) * 4;
    int b_row = (lane & 7) + (lane >> 4) * 8;
    int b_col = ((lane >> 3) & 1) * 4;

    stage_async(sA[0], sB[0], A1, B1, A2, B2, 0, m0, n0);
    CP_COMMIT();

    int NC = Kd / BKH;
    for (int cc = 0; cc < NC; cc++) {
        int buf = cc & 1;
        __syncthreads();
        if (cc + 1 < NC) {
            stage_async(sA[buf ^ 1], sB[buf ^ 1], A1, B1, A2, B2,
                        (cc + 1) * BKH, m0, n0);
            CP_COMMIT();
            CP_WAIT1();
        } else {
            CP_WAIT0();
        }
        __syncthreads();

        #pragma unroll
        for (int ks = 0; ks < 4; ks++) {
            uint32_t af[2][4];
            #pragma unroll
            for (int mt = 0; mt < 2; mt++)
                ldsm_x4(af[mt], &As[buf][wm * 32 + mt * 16 + a_row][ks * 8 + a_col]);
            #pragma unroll
            for (int np = 0; np < 4; np++) {
                uint32_t b4[4];
                ldsm_x4(b4, &Bs[buf][wn * 64 + np * 16 + b_row][ks * 8 + b_col]);
                #pragma unroll
                for (int mt = 0; mt < 2; mt++) {
                    mma_f16(c[mt][2 * np    ], af[mt], &b4[0]);
                    mma_f16(c[mt][2 * np + 1], af[mt], &b4[2]);
                }
            }
        }
    }
}

// ---------------------------------------------------------------------------
// Projection GEMMs: z in {0,1,2}: bf16 q/k/v scatter BHTK; z=3: gated qg fp16.
// ---------------------------------------------------------------------------
__global__ __launch_bounds__(256, 2) void proj_tc() {
    extern __shared__ uint32_t sm[];
    int z = blockIdx.z;
    const __half* Bt = g_wt + (size_t)z * DIM * DIM;

    int m0 = blockIdx.y * BM, n0 = blockIdx.x * BN;
    float c[2][8][4] = {};
    gemm_core_f16(sm, g_xnh, Bt, g_xnh, Bt, DIM, m0, n0, c);

    int lane = threadIdx.x & 31, wid = threadIdx.x >> 5;
    int wm = wid & 3, wn = wid >> 2;
    int r = lane >> 2, cq = lane & 3;
    __nv_bfloat16* Cb = (z == 0) ? g_qb : (z == 1) ? g_kb : g_vb;

    #pragma unroll
    for (int mt = 0; mt < 2; mt++) {
        #pragma unroll
        for (int i = 0; i < 2; i++) {
            int row = m0 + wm * 32 + mt * 16 + r + i * 8;
            float gv = (z == 3) ? g_gate[row] : 0.f;
            #pragma unroll
            for (int nt = 0; nt < 8; nt++) {
                int col = n0 + wn * 64 + nt * 8 + 2 * cq;
                float v0 = c[mt][nt][i * 2 + 0];
                float v1 = c[mt][nt][i * 2 + 1];
                if (z == 3) {
                    v0 = fmaxf(v0, 0.f) * gv;
                    v1 = fmaxf(v1, 0.f) * gv;
                    *(uint32_t*)(g_qgg + (size_t)row * HKD + col) = pack_f16(v0, v1);
                } else {
                    int h = col >> 6, kk = col & 63;
                    int b = row >> 11, t = row & (TSEQ - 1);
                    size_t idx = (((size_t)(b * NH + h) * TSEQ + t) << 6) + kk;
                    *((uint32_t*)Cb + (idx >> 1)) = pack_bf16(v0, v1);
                }
            }
        }
    }
}

// ---------------------------------------------------------------------------
// Final GEMM: out = x + [local | qgg] @ [Wo^T ; Mt_b], K=1536.
// ---------------------------------------------------------------------------
__global__ __launch_bounds__(256, 2) void out_tc(float* __restrict__ C,
                                                 const float* __restrict__ addsrc) {
    extern __shared__ uint32_t sm[];
    int m0 = blockIdx.y * BM, n0 = blockIdx.x * BN;
    int b = m0 >> 11;
    float c[2][8][4] = {};
    gemm_core_f16(sm, g_localh, g_wt + (size_t)4 * DIM * DIM,
                  g_qgg, g_mt + (size_t)b * DIM * DIM,
                  2 * DIM, m0, n0, c);

    int lane = threadIdx.x & 31, wid = threadIdx.x >> 5;
    int wm = wid & 3, wn = wid >> 2;
    int r = lane >> 2, cq = lane & 3;
    #pragma unroll
    for (int mt = 0; mt < 2; mt++) {
        #pragma unroll
        for (int i = 0; i < 2; i++) {
            int row = m0 + wm * 32 + mt * 16 + r + i * 8;
            #pragma unroll
            for (int nt = 0; nt < 8; nt++) {
                int col = n0 + wn * 64 + nt * 8 + 2 * cq;
                size_t idx = (size_t)row * DIM + col;
                float2 a2 = *(const float2*)(addsrc + idx);
                float2 o;
                o.x = c[mt][nt][i * 2 + 0] + a2.x;
                o.y = c[mt][nt][i * 2 + 1] + a2.y;
                *(float2*)(C + idx) = o;
            }
        }
    }
}

// ---------------------------------------------------------------------------
// bf16 flash attention with cp.async double-buffered K/V tiles.
// smem: Qs[128][36] | Ks[2][64][36] | Vs[2][64][36] = 55.3 KB
// ---------------------------------------------------------------------------
#define ATTN_SMEM_WORDS (128*36 + 4*64*36)
#define ATTN_SMEM_BYTES (ATTN_SMEM_WORDS*4)

__device__ __forceinline__ void attn_stage_kv(
    uint32_t sK, uint32_t sV,
    const __nv_bfloat16* __restrict__ Kg, const __nv_bfloat16* __restrict__ Vg,
    size_t base, int s0)
{
    int tid = threadIdx.x;
    #pragma unroll
    for (int p = 0; p < 2; p++) {
        int idx = tid + p * 256;
        int key = idx >> 3, seg = idx & 7;
        CP_ASYNC16(sK + (key * 36 + seg * 4) * 4,
                   Kg + base + (size_t)(s0 + key) * HD + seg * 8);
    }
    #pragma unroll
    for (int p = 0; p < 2; p++) {
        int idx = tid + p * 256;
        int key = idx >> 3, seg = idx & 7;
        CP_ASYNC16(sV + (key * 36 + seg * 4) * 4,
                   Vg + base + (size_t)(s0 + key) * HD + seg * 8);
    }
}

__global__ __launch_bounds__(256, 2) void attn_tc() {
    extern __shared__ uint32_t sm[];
    uint32_t (*Qs)[36]     = (uint32_t(*)[36])(sm);
    uint32_t (*Ks)[64][36] = (uint32_t(*)[64][36])(sm + 128*36);
    uint32_t (*Vs)[64][36] = (uint32_t(*)[64][36])(sm + 128*36 + 2*64*36);
    uint32_t s_base = (uint32_t)__cvta_generic_to_shared(sm);
    uint32_t sK[2], sV[2];
    sK[0] = s_base + 128*36*4;           sK[1] = sK[0] + 64*36*4;
    sV[0] = s_base + (128*36 + 2*64*36)*4; sV[1] = sV[0] + 64*36*4;

    int qt = blockIdx.x;
    int bh = blockIdx.y;
    int q0 = qt * 128;
    int tid = threadIdx.x, lane = tid & 31, wid = tid >> 5;
    int r = lane >> 2, cq = lane & 3;
    size_t base = (size_t)bh * TSEQ * HD;

    int a_row = (lane & 7) + ((lane >> 3) & 1) * 8;
    int a_col = (lane >> 4) * 4;
    int b_row = (lane & 7) + (lane >> 4) * 8;
    int b_col = ((lane >> 3) & 1) * 4;
    int v_row = (lane & 7) + ((lane >> 3) & 1) * 8;
    int v_col = (lane >> 4) * 4;

    int kstart = q0 - WIN; if (kstart < 0) kstart = 0;

    // prefetch first K/V tile while staging Q
    attn_stage_kv(sK[0], sV[0], g_kb, g_vb, base, kstart);
    CP_COMMIT();

    {
        const __nv_bfloat16* Qg = g_qb + base + (size_t)q0 * HD;
        #pragma unroll
        for (int p = 0; p < 4; p++) {
            int idx = tid + p * 256;
            int row = idx >> 3, seg = idx & 7;
            uint4 u = *(const uint4*)(Qg + (size_t)row * HD + seg * 8);
            *(uint4*)&Qs[row][seg * 4] = u;
        }
    }
    __syncthreads();
    uint32_t qf[4][4];
    #pragma unroll
    for (int ks = 0; ks < 4; ks++)
        ldsm_x4(qf[ks], &Qs[wid * 16 + a_row][ks * 8 + a_col]);

    float of[8][4] = {};
    float mz[2] = {NEG_BIG, NEG_BIG};
    float lv[2] = {0.f, 0.f};
    const float zscale = 0.125f * 1.44269504f;

    int t = 0;
    for (int s0 = kstart; s0 <= q0 + 64; s0 += 64, t++) {
        int buf = t & 1;
        __syncthreads();   // all warps done with buf^1 (previous tile's compute)
        if (s0 + 64 <= q0 + 64) {
            attn_stage_kv(sK[buf ^ 1], sV[buf ^ 1], g_kb, g_vb, base, s0 + 64);
            CP_COMMIT();
            CP_WAIT1();    // this tile's group done; next overlaps compute
        } else {
            CP_WAIT0();
        }
        __syncthreads();

        // ---- S = Q @ K^T ----
        float sf[8][4] = {};
        #pragma unroll
        for (int ks = 0; ks < 4; ks++) {
            #pragma unroll
            for (int np = 0; np < 4; np++) {
                uint32_t b4[4];
                ldsm_x4(b4, &Ks[buf][np * 16 + b_row][ks * 8 + b_col]);
                mma_bf16(sf[2 * np    ], qf[ks], &b4[0]);
                mma_bf16(sf[2 * np + 1], qf[ks], &b4[2]);
            }
        }

        // ---- scale to log2 domain (+ mask on boundary tiles) ----
        bool need_mask = (s0 >= q0) || (s0 + WIN < q0 + 128);
        if (need_mask) {
            int q_lo = q0 + wid * 16 + r;
            #pragma unroll
            for (int nt = 0; nt < 8; nt++) {
                #pragma unroll
                for (int j = 0; j < 4; j++) {
                    int key = s0 + nt * 8 + 2 * cq + (j & 1);
                    int q = q_lo + (j >> 1) * 8;
                    bool ok = (key <= q) && (key >= q - WIN);
                    sf[nt][j] = ok ? sf[nt][j] * zscale : NEG_BIG;
                }
            }
        } else {
            #pragma unroll
            for (int nt = 0; nt < 8; nt++)
                #pragma unroll
                for (int j = 0; j < 4; j++) sf[nt][j] *= zscale;
        }

        // ---- online softmax ----
        float mx0 = NEG_BIG, mx1 = NEG_BIG;
        #pragma unroll
        for (int nt = 0; nt < 8; nt++) {
            mx0 = fmaxf(mx0, fmaxf(sf[nt][0], sf[nt][1]));
            mx1 = fmaxf(mx1, fmaxf(sf[nt][2], sf[nt][3]));
        }
        mx0 = fmaxf(mx0, __shfl_xor_sync(0xffffffffu, mx0, 1));
        mx0 = fmaxf(mx0, __shfl_xor_sync(0xffffffffu, mx0, 2));
        mx1 = fmaxf(mx1, __shfl_xor_sync(0xffffffffu, mx1, 1));
        mx1 = fmaxf(mx1, __shfl_xor_sync(0xffffffffu, mx1, 2));
        float nm0 = fmaxf(mz[0], mx0);
        float nm1 = fmaxf(mz[1], mx1);
        float c0 = exp2_fast(mz[0] - nm0);
        float c1 = exp2_fast(mz[1] - nm1);

        float rs0 = 0.f, rs1 = 0.f;
        #pragma unroll
        for (int nt = 0; nt < 8; nt++) {
            sf[nt][0] = exp2_fast(sf[nt][0] - nm0);
            sf[nt][1] = exp2_fast(sf[nt][1] - nm0);
            sf[nt][2] = exp2_fast(sf[nt][2] - nm1);
            sf[nt][3] = exp2_fast(sf[nt][3] - nm1);
            rs0 += sf[nt][0] + sf[nt][1];
            rs1 += sf[nt][2] + sf[nt][3];
        }
        rs0 += __shfl_xor_sync(0xffffffffu, rs0, 1);
        rs0 += __shfl_xor_sync(0xffffffffu, rs0, 2);
        rs1 += __shfl_xor_sync(0xffffffffu, rs1, 1);
        rs1 += __shfl_xor_sync(0xffffffffu, rs1, 2);
        lv[0] = lv[0] * c0 + rs0;
        lv[1] = lv[1] * c1 + rs1;
        mz[0] = nm0; mz[1] = nm1;
        #pragma unroll
        for (int nt = 0; nt < 8; nt++) {
            of[nt][0] *= c0; of[nt][1] *= c0;
            of[nt][2] *= c1; of[nt][3] *= c1;
        }

        // ---- O += P @ V ----
        #pragma unroll
        for (int ks = 0; ks < 4; ks++) {
            uint32_t a[4];
            a[0] = pack_bf16(sf[2*ks    ][0], sf[2*ks    ][1]);
            a[1] = pack_bf16(sf[2*ks    ][2], sf[2*ks    ][3]);
            a[2] = pack_bf16(sf[2*ks + 1][0], sf[2*ks + 1][1]);
            a[3] = pack_bf16(sf[2*ks + 1][2], sf[2*ks + 1][3]);
            #pragma unroll
            for (int np = 0; np < 4; np++) {
                uint32_t b4[4];
                ldsm_x4t(b4, &Vs[buf][ks * 16 + v_row][np * 8 + v_col]);
                mma_bf16(of[2 * np    ], a, &b4[0]);
                mma_bf16(of[2 * np + 1], a, &b4[2]);
            }
        }
    }

    // ---- normalize + write (fp16) ----
    int b = bh / NH, h = bh % NH;
    float inv0 = 1.f / lv[0], inv1 = 1.f / lv[1];
    int qa = q0 + wid * 16 + r;
    #pragma unroll
    for (int nt = 0; nt < 8; nt++) {
        int col = h * HD + nt * 8 + 2 * cq;
        *(uint32_t*)(g_localh + ((size_t)(b * TSEQ + qa    )) * HKD + col) =
            pack_f16(of[nt][0] * inv0, of[nt][1] * inv0);
        *(uint32_t*)(g_localh + ((size_t)(b * TSEQ + qa + 8)) * HKD + col) =
            pack_f16(of[nt][2] * inv1, of[nt][3] * inv1);
    }
}

// ---------------------------------------------------------------------------
// Launch
// ---------------------------------------------------------------------------
extern "C" void kernel_launch(void* const* d_in, const int* in_sizes, int n_in,
                              void* d_out, int out_size) {
    const float* x      = (const float*)d_in[0];
    const float* state  = (const float*)d_in[1];
    const float* Wq     = (const float*)d_in[2];
    const float* Wk     = (const float*)d_in[3];
    const float* Wv     = (const float*)d_in[4];
    const float* Wo     = (const float*)d_in[5];
    const float* Wgq    = (const float*)d_in[6];
    const float* Wro    = (const float*)d_in[7];
    const float* Wg     = (const float*)d_in[8];
    const float* bg     = (const float*)d_in[9];
    const float* norm_w = (const float*)d_in[10];
    float* out = (float*)d_out;

    cudaFuncSetAttribute(proj_tc, cudaFuncAttributeMaxDynamicSharedMemorySize,
                         GEMM_SMEM_BYTES);
    cudaFuncSetAttribute(out_tc, cudaFuncAttributeMaxDynamicSharedMemorySize,
                         GEMM_SMEM_BYTES);
    cudaFuncSetAttribute(attn_tc, cudaFuncAttributeMaxDynamicSharedMemorySize,
                         ATTN_SMEM_BYTES);

    wt_k<<<dim3(24, 24, 5), dim3(32, 8)>>>(Wq, Wk, Wv, Wgq, Wo);
    mkm_k<<<dim3(12, NH, BSZ), 256>>>(state, Wro);
    rmsnorm_k<<<ROWS, 256>>>(x, norm_w, Wg, bg);

    proj_tc<<<dim3(DIM / BN, ROWS / BM, 4), 256, GEMM_SMEM_BYTES>>>();

    attn_tc<<<dim3(TSEQ / 128, BSZ * NH), 256, ATTN_SMEM_BYTES>>>();

    out_tc<<<dim3(DIM / BN, ROWS / BM), 256, GEMM_SMEM_BYTES>>>(out, x);
}